// round 4
// baseline (speedup 1.0000x reference)
#include <cuda_runtime.h>
#include <stdint.h>
#include <math.h>

#define B_   2
#define S_   1024
#define D_   1024
#define H_   16
#define DH_  64
#define FF_  4096
#define V_   32000
#define L_   4
#define PAD_ 3
#define CTX_ 1025

// ---------------- scratch (static device globals; no runtime alloc) -------
__device__ float g_x  [B_*S_*D_];
__device__ float g_xn [B_*S_*D_];
__device__ float g_q  [B_*S_*D_];
__device__ float g_k  [B_*S_*D_];
__device__ float g_v  [B_*S_*D_];
__device__ float g_o  [B_*S_*D_];
__device__ float g_rel[S_*D_];
__device__ float g_r  [S_*D_];
__device__ float g_ff [B_*S_*FF_];
__device__ float g_aw [(size_t)B_*H_*S_*S_];   // scores then attn weights
__device__ float g_uk [B_*H_*S_];              // u·k[b,h,key]
__device__ float g_vr [H_*S_];                 // v·r[h,rrow]

// ---------------- helpers --------------------------------------------------
__device__ __forceinline__ float gelu_t(float x){
    return 0.5f*x*(1.0f + tanhf(0.7978845608028654f*(x + 0.044715f*x*x*x)));
}
__device__ __forceinline__ uint32_t f2tf(float x){
    uint32_t y; asm("cvt.rna.tf32.f32 %0, %1;" : "=r"(y) : "f"(x)); return y;
}
__device__ __forceinline__ void mma_tf32(float c[4], const uint32_t a[4], const uint32_t b[2]){
    asm volatile(
      "mma.sync.aligned.m16n8k8.row.col.f32.tf32.tf32.f32 "
      "{%0,%1,%2,%3}, {%4,%5,%6,%7}, {%8,%9}, {%0,%1,%2,%3};\n"
      : "+f"(c[0]), "+f"(c[1]), "+f"(c[2]), "+f"(c[3])
      : "r"(a[0]), "r"(a[1]), "r"(a[2]), "r"(a[3]), "r"(b[0]), "r"(b[1]));
}

// ---------------- embedding ------------------------------------------------
__global__ void embed_kernel(const int* __restrict__ text, const float* __restrict__ emb){
    int idx = blockIdx.x*256 + threadIdx.x;
    int d4  = idx & (D_/4 - 1);
    int bs  = idx >> 8;
    int s   = bs & (S_-1);
    int b   = bs >> 10;
    int tok = text[b*CTX_ + s];
    ((float4*)g_x)[idx] = ((const float4*)(emb + (size_t)tok*D_))[d4];
}

// ---------------- sinusoidal relative positions ----------------------------
__global__ void rel_kernel(){
    int idx = blockIdx.x*256 + threadIdx.x;
    int j = idx & 511;
    int s = idx >> 9;
    float pos  = (float)(S_-1-s);
    float invf = powf(10000.0f, -(float)(2*j)/(float)D_);
    float a = pos*invf;
    g_rel[s*D_ + j]       = sinf(a);
    g_rel[s*D_ + j + 512] = cosf(a);
}

// ---------------- layernorm ------------------------------------------------
__global__ void ln_kernel(const float* __restrict__ in, float* __restrict__ out,
                          const float* __restrict__ gam, const float* __restrict__ bet){
    int row = blockIdx.x;
    int t = threadIdx.x;
    const float4* x4 = (const float4*)(in + (size_t)row*D_);
    float4 v = x4[t];
    float s  = v.x+v.y+v.z+v.w;
    float s2 = v.x*v.x+v.y*v.y+v.z*v.z+v.w*v.w;
    #pragma unroll
    for (int o=16;o;o>>=1){ s += __shfl_xor_sync(0xffffffffu,s,o); s2 += __shfl_xor_sync(0xffffffffu,s2,o); }
    __shared__ float shs[8], shs2[8], bc[2];
    int w = t>>5, lane = t&31;
    if (!lane){ shs[w]=s; shs2[w]=s2; }
    __syncthreads();
    if (t==0){
        float ts=0.f, ts2=0.f;
        #pragma unroll
        for (int i=0;i<8;i++){ ts+=shs[i]; ts2+=shs2[i]; }
        float m   = ts*(1.0f/(float)D_);
        float var = ts2*(1.0f/(float)D_) - m*m;
        bc[0]=m; bc[1]=rsqrtf(var + 1e-5f);
    }
    __syncthreads();
    float m = bc[0], inv = bc[1];
    float4 gg = ((const float4*)gam)[t];
    float4 bb = ((const float4*)bet)[t];
    float4 o4;
    o4.x = (v.x-m)*inv*gg.x + bb.x;
    o4.y = (v.y-m)*inv*gg.y + bb.y;
    o4.z = (v.z-m)*inv*gg.z + bb.z;
    o4.w = (v.w-m)*inv*gg.w + bb.w;
    ((float4*)(out + (size_t)row*D_))[t] = o4;
}

// ================= tf32 tensor-core GEMM v2 =================================
// CTA tile 128x128x32, 256 threads, 8 warps (4m x 2n), warp 32x64.
// Fragment-paired smem: A pairs (k,k+4) per row; B pairs (k,k+4) per (ks,cg).
#define TBM 128
#define TBN 128
#define TBK 32
#define ARS 18      // A row stride in 8B pairs
#define BPS 137     // B stride per (ks*4+cg) in 8B pairs
#define AWORDS (TBM*ARS*2)     // 4608 words
#define BWORDS (16*BPS*2)      // 4384 words
#define GEMM_SMEM ((AWORDS + BWORDS)*2*4)   // 71936 bytes

// EPI: 0 plain | 1 +bias | 2 gelu(acc+bias) | 3 R1+R2+acc+bias | 4 R1+gelu(acc+bias)
template<int EPI>
__device__ __forceinline__ void tgemm_body(
    const float* __restrict__ A, const float* __restrict__ Bm,
    const float* __restrict__ bias, float* __restrict__ C,
    const float* __restrict__ R1, const float* __restrict__ R2,
    int N, int K)
{
    extern __shared__ uint32_t smg[];
    uint32_t* Asm = smg;                 // [2][AWORDS]
    uint32_t* Bsm = smg + 2*AWORDS;      // [2][BWORDS]

    const int tid = threadIdx.x;
    const int lane = tid & 31, wid = tid >> 5;
    const int wm = wid >> 1, wn = wid & 1;
    const int r = lane >> 2, cg = lane & 3;
    const int bm = blockIdx.y*TBM, bn = blockIdx.x*TBN;

    // fill roles
    const int arow = tid >> 1, akh = tid & 1;      // A: row 0..127, k-half
    const int bkp  = tid >> 4;                     // B: 0..15 = ks*4+cg
    const int bk   = (bkp >> 2)*8 + (bkp & 3);
    const int bnq0 = tid & 15;                     // n-quads bnq0, bnq0+16

    float acc[2][8][4];
    #pragma unroll
    for (int mt=0;mt<2;mt++)
        #pragma unroll
        for (int nt=0;nt<8;nt++)
            #pragma unroll
            for (int i=0;i<4;i++) acc[mt][nt][i]=0.f;

    const int nkt = K/TBK;
    float4 sa[2][2], sb[2][2];

    auto ldg_tile = [&](int kt){
        const float* ap = A + (size_t)(bm+arow)*K + kt*TBK + akh*16;
        sa[0][0] = *(const float4*)ap;
        sa[0][1] = *(const float4*)(ap+4);
        sa[1][0] = *(const float4*)(ap+8);
        sa[1][1] = *(const float4*)(ap+12);
        #pragma unroll
        for (int it=0; it<2; it++){
            int nq = bnq0 + it*16;
            const float* bp = Bm + ((size_t)(kt*TBK + bk))*N + bn + nq*4;
            sb[it][0] = *(const float4*)bp;
            sb[it][1] = *(const float4*)(bp + 4*(size_t)N);
        }
    };
    auto sts_tile = [&](int buf){
        uint32_t* ab = Asm + buf*AWORDS;
        uint32_t* bb = Bsm + buf*BWORDS;
        #pragma unroll
        for (int g=0; g<2; g++){
            int ks = akh*2 + g;
            const float* v0 = (const float*)&sa[g][0];
            const float* v1 = (const float*)&sa[g][1];
            #pragma unroll
            for (int c=0;c<4;c++){
                uint2 p; p.x = f2tf(v0[c]); p.y = f2tf(v1[c]);
                *(uint2*)&ab[(arow*ARS + ks*4 + c)*2] = p;
            }
        }
        #pragma unroll
        for (int it=0; it<2; it++){
            int nq = bnq0 + it*16;
            const float* v0 = (const float*)&sb[it][0];
            const float* v1 = (const float*)&sb[it][1];
            #pragma unroll
            for (int c=0;c<4;c++){
                uint2 p; p.x = f2tf(v0[c]); p.y = f2tf(v1[c]);
                *(uint2*)&bb[(bkp*BPS + nq*4 + c)*2] = p;
            }
        }
    };

    ldg_tile(0);
    sts_tile(0);
    __syncthreads();

    for (int kt=0; kt<nkt; kt++){
        const int cb = kt & 1, nb = cb ^ 1;
        const bool more = (kt+1 < nkt);
        if (more) ldg_tile(kt+1);

        const uint32_t* ab = Asm + cb*AWORDS;
        const uint32_t* bb = Bsm + cb*BWORDS;
        #pragma unroll
        for (int ks=0; ks<4; ks++){
            uint32_t af[2][4];
            #pragma unroll
            for (int mt=0;mt<2;mt++){
                int row = wm*32 + mt*16 + r;
                uint2 p0 = *(const uint2*)&ab[(row*ARS     + ks*4 + cg)*2];
                uint2 p1 = *(const uint2*)&ab[((row+8)*ARS + ks*4 + cg)*2];
                af[mt][0]=p0.x; af[mt][1]=p1.x; af[mt][2]=p0.y; af[mt][3]=p1.y;
            }
            #pragma unroll
            for (int nt=0;nt<8;nt++){
                uint2 bp = *(const uint2*)&bb[((ks*4+cg)*BPS + wn*64 + nt*8 + r)*2];
                uint32_t bf[2] = {bp.x, bp.y};
                mma_tf32(acc[0][nt], af[0], bf);
                mma_tf32(acc[1][nt], af[1], bf);
            }
        }
        if (more) sts_tile(nb);
        __syncthreads();
    }

    // -------- epilogue
    #pragma unroll
    for (int mt=0;mt<2;mt++){
        int row0 = bm + wm*32 + mt*16 + r;
        #pragma unroll
        for (int nt=0;nt<8;nt++){
            int col = bn + wn*64 + nt*8 + cg*2;
            float2 b2 = make_float2(0.f,0.f);
            if (EPI >= 1) b2 = *(const float2*)(bias + col);
            float2 v0, v1;
            v0.x = acc[mt][nt][0] + b2.x; v0.y = acc[mt][nt][1] + b2.y;
            v1.x = acc[mt][nt][2] + b2.x; v1.y = acc[mt][nt][3] + b2.y;
            if (EPI == 2 || EPI == 4){
                v0.x = gelu_t(v0.x); v0.y = gelu_t(v0.y);
                v1.x = gelu_t(v1.x); v1.y = gelu_t(v1.y);
            }
            size_t i0 = (size_t)row0*N + col, i1 = (size_t)(row0+8)*N + col;
            if (EPI == 3){
                float2 a0 = *(const float2*)(R1 + i0), a1 = *(const float2*)(R1 + i1);
                float2 x0 = *(const float2*)(R2 + i0), x1 = *(const float2*)(R2 + i1);
                v0.x += a0.x + x0.x; v0.y += a0.y + x0.y;
                v1.x += a1.x + x1.x; v1.y += a1.y + x1.y;
            }
            if (EPI == 4){
                float2 a0 = *(const float2*)(R1 + i0), a1 = *(const float2*)(R1 + i1);
                v0.x += a0.x; v0.y += a0.y;
                v1.x += a1.x; v1.y += a1.y;
            }
            *(float2*)(C + i0) = v0;
            *(float2*)(C + i1) = v1;
        }
    }
}

template<int EPI>
__global__ void __launch_bounds__(256, 2)
tgemm_kernel(const float* __restrict__ A, const float* __restrict__ Bm,
             const float* __restrict__ bias, float* __restrict__ C,
             const float* __restrict__ R1, const float* __restrict__ R2,
             int N, int K)
{
    tgemm_body<EPI>(A, Bm, bias, C, R1, R2, N, K);
}

__global__ void __launch_bounds__(256, 2)
qkvr_kernel(const float* __restrict__ xn, const float* __restrict__ rel,
            const float* __restrict__ Wq, const float* __restrict__ Wk,
            const float* __restrict__ Wv, const float* __restrict__ Wr,
            float* __restrict__ q, float* __restrict__ k,
            float* __restrict__ v, float* __restrict__ rr)
{
    const int z = blockIdx.z;
    if (z == 3 && blockIdx.y*TBM >= S_) return;
    const float* A = (z < 3) ? xn : rel;
    const float* W = (z==0) ? Wq : (z==1) ? Wk : (z==2) ? Wv : Wr;
    float*       C = (z==0) ? q  : (z==1) ? k  : (z==2) ? v  : rr;
    tgemm_body<0>(A, W, nullptr, C, nullptr, nullptr, D_, D_);
}

// ---------------- bias precompute: uk[b,h,key]=u·k, vr[h,row]=v·r ----------
__global__ void bias_kernel(const float* __restrict__ uvec, const float* __restrict__ vvec){
    const int t = threadIdx.x;
    if (blockIdx.y == 0){
        int row = blockIdx.x;
        float4 kv = ((const float4*)(g_k + (size_t)row*D_))[t];
        float4 uu = ((const float4*)uvec)[t];
        float p = kv.x*uu.x + kv.y*uu.y + kv.z*uu.z + kv.w*uu.w;
        p += __shfl_xor_sync(0xffffffffu, p, 8);
        p += __shfl_xor_sync(0xffffffffu, p, 4);
        p += __shfl_xor_sync(0xffffffffu, p, 2);
        p += __shfl_xor_sync(0xffffffffu, p, 1);
        if ((t & 15) == 0){
            int h = t >> 4;
            int b = row >> 10, key = row & (S_-1);
            g_uk[((size_t)(b*H_ + h))*S_ + key] = p;
        }
    } else {
        int rrow = blockIdx.x;
        if (rrow >= S_) return;
        float4 rv = ((const float4*)(g_r + (size_t)rrow*D_))[t];
        float4 vv = ((const float4*)vvec)[t];
        float p = rv.x*vv.x + rv.y*vv.y + rv.z*vv.z + rv.w*vv.w;
        p += __shfl_xor_sync(0xffffffffu, p, 8);
        p += __shfl_xor_sync(0xffffffffu, p, 4);
        p += __shfl_xor_sync(0xffffffffu, p, 2);
        p += __shfl_xor_sync(0xffffffffu, p, 1);
        if ((t & 15) == 0)
            g_vr[(t>>4)*S_ + rrow] = p;
    }
}

// ---------------- tensor-core score kernel (unchanged) ----------------------
#define QSS 68
#define KSS 72
#define RSS 136
#define CSS 132
#define SC_SMEM ((64*QSS + 64*KSS + 64*RSS + 64*CSS)*4)

__global__ void __launch_bounds__(256)
score_kernel(){
    if (blockIdx.x > blockIdx.y) return;
    const int kt0 = blockIdx.x*64, qt0 = blockIdx.y*64;
    const int bh = blockIdx.z, b = bh >> 4, h = bh & 15;
    const int rbase = S_ - 64 - qt0 + kt0;

    extern __shared__ uint32_t sm[];
    uint32_t* Qs = sm;
    uint32_t* Ks = Qs + 64*QSS;
    uint32_t* Rs = Ks + 64*KSS;
    float*    C2 = (float*)(Rs + 64*RSS);

    const int tid = threadIdx.x;
    const int lane = tid & 31, wid = tid >> 5;
    const int wm = wid >> 1, wn = wid & 1;
    const int r = lane >> 2, cg = lane & 3;

    {
        const int pos = tid & 63, dg = tid >> 6;
        const float* qrow = g_q + ((size_t)(b*S_ + qt0 + pos))*D_ + h*DH_;
        const float* krow = g_k + ((size_t)(b*S_ + kt0 + pos))*D_ + h*DH_;
        #pragma unroll
        for (int c=0;c<4;c++){
            int d0 = dg*16 + c*4;
            float4 v = *(const float4*)(qrow + d0);
            uint4 t; t.x=f2tf(v.x); t.y=f2tf(v.y); t.z=f2tf(v.z); t.w=f2tf(v.w);
            *(uint4*)&Qs[pos*QSS + d0] = t;
            float4 w = *(const float4*)(krow + d0);
            Ks[(d0+0)*KSS + pos] = f2tf(w.x);
            Ks[(d0+1)*KSS + pos] = f2tf(w.y);
            Ks[(d0+2)*KSS + pos] = f2tf(w.z);
            Ks[(d0+3)*KSS + pos] = f2tf(w.w);
        }
    }
    {
        const int j = tid & 127, dh2 = tid >> 7;
        const int rrow = rbase + j;
        if (rrow >= 0 && rrow < S_ && j < 127){
            const float* rr = g_r + (size_t)rrow*D_ + h*DH_ + dh2*32;
            #pragma unroll
            for (int c=0;c<8;c++){
                float4 v = *(const float4*)(rr + c*4);
                int d0 = dh2*32 + c*4;
                Rs[(d0+0)*RSS + j] = f2tf(v.x);
                Rs[(d0+1)*RSS + j] = f2tf(v.y);
                Rs[(d0+2)*RSS + j] = f2tf(v.z);
                Rs[(d0+3)*RSS + j] = f2tf(v.w);
            }
        } else {
            #pragma unroll
            for (int c=0;c<8;c++){
                int d0 = dh2*32 + c*4;
                Rs[(d0+0)*RSS + j] = 0u;
                Rs[(d0+1)*RSS + j] = 0u;
                Rs[(d0+2)*RSS + j] = 0u;
                Rs[(d0+3)*RSS + j] = 0u;
            }
        }
    }
    __syncthreads();

    float accA[4][4]; float accB[8][4];
    #pragma unroll
    for (int nt=0;nt<4;nt++){ accA[nt][0]=accA[nt][1]=accA[nt][2]=accA[nt][3]=0.f; }
    #pragma unroll
    for (int nt=0;nt<8;nt++){ accB[nt][0]=accB[nt][1]=accB[nt][2]=accB[nt][3]=0.f; }

    #pragma unroll
    for (int ks=0; ks<8; ks++){
        uint32_t a[4];
        const int mr = wm*16 + r;
        a[0] = Qs[mr*QSS     + ks*8 + cg];
        a[1] = Qs[(mr+8)*QSS + ks*8 + cg];
        a[2] = Qs[mr*QSS     + ks*8 + cg + 4];
        a[3] = Qs[(mr+8)*QSS + ks*8 + cg + 4];
        #pragma unroll
        for (int nt=0;nt<4;nt++){
            uint32_t bfr[2];
            bfr[0] = Ks[(ks*8+cg  )*KSS + wn*32 + nt*8 + r];
            bfr[1] = Ks[(ks*8+cg+4)*KSS + wn*32 + nt*8 + r];
            mma_tf32(accA[nt], a, bfr);
        }
        #pragma unroll
        for (int nt=0;nt<8;nt++){
            uint32_t bfr[2];
            bfr[0] = Rs[(ks*8+cg  )*RSS + wn*64 + nt*8 + r];
            bfr[1] = Rs[(ks*8+cg+4)*RSS + wn*64 + nt*8 + r];
            mma_tf32(accB[nt], a, bfr);
        }
    }
    #pragma unroll
    for (int nt=0;nt<8;nt++){
        int col = wn*64 + nt*8 + cg*2;
        C2[(wm*16+r  )*CSS + col    ] = accB[nt][0];
        C2[(wm*16+r  )*CSS + col + 1] = accB[nt][1];
        C2[(wm*16+r+8)*CSS + col    ] = accB[nt][2];
        C2[(wm*16+r+8)*CSS + col + 1] = accB[nt][3];
    }
    __syncthreads();

    const float* ukp = g_uk + (size_t)bh*S_ + kt0;
    const float* vrp = g_vr + (size_t)h*S_;
    #pragma unroll
    for (int i=0;i<2;i++){
        const int qr = wm*16 + r + i*8;
        const int q  = qt0 + qr;
        #pragma unroll
        for (int nt=0;nt<4;nt++){
            const int kr0 = wn*32 + nt*8 + cg*2;
            float2 o2;
            #pragma unroll
            for (int cc=0;cc<2;cc++){
                const int kr = kr0 + cc;
                const int k  = kt0 + kr;
                float sc;
                if (k <= q){
                    float bd = C2[qr*CSS + 63 + kr - qr] + vrp[S_-1-q+k];
                    sc = (accA[nt][i*2+cc] + ukp[kr] + bd) * 0.125f;
                } else sc = -1e30f;
                (cc ? o2.y : o2.x) = sc;
            }
            *(float2*)(g_aw + ((size_t)bh*S_ + q)*S_ + kt0 + kr0) = o2;
        }
    }
}

// ---------------- softmax per row -------------------------------------------
__global__ void softmax_kernel(const int* __restrict__ text){
    const int q = blockIdx.x, bh = blockIdx.y, b = bh >> 4;
    float* row = g_aw + ((size_t)bh*S_ + q)*S_;
    const int t = threadIdx.x;
    float4 v = ((float4*)row)[t];
    const int k0 = t*4;
    float vals[4] = {v.x, v.y, v.z, v.w};
    float mx = -1e30f;
    #pragma unroll
    for (int c=0;c<4;c++) if (k0+c <= q) mx = fmaxf(mx, vals[c]);
    #pragma unroll
    for (int o=16;o;o>>=1) mx = fmaxf(mx, __shfl_xor_sync(0xffffffffu, mx, o));
    __shared__ float sh[8], bc[2];
    int w = t>>5, lane = t&31;
    if (!lane) sh[w] = mx;
    __syncthreads();
    if (t==0){ float m=sh[0]; for (int i=1;i<8;i++) m=fmaxf(m,sh[i]); bc[0]=m; }
    __syncthreads();
    mx = bc[0];
    float e[4]; float s = 0.f;
    #pragma unroll
    for (int c=0;c<4;c++){ e[c] = (k0+c <= q) ? __expf(vals[c]-mx) : 0.f; s += e[c]; }
    #pragma unroll
    for (int o=16;o;o>>=1) s += __shfl_xor_sync(0xffffffffu, s, o);
    if (!lane) sh[w] = s;
    __syncthreads();
    if (t==0){ float m=0.f; for (int i=0;i<8;i++) m+=sh[i]; bc[1]=m; }
    __syncthreads();
    bool padq = (text[b*CTX_ + q] == PAD_);
    float inv = padq ? 0.f : 1.0f/bc[1];
    v.x=e[0]*inv; v.y=e[1]*inv; v.z=e[2]*inv; v.w=e[3]*inv;
    ((float4*)row)[t] = v;
}

// ---------------- tensor-core o = aw @ v ------------------------------------
#define AWS 68
#define VSS 72
__global__ void __launch_bounds__(256)
av2_kernel(){
    const int qt0 = blockIdx.x*64;
    const int bh = blockIdx.y, b = bh>>4, h = bh&15;
    __shared__ uint32_t AWs[64*AWS];
    __shared__ uint32_t Vs [64*VSS];

    const int tid = threadIdx.x;
    const int lane = tid & 31, wid = tid >> 5;
    const int wm = wid >> 1, wn = wid & 1;
    const int r = lane >> 2, cg = lane & 3;
    const int pos = tid & 63, dg = tid >> 6;

    float acc[4][4];
    #pragma unroll
    for (int nt=0;nt<4;nt++){ acc[nt][0]=acc[nt][1]=acc[nt][2]=acc[nt][3]=0.f; }

    for (int kt=0; kt<=blockIdx.x; kt++){
        {
            const float* arow = g_aw + ((size_t)bh*S_ + qt0 + pos)*S_ + kt*64;
            const float* vrow = g_v  + ((size_t)(b*S_ + kt*64 + pos))*D_ + h*DH_;
            #pragma unroll
            for (int c=0;c<4;c++){
                int d0 = dg*16 + c*4;
                float4 v = *(const float4*)(arow + d0);
                uint4 t; t.x=f2tf(v.x); t.y=f2tf(v.y); t.z=f2tf(v.z); t.w=f2tf(v.w);
                *(uint4*)&AWs[pos*AWS + d0] = t;
                float4 w = *(const float4*)(vrow + d0);
                uint4 tw; tw.x=f2tf(w.x); tw.y=f2tf(w.y); tw.z=f2tf(w.z); tw.w=f2tf(w.w);
                *(uint4*)&Vs[pos*VSS + d0] = tw;
            }
        }
        __syncthreads();
        #pragma unroll
        for (int ks=0; ks<8; ks++){
            uint32_t a[4];
            const int mr = wm*16 + r;
            a[0] = AWs[mr*AWS     + ks*8 + cg];
            a[1] = AWs[(mr+8)*AWS + ks*8 + cg];
            a[2] = AWs[mr*AWS     + ks*8 + cg + 4];
            a[3] = AWs[(mr+8)*AWS + ks*8 + cg + 4];
            #pragma unroll
            for (int nt=0;nt<4;nt++){
                uint32_t bfr[2];
                bfr[0] = Vs[(ks*8+cg  )*VSS + wn*32 + nt*8 + r];
                bfr[1] = Vs[(ks*8+cg+4)*VSS + wn*32 + nt*8 + r];
                mma_tf32(acc[nt], a, bfr);
            }
        }
        __syncthreads();
    }
    #pragma unroll
    for (int i=0;i<2;i++){
        int q = qt0 + wm*16 + r + i*8;
        #pragma unroll
        for (int nt=0;nt<4;nt++){
            float2 o2;
            o2.x = acc[nt][i*2+0]; o2.y = acc[nt][i*2+1];
            *(float2*)(g_o + ((size_t)(b*S_ + q))*D_ + h*DH_ + wn*32 + nt*8 + cg*2) = o2;
        }
    }
}

// ---------------- orchestration ---------------------------------------------
extern "C" void kernel_launch(void* const* d_in, const int* in_sizes, int n_in,
                              void* d_out, int out_size)
{
    (void)in_sizes; (void)n_in; (void)out_size;
    const int*   text = (const int*)  d_in[0];
    const float* emb  = (const float*)d_in[1];
    const float* u    = (const float*)d_in[2];
    const float* vbp  = (const float*)d_in[3];
    const float* Wq   = (const float*)d_in[4];
    const float* Wk   = (const float*)d_in[5];
    const float* Wv   = (const float*)d_in[6];
    const float* Wr   = (const float*)d_in[7];
    const float* Wfc  = (const float*)d_in[8];
    const float* bfc  = (const float*)d_in[9];
    const float* ln1g = (const float*)d_in[10];
    const float* ln1b = (const float*)d_in[11];
    const float* ln2g = (const float*)d_in[12];
    const float* ln2b = (const float*)d_in[13];
    const float* W1   = (const float*)d_in[14];
    const float* b1   = (const float*)d_in[15];
    const float* W2   = (const float*)d_in[16];
    const float* b2   = (const float*)d_in[17];
    const float* lnfg = (const float*)d_in[18];
    const float* lnfb = (const float*)d_in[19];
    const float* Wlm  = (const float*)d_in[20];
    const float* blm  = (const float*)d_in[21];
    float* out = (float*)d_out;

    float *px,*pxn,*pq,*pk,*pv,*po,*prel,*pr,*pff;
    cudaGetSymbolAddress((void**)&px,   g_x);
    cudaGetSymbolAddress((void**)&pxn,  g_xn);
    cudaGetSymbolAddress((void**)&pq,   g_q);
    cudaGetSymbolAddress((void**)&pk,   g_k);
    cudaGetSymbolAddress((void**)&pv,   g_v);
    cudaGetSymbolAddress((void**)&po,   g_o);
    cudaGetSymbolAddress((void**)&prel, g_rel);
    cudaGetSymbolAddress((void**)&pr,   g_r);
    cudaGetSymbolAddress((void**)&pff,  g_ff);

    static bool attr_done = false;
    if (!attr_done){
        cudaFuncSetAttribute(score_kernel, cudaFuncAttributeMaxDynamicSharedMemorySize, SC_SMEM);
        cudaFuncSetAttribute(qkvr_kernel,  cudaFuncAttributeMaxDynamicSharedMemorySize, GEMM_SMEM);
        cudaFuncSetAttribute(tgemm_kernel<1>, cudaFuncAttributeMaxDynamicSharedMemorySize, GEMM_SMEM);
        cudaFuncSetAttribute(tgemm_kernel<2>, cudaFuncAttributeMaxDynamicSharedMemorySize, GEMM_SMEM);
        cudaFuncSetAttribute(tgemm_kernel<3>, cudaFuncAttributeMaxDynamicSharedMemorySize, GEMM_SMEM);
        cudaFuncSetAttribute(tgemm_kernel<4>, cudaFuncAttributeMaxDynamicSharedMemorySize, GEMM_SMEM);
        attr_done = true;
    }

    const int MR = B_*S_;

    embed_kernel<<<2048,256>>>(text, emb);
    rel_kernel  <<<2048,256>>>();

    for (int l=0; l<L_; l++){
        ln_kernel<<<MR,256>>>(px, pxn, ln1g + l*D_, ln1b + l*D_);

        qkvr_kernel<<<dim3(D_/TBN, MR/TBM, 4),256, GEMM_SMEM>>>(
            pxn, prel,
            Wq + (size_t)l*D_*D_, Wk + (size_t)l*D_*D_,
            Wv + (size_t)l*D_*D_, Wr + (size_t)l*D_*D_,
            pq, pk, pv, pr);

        bias_kernel   <<<dim3(B_*S_, 2),256>>>(u, vbp);
        score_kernel  <<<dim3(16,16,B_*H_),256, SC_SMEM>>>();
        softmax_kernel<<<dim3(S_, B_*H_),256>>>(text);
        av2_kernel    <<<dim3(16, B_*H_),256>>>();

        // x = x + xn + o@Wfc + bfc
        tgemm_kernel<3><<<dim3(D_/TBN, MR/TBM),256, GEMM_SMEM>>>(
            po, Wfc + (size_t)l*D_*D_, bfc + l*D_, px, px, pxn, D_, D_);

        ln_kernel<<<MR,256>>>(px, pxn, ln2g + l*D_, ln2b + l*D_);
        tgemm_kernel<2><<<dim3(FF_/TBN, MR/TBM),256, GEMM_SMEM>>>(
            pxn, W1 + (size_t)l*D_*FF_, b1 + l*FF_, pff, nullptr, nullptr, FF_, D_);
        // x = x + gelu(ff@W2 + b2)
        tgemm_kernel<4><<<dim3(D_/TBN, MR/TBM),256, GEMM_SMEM>>>(
            pff, W2 + (size_t)l*FF_*D_, b2 + l*D_, px, px, nullptr, D_, FF_);
    }

    ln_kernel<<<MR,256>>>(px, pxn, lnfg, lnfb);
    tgemm_kernel<1><<<dim3(V_/TBN, MR/TBM),256, GEMM_SMEM>>>(
        pxn, Wlm, blm, out, nullptr, nullptr, V_, D_);
}

// round 5
// speedup vs baseline: 1.5102x; 1.5102x over previous
#include <cuda_runtime.h>
#include <cuda_fp16.h>
#include <stdint.h>
#include <math.h>

#define B_   2
#define S_   1024
#define D_   1024
#define H_   16
#define DH_  64
#define FF_  4096
#define V_   32000
#define L_   4
#define PAD_ 3
#define CTX_ 1025

// ---------------- scratch ----------------------------------------------------
__device__ float g_x  [B_*S_*D_];
__device__ float g_xn [B_*S_*D_];
__device__ float g_q  [B_*S_*D_];
__device__ float g_k  [B_*S_*D_];
__device__ float g_v  [B_*S_*D_];
__device__ float g_o  [B_*S_*D_];
__device__ float g_rel[S_*D_];
__device__ float g_r  [S_*D_];
__device__ float g_ff [B_*S_*FF_];
__device__ float g_aw [(size_t)B_*H_*S_*S_];
__device__ float g_uk [B_*H_*S_];
__device__ float g_vr [H_*S_];

// ---------------- helpers ----------------------------------------------------
__device__ __forceinline__ float gelu_t(float x){
    return 0.5f*x*(1.0f + tanhf(0.7978845608028654f*(x + 0.044715f*x*x*x)));
}
__device__ __forceinline__ uint32_t f2tf(float x){
    uint32_t y; asm("cvt.rna.tf32.f32 %0, %1;" : "=r"(y) : "f"(x)); return y;
}
__device__ __forceinline__ uint32_t f22h2(float a, float b){
    __half2 h = __floats2half2_rn(a, b);
    return *(uint32_t*)&h;
}
__device__ __forceinline__ uint32_t smaddr(const void* p){
    return (uint32_t)__cvta_generic_to_shared(p);
}
__device__ __forceinline__ void mma_tf32(float c[4], const uint32_t a[4], const uint32_t b[2]){
    asm volatile(
      "mma.sync.aligned.m16n8k8.row.col.f32.tf32.tf32.f32 "
      "{%0,%1,%2,%3}, {%4,%5,%6,%7}, {%8,%9}, {%0,%1,%2,%3};\n"
      : "+f"(c[0]), "+f"(c[1]), "+f"(c[2]), "+f"(c[3])
      : "r"(a[0]), "r"(a[1]), "r"(a[2]), "r"(a[3]), "r"(b[0]), "r"(b[1]));
}
__device__ __forceinline__ void mma_f16(float c[4], const uint32_t a[4], const uint32_t b0, const uint32_t b1){
    asm volatile(
      "mma.sync.aligned.m16n8k16.row.col.f32.f16.f16.f32 "
      "{%0,%1,%2,%3}, {%4,%5,%6,%7}, {%8,%9}, {%0,%1,%2,%3};\n"
      : "+f"(c[0]), "+f"(c[1]), "+f"(c[2]), "+f"(c[3])
      : "r"(a[0]), "r"(a[1]), "r"(a[2]), "r"(a[3]), "r"(b0), "r"(b1));
}
__device__ __forceinline__ void ldsm_x4(uint32_t r[4], uint32_t addr){
    asm volatile("ldmatrix.sync.aligned.m8n8.x4.shared.b16 {%0,%1,%2,%3}, [%4];"
      : "=r"(r[0]), "=r"(r[1]), "=r"(r[2]), "=r"(r[3]) : "r"(addr));
}
__device__ __forceinline__ void ldsm_x4_t(uint32_t r[4], uint32_t addr){
    asm volatile("ldmatrix.sync.aligned.m8n8.x4.trans.shared.b16 {%0,%1,%2,%3}, [%4];"
      : "=r"(r[0]), "=r"(r[1]), "=r"(r[2]), "=r"(r[3]) : "r"(addr));
}

// ---------------- embedding ---------------------------------------------------
__global__ void embed_kernel(const int* __restrict__ text, const float* __restrict__ emb){
    int idx = blockIdx.x*256 + threadIdx.x;
    int d4  = idx & (D_/4 - 1);
    int bs  = idx >> 8;
    int s   = bs & (S_-1);
    int b   = bs >> 10;
    int tok = text[b*CTX_ + s];
    ((float4*)g_x)[idx] = ((const float4*)(emb + (size_t)tok*D_))[d4];
}

// ---------------- sinusoidal relative positions -------------------------------
__global__ void rel_kernel(){
    int idx = blockIdx.x*256 + threadIdx.x;
    int j = idx & 511;
    int s = idx >> 9;
    float pos  = (float)(S_-1-s);
    float invf = powf(10000.0f, -(float)(2*j)/(float)D_);
    float a = pos*invf;
    g_rel[s*D_ + j]       = sinf(a);
    g_rel[s*D_ + j + 512] = cosf(a);
}

// ---------------- layernorm ---------------------------------------------------
__global__ void ln_kernel(const float* __restrict__ in, float* __restrict__ out,
                          const float* __restrict__ gam, const float* __restrict__ bet){
    int row = blockIdx.x;
    int t = threadIdx.x;
    const float4* x4 = (const float4*)(in + (size_t)row*D_);
    float4 v = x4[t];
    float s  = v.x+v.y+v.z+v.w;
    float s2 = v.x*v.x+v.y*v.y+v.z*v.z+v.w*v.w;
    #pragma unroll
    for (int o=16;o;o>>=1){ s += __shfl_xor_sync(0xffffffffu,s,o); s2 += __shfl_xor_sync(0xffffffffu,s2,o); }
    __shared__ float shs[8], shs2[8], bc[2];
    int w = t>>5, lane = t&31;
    if (!lane){ shs[w]=s; shs2[w]=s2; }
    __syncthreads();
    if (t==0){
        float ts=0.f, ts2=0.f;
        #pragma unroll
        for (int i=0;i<8;i++){ ts+=shs[i]; ts2+=shs2[i]; }
        float m   = ts*(1.0f/(float)D_);
        float var = ts2*(1.0f/(float)D_) - m*m;
        bc[0]=m; bc[1]=rsqrtf(var + 1e-5f);
    }
    __syncthreads();
    float m = bc[0], inv = bc[1];
    float4 gg = ((const float4*)gam)[t];
    float4 bb = ((const float4*)bet)[t];
    float4 o4;
    o4.x = (v.x-m)*inv*gg.x + bb.x;
    o4.y = (v.y-m)*inv*gg.y + bb.y;
    o4.z = (v.z-m)*inv*gg.z + bb.z;
    o4.w = (v.w-m)*inv*gg.w + bb.w;
    ((float4*)(out + (size_t)row*D_))[t] = o4;
}

// ================= fp16 tensor-core GEMM =====================================
// C[M,N] = A@B (+epilogue). CTA 128x128x32, 256 thr, 8 warps (4m x 2n),
// warp tile 32x64, mma.m16n8k16 f16 -> f32 accum, ldmatrix fragment loads.
#define TBM 128
#define TBN 128
#define TBK 32

// EPI: 0 plain | 1 +bias | 2 gelu(acc+bias) | 3 R1+R2+acc+bias | 4 R1+gelu(acc+bias)
template<int EPI>
__device__ __forceinline__ void hgemm_body(
    const float* __restrict__ A, const float* __restrict__ Bm,
    const float* __restrict__ bias, float* __restrict__ C,
    const float* __restrict__ R1, const float* __restrict__ R2,
    int N, int K)
{
    __shared__ __align__(16) __half As[2][TBM][40];
    __shared__ __align__(16) __half Bs[2][TBK][136];

    const int tid = threadIdx.x;
    const int lane = tid & 31, wid = tid >> 5;
    const int wm = wid >> 1, wn = wid & 1;
    const int r = lane >> 2, cg = lane & 3;
    const int bm = blockIdx.y*TBM, bn = blockIdx.x*TBN;

    // fill roles
    const int arow = tid >> 1,  akh = tid & 1;   // A: row, k-half(16)
    const int bkr  = tid >> 3,  bc8 = tid & 7;   // B: k-row, 16-col chunk

    // ldmatrix lane roles
    const int aRowL = lane & 15, aKH = lane >> 4;
    const int bKL   = (lane & 7) + ((lane >> 3) & 1)*8, bNH = lane >> 4;

    float acc[2][8][4];
    #pragma unroll
    for (int mt=0;mt<2;mt++)
        #pragma unroll
        for (int nt=0;nt<8;nt++)
            #pragma unroll
            for (int i=0;i<4;i++) acc[mt][nt][i]=0.f;

    const int nkt = K/TBK;
    float4 sa[4], sb[4];

    auto ldg_tile = [&](int kt){
        const float* ap = A + (size_t)(bm+arow)*K + kt*TBK + akh*16;
        sa[0] = *(const float4*)ap;      sa[1] = *(const float4*)(ap+4);
        sa[2] = *(const float4*)(ap+8);  sa[3] = *(const float4*)(ap+12);
        const float* bp = Bm + (size_t)(kt*TBK + bkr)*N + bn + bc8*16;
        sb[0] = *(const float4*)bp;      sb[1] = *(const float4*)(bp+4);
        sb[2] = *(const float4*)(bp+8);  sb[3] = *(const float4*)(bp+12);
    };
    auto sts_tile = [&](int buf){
        uint4 t0, t1;
        t0.x = f22h2(sa[0].x, sa[0].y); t0.y = f22h2(sa[0].z, sa[0].w);
        t0.z = f22h2(sa[1].x, sa[1].y); t0.w = f22h2(sa[1].z, sa[1].w);
        t1.x = f22h2(sa[2].x, sa[2].y); t1.y = f22h2(sa[2].z, sa[2].w);
        t1.z = f22h2(sa[3].x, sa[3].y); t1.w = f22h2(sa[3].z, sa[3].w);
        *(uint4*)&As[buf][arow][akh*16]     = t0;
        *(uint4*)&As[buf][arow][akh*16 + 8] = t1;
        uint4 u0, u1;
        u0.x = f22h2(sb[0].x, sb[0].y); u0.y = f22h2(sb[0].z, sb[0].w);
        u0.z = f22h2(sb[1].x, sb[1].y); u0.w = f22h2(sb[1].z, sb[1].w);
        u1.x = f22h2(sb[2].x, sb[2].y); u1.y = f22h2(sb[2].z, sb[2].w);
        u1.z = f22h2(sb[3].x, sb[3].y); u1.w = f22h2(sb[3].z, sb[3].w);
        *(uint4*)&Bs[buf][bkr][bc8*16]     = u0;
        *(uint4*)&Bs[buf][bkr][bc8*16 + 8] = u1;
    };

    ldg_tile(0);
    sts_tile(0);
    __syncthreads();

    for (int kt=0; kt<nkt; kt++){
        const int cb = kt & 1, nb = cb ^ 1;
        const bool more = (kt+1 < nkt);
        if (more) ldg_tile(kt+1);

        #pragma unroll
        for (int ks=0; ks<2; ks++){
            uint32_t af[2][4];
            #pragma unroll
            for (int mt=0;mt<2;mt++)
                ldsm_x4(af[mt], smaddr(&As[cb][wm*32 + mt*16 + aRowL][ks*16 + aKH*8]));
            #pragma unroll
            for (int nt=0;nt<4;nt++){
                uint32_t bf[4];
                ldsm_x4_t(bf, smaddr(&Bs[cb][ks*16 + bKL][wn*64 + nt*16 + bNH*8]));
                mma_f16(acc[0][nt*2+0], af[0], bf[0], bf[1]);
                mma_f16(acc[1][nt*2+0], af[1], bf[0], bf[1]);
                mma_f16(acc[0][nt*2+1], af[0], bf[2], bf[3]);
                mma_f16(acc[1][nt*2+1], af[1], bf[2], bf[3]);
            }
        }
        if (more) sts_tile(nb);
        __syncthreads();
    }

    // -------- epilogue
    #pragma unroll
    for (int mt=0;mt<2;mt++){
        int row0 = bm + wm*32 + mt*16 + r;
        #pragma unroll
        for (int nt=0;nt<8;nt++){
            int col = bn + wn*64 + nt*8 + cg*2;
            float2 b2 = make_float2(0.f,0.f);
            if (EPI >= 1) b2 = *(const float2*)(bias + col);
            float2 v0, v1;
            v0.x = acc[mt][nt][0] + b2.x; v0.y = acc[mt][nt][1] + b2.y;
            v1.x = acc[mt][nt][2] + b2.x; v1.y = acc[mt][nt][3] + b2.y;
            if (EPI == 2 || EPI == 4){
                v0.x = gelu_t(v0.x); v0.y = gelu_t(v0.y);
                v1.x = gelu_t(v1.x); v1.y = gelu_t(v1.y);
            }
            size_t i0 = (size_t)row0*N + col, i1 = (size_t)(row0+8)*N + col;
            if (EPI == 3){
                float2 a0 = *(const float2*)(R1 + i0), a1 = *(const float2*)(R1 + i1);
                float2 x0 = *(const float2*)(R2 + i0), x1 = *(const float2*)(R2 + i1);
                v0.x += a0.x + x0.x; v0.y += a0.y + x0.y;
                v1.x += a1.x + x1.x; v1.y += a1.y + x1.y;
            }
            if (EPI == 4){
                float2 a0 = *(const float2*)(R1 + i0), a1 = *(const float2*)(R1 + i1);
                v0.x += a0.x; v0.y += a0.y;
                v1.x += a1.x; v1.y += a1.y;
            }
            *(float2*)(C + i0) = v0;
            *(float2*)(C + i1) = v1;
        }
    }
}

template<int EPI>
__global__ void __launch_bounds__(256)
hgemm_kernel(const float* __restrict__ A, const float* __restrict__ Bm,
             const float* __restrict__ bias, float* __restrict__ C,
             const float* __restrict__ R1, const float* __restrict__ R2,
             int N, int K)
{
    hgemm_body<EPI>(A, Bm, bias, C, R1, R2, N, K);
}

__global__ void __launch_bounds__(256)
qkvr_kernel(const float* __restrict__ xn, const float* __restrict__ rel,
            const float* __restrict__ Wq, const float* __restrict__ Wk,
            const float* __restrict__ Wv, const float* __restrict__ Wr,
            float* __restrict__ q, float* __restrict__ k,
            float* __restrict__ v, float* __restrict__ rr)
{
    const int z = blockIdx.z;
    if (z == 3 && blockIdx.y*TBM >= S_) return;
    const float* A = (z < 3) ? xn : rel;
    const float* W = (z==0) ? Wq : (z==1) ? Wk : (z==2) ? Wv : Wr;
    float*       C = (z==0) ? q  : (z==1) ? k  : (z==2) ? v  : rr;
    hgemm_body<0>(A, W, nullptr, C, nullptr, nullptr, D_, D_);
}

// ---------------- bias precompute: uk[b,h,key]=u·k, vr[h,row]=v·r -----------
__global__ void bias_kernel(const float* __restrict__ uvec, const float* __restrict__ vvec){
    const int t = threadIdx.x;
    if (blockIdx.y == 0){
        int row = blockIdx.x;
        float4 kv = ((const float4*)(g_k + (size_t)row*D_))[t];
        float4 uu = ((const float4*)uvec)[t];
        float p = kv.x*uu.x + kv.y*uu.y + kv.z*uu.z + kv.w*uu.w;
        p += __shfl_xor_sync(0xffffffffu, p, 8);
        p += __shfl_xor_sync(0xffffffffu, p, 4);
        p += __shfl_xor_sync(0xffffffffu, p, 2);
        p += __shfl_xor_sync(0xffffffffu, p, 1);
        if ((t & 15) == 0){
            int h = t >> 4;
            int b = row >> 10, key = row & (S_-1);
            g_uk[((size_t)(b*H_ + h))*S_ + key] = p;
        }
    } else {
        int rrow = blockIdx.x;
        if (rrow >= S_) return;
        float4 rv = ((const float4*)(g_r + (size_t)rrow*D_))[t];
        float4 vv = ((const float4*)vvec)[t];
        float p = rv.x*vv.x + rv.y*vv.y + rv.z*vv.z + rv.w*vv.w;
        p += __shfl_xor_sync(0xffffffffu, p, 8);
        p += __shfl_xor_sync(0xffffffffu, p, 4);
        p += __shfl_xor_sync(0xffffffffu, p, 2);
        p += __shfl_xor_sync(0xffffffffu, p, 1);
        if ((t & 15) == 0)
            g_vr[(t>>4)*S_ + rrow] = p;
    }
}

// ---------------- tensor-core score kernel (tf32, unchanged) ----------------
#define QSS 68
#define KSS 72
#define RSS 136
#define CSS 132
#define SC_SMEM ((64*QSS + 64*KSS + 64*RSS + 64*CSS)*4)

__global__ void __launch_bounds__(256)
score_kernel(){
    if (blockIdx.x > blockIdx.y) return;
    const int kt0 = blockIdx.x*64, qt0 = blockIdx.y*64;
    const int bh = blockIdx.z, b = bh >> 4, h = bh & 15;
    const int rbase = S_ - 64 - qt0 + kt0;

    extern __shared__ uint32_t sm[];
    uint32_t* Qs = sm;
    uint32_t* Ks = Qs + 64*QSS;
    uint32_t* Rs = Ks + 64*KSS;
    float*    C2 = (float*)(Rs + 64*RSS);

    const int tid = threadIdx.x;
    const int lane = tid & 31, wid = tid >> 5;
    const int wm = wid >> 1, wn = wid & 1;
    const int r = lane >> 2, cg = lane & 3;

    {
        const int pos = tid & 63, dg = tid >> 6;
        const float* qrow = g_q + ((size_t)(b*S_ + qt0 + pos))*D_ + h*DH_;
        const float* krow = g_k + ((size_t)(b*S_ + kt0 + pos))*D_ + h*DH_;
        #pragma unroll
        for (int c=0;c<4;c++){
            int d0 = dg*16 + c*4;
            float4 v = *(const float4*)(qrow + d0);
            uint4 t; t.x=f2tf(v.x); t.y=f2tf(v.y); t.z=f2tf(v.z); t.w=f2tf(v.w);
            *(uint4*)&Qs[pos*QSS + d0] = t;
            float4 w = *(const float4*)(krow + d0);
            Ks[(d0+0)*KSS + pos] = f2tf(w.x);
            Ks[(d0+1)*KSS + pos] = f2tf(w.y);
            Ks[(d0+2)*KSS + pos] = f2tf(w.z);
            Ks[(d0+3)*KSS + pos] = f2tf(w.w);
        }
    }
    {
        const int j = tid & 127, dh2 = tid >> 7;
        const int rrow = rbase + j;
        if (rrow >= 0 && rrow < S_ && j < 127){
            const float* rr = g_r + (size_t)rrow*D_ + h*DH_ + dh2*32;
            #pragma unroll
            for (int c=0;c<8;c++){
                float4 v = *(const float4*)(rr + c*4);
                int d0 = dh2*32 + c*4;
                Rs[(d0+0)*RSS + j] = f2tf(v.x);
                Rs[(d0+1)*RSS + j] = f2tf(v.y);
                Rs[(d0+2)*RSS + j] = f2tf(v.z);
                Rs[(d0+3)*RSS + j] = f2tf(v.w);
            }
        } else {
            #pragma unroll
            for (int c=0;c<8;c++){
                int d0 = dh2*32 + c*4;
                Rs[(d0+0)*RSS + j] = 0u;
                Rs[(d0+1)*RSS + j] = 0u;
                Rs[(d0+2)*RSS + j] = 0u;
                Rs[(d0+3)*RSS + j] = 0u;
            }
        }
    }
    __syncthreads();

    float accA[4][4]; float accB[8][4];
    #pragma unroll
    for (int nt=0;nt<4;nt++){ accA[nt][0]=accA[nt][1]=accA[nt][2]=accA[nt][3]=0.f; }
    #pragma unroll
    for (int nt=0;nt<8;nt++){ accB[nt][0]=accB[nt][1]=accB[nt][2]=accB[nt][3]=0.f; }

    #pragma unroll
    for (int ks=0; ks<8; ks++){
        uint32_t a[4];
        const int mr = wm*16 + r;
        a[0] = Qs[mr*QSS     + ks*8 + cg];
        a[1] = Qs[(mr+8)*QSS + ks*8 + cg];
        a[2] = Qs[mr*QSS     + ks*8 + cg + 4];
        a[3] = Qs[(mr+8)*QSS + ks*8 + cg + 4];
        #pragma unroll
        for (int nt=0;nt<4;nt++){
            uint32_t bfr[2];
            bfr[0] = Ks[(ks*8+cg  )*KSS + wn*32 + nt*8 + r];
            bfr[1] = Ks[(ks*8+cg+4)*KSS + wn*32 + nt*8 + r];
            mma_tf32(accA[nt], a, bfr);
        }
        #pragma unroll
        for (int nt=0;nt<8;nt++){
            uint32_t bfr[2];
            bfr[0] = Rs[(ks*8+cg  )*RSS + wn*64 + nt*8 + r];
            bfr[1] = Rs[(ks*8+cg+4)*RSS + wn*64 + nt*8 + r];
            mma_tf32(accB[nt], a, bfr);
        }
    }
    #pragma unroll
    for (int nt=0;nt<8;nt++){
        int col = wn*64 + nt*8 + cg*2;
        C2[(wm*16+r  )*CSS + col    ] = accB[nt][0];
        C2[(wm*16+r  )*CSS + col + 1] = accB[nt][1];
        C2[(wm*16+r+8)*CSS + col    ] = accB[nt][2];
        C2[(wm*16+r+8)*CSS + col + 1] = accB[nt][3];
    }
    __syncthreads();

    const float* ukp = g_uk + (size_t)bh*S_ + kt0;
    const float* vrp = g_vr + (size_t)h*S_;
    #pragma unroll
    for (int i=0;i<2;i++){
        const int qr = wm*16 + r + i*8;
        const int q  = qt0 + qr;
        #pragma unroll
        for (int nt=0;nt<4;nt++){
            const int kr0 = wn*32 + nt*8 + cg*2;
            float2 o2;
            #pragma unroll
            for (int cc=0;cc<2;cc++){
                const int kr = kr0 + cc;
                const int k  = kt0 + kr;
                float sc;
                if (k <= q){
                    float bd = C2[qr*CSS + 63 + kr - qr] + vrp[S_-1-q+k];
                    sc = (accA[nt][i*2+cc] + ukp[kr] + bd) * 0.125f;
                } else sc = -1e30f;
                (cc ? o2.y : o2.x) = sc;
            }
            *(float2*)(g_aw + ((size_t)bh*S_ + q)*S_ + kt0 + kr0) = o2;
        }
    }
}

// ---------------- softmax per row --------------------------------------------
__global__ void softmax_kernel(const int* __restrict__ text){
    const int q = blockIdx.x, bh = blockIdx.y, b = bh >> 4;
    float* row = g_aw + ((size_t)bh*S_ + q)*S_;
    const int t = threadIdx.x;
    float4 v = ((float4*)row)[t];
    const int k0 = t*4;
    float vals[4] = {v.x, v.y, v.z, v.w};
    float mx = -1e30f;
    #pragma unroll
    for (int c=0;c<4;c++) if (k0+c <= q) mx = fmaxf(mx, vals[c]);
    #pragma unroll
    for (int o=16;o;o>>=1) mx = fmaxf(mx, __shfl_xor_sync(0xffffffffu, mx, o));
    __shared__ float sh[8], bc[2];
    int w = t>>5, lane = t&31;
    if (!lane) sh[w] = mx;
    __syncthreads();
    if (t==0){ float m=sh[0]; for (int i=1;i<8;i++) m=fmaxf(m,sh[i]); bc[0]=m; }
    __syncthreads();
    mx = bc[0];
    float e[4]; float s = 0.f;
    #pragma unroll
    for (int c=0;c<4;c++){ e[c] = (k0+c <= q) ? __expf(vals[c]-mx) : 0.f; s += e[c]; }
    #pragma unroll
    for (int o=16;o;o>>=1) s += __shfl_xor_sync(0xffffffffu, s, o);
    if (!lane) sh[w] = s;
    __syncthreads();
    if (t==0){ float m=0.f; for (int i=0;i<8;i++) m+=sh[i]; bc[1]=m; }
    __syncthreads();
    bool padq = (text[b*CTX_ + q] == PAD_);
    float inv = padq ? 0.f : 1.0f/bc[1];
    v.x=e[0]*inv; v.y=e[1]*inv; v.z=e[2]*inv; v.w=e[3]*inv;
    ((float4*)row)[t] = v;
}

// ---------------- tensor-core o = aw @ v (tf32, unchanged) -------------------
#define AWS 68
#define VSS 72
__global__ void __launch_bounds__(256)
av2_kernel(){
    const int qt0 = blockIdx.x*64;
    const int bh = blockIdx.y, b = bh>>4, h = bh&15;
    __shared__ uint32_t AWs[64*AWS];
    __shared__ uint32_t Vs [64*VSS];

    const int tid = threadIdx.x;
    const int lane = tid & 31, wid = tid >> 5;
    const int wm = wid >> 1, wn = wid & 1;
    const int r = lane >> 2, cg = lane & 3;
    const int pos = tid & 63, dg = tid >> 6;

    float acc[4][4];
    #pragma unroll
    for (int nt=0;nt<4;nt++){ acc[nt][0]=acc[nt][1]=acc[nt][2]=acc[nt][3]=0.f; }

    for (int kt=0; kt<=blockIdx.x; kt++){
        {
            const float* arow = g_aw + ((size_t)bh*S_ + qt0 + pos)*S_ + kt*64;
            const float* vrow = g_v  + ((size_t)(b*S_ + kt*64 + pos))*D_ + h*DH_;
            #pragma unroll
            for (int c=0;c<4;c++){
                int d0 = dg*16 + c*4;
                float4 v = *(const float4*)(arow + d0);
                uint4 t; t.x=f2tf(v.x); t.y=f2tf(v.y); t.z=f2tf(v.z); t.w=f2tf(v.w);
                *(uint4*)&AWs[pos*AWS + d0] = t;
                float4 w = *(const float4*)(vrow + d0);
                uint4 tw; tw.x=f2tf(w.x); tw.y=f2tf(w.y); tw.z=f2tf(w.z); tw.w=f2tf(w.w);
                *(uint4*)&Vs[pos*VSS + d0] = tw;
            }
        }
        __syncthreads();
        #pragma unroll
        for (int ks=0; ks<8; ks++){
            uint32_t a[4];
            const int mr = wm*16 + r;
            a[0] = AWs[mr*AWS     + ks*8 + cg];
            a[1] = AWs[(mr+8)*AWS + ks*8 + cg];
            a[2] = AWs[mr*AWS     + ks*8 + cg + 4];
            a[3] = AWs[(mr+8)*AWS + ks*8 + cg + 4];
            #pragma unroll
            for (int nt=0;nt<4;nt++){
                uint32_t bfr[2];
                bfr[0] = Vs[(ks*8+cg  )*VSS + wn*32 + nt*8 + r];
                bfr[1] = Vs[(ks*8+cg+4)*VSS + wn*32 + nt*8 + r];
                mma_tf32(acc[nt], a, bfr);
            }
        }
        __syncthreads();
    }
    #pragma unroll
    for (int i=0;i<2;i++){
        int q = qt0 + wm*16 + r + i*8;
        #pragma unroll
        for (int nt=0;nt<4;nt++){
            float2 o2;
            o2.x = acc[nt][i*2+0]; o2.y = acc[nt][i*2+1];
            *(float2*)(g_o + ((size_t)(b*S_ + q))*D_ + h*DH_ + wn*32 + nt*8 + cg*2) = o2;
        }
    }
}

// ---------------- orchestration -----------------------------------------------
extern "C" void kernel_launch(void* const* d_in, const int* in_sizes, int n_in,
                              void* d_out, int out_size)
{
    (void)in_sizes; (void)n_in; (void)out_size;
    const int*   text = (const int*)  d_in[0];
    const float* emb  = (const float*)d_in[1];
    const float* u    = (const float*)d_in[2];
    const float* vbp  = (const float*)d_in[3];
    const float* Wq   = (const float*)d_in[4];
    const float* Wk   = (const float*)d_in[5];
    const float* Wv   = (const float*)d_in[6];
    const float* Wr   = (const float*)d_in[7];
    const float* Wfc  = (const float*)d_in[8];
    const float* bfc  = (const float*)d_in[9];
    const float* ln1g = (const float*)d_in[10];
    const float* ln1b = (const float*)d_in[11];
    const float* ln2g = (const float*)d_in[12];
    const float* ln2b = (const float*)d_in[13];
    const float* W1   = (const float*)d_in[14];
    const float* b1   = (const float*)d_in[15];
    const float* W2   = (const float*)d_in[16];
    const float* b2   = (const float*)d_in[17];
    const float* lnfg = (const float*)d_in[18];
    const float* lnfb = (const float*)d_in[19];
    const float* Wlm  = (const float*)d_in[20];
    const float* blm  = (const float*)d_in[21];
    float* out = (float*)d_out;

    float *px,*pxn,*pq,*pk,*pv,*po,*prel,*pr,*pff;
    cudaGetSymbolAddress((void**)&px,   g_x);
    cudaGetSymbolAddress((void**)&pxn,  g_xn);
    cudaGetSymbolAddress((void**)&pq,   g_q);
    cudaGetSymbolAddress((void**)&pk,   g_k);
    cudaGetSymbolAddress((void**)&pv,   g_v);
    cudaGetSymbolAddress((void**)&po,   g_o);
    cudaGetSymbolAddress((void**)&prel, g_rel);
    cudaGetSymbolAddress((void**)&pr,   g_r);
    cudaGetSymbolAddress((void**)&pff,  g_ff);

    static bool attr_done = false;
    if (!attr_done){
        cudaFuncSetAttribute(score_kernel, cudaFuncAttributeMaxDynamicSharedMemorySize, SC_SMEM);
        attr_done = true;
    }

    const int MR = B_*S_;

    embed_kernel<<<2048,256>>>(text, emb);
    rel_kernel  <<<2048,256>>>();

    for (int l=0; l<L_; l++){
        ln_kernel<<<MR,256>>>(px, pxn, ln1g + l*D_, ln1b + l*D_);

        qkvr_kernel<<<dim3(D_/TBN, MR/TBM, 4),256>>>(
            pxn, prel,
            Wq + (size_t)l*D_*D_, Wk + (size_t)l*D_*D_,
            Wv + (size_t)l*D_*D_, Wr + (size_t)l*D_*D_,
            pq, pk, pv, pr);

        bias_kernel   <<<dim3(B_*S_, 2),256>>>(u, vbp);
        score_kernel  <<<dim3(16,16,B_*H_),256, SC_SMEM>>>();
        softmax_kernel<<<dim3(S_, B_*H_),256>>>(text);
        av2_kernel    <<<dim3(16, B_*H_),256>>>();

        // x = x + xn + o@Wfc + bfc
        hgemm_kernel<3><<<dim3(D_/TBN, MR/TBM),256>>>(
            po, Wfc + (size_t)l*D_*D_, bfc + l*D_, px, px, pxn, D_, D_);

        ln_kernel<<<MR,256>>>(px, pxn, ln2g + l*D_, ln2b + l*D_);
        hgemm_kernel<2><<<dim3(FF_/TBN, MR/TBM),256>>>(
            pxn, W1 + (size_t)l*D_*FF_, b1 + l*FF_, pff, nullptr, nullptr, FF_, D_);
        // x = x + gelu(ff@W2 + b2)
        hgemm_kernel<4><<<dim3(D_/TBN, MR/TBM),256>>>(
            pff, W2 + (size_t)l*FF_*D_, b2 + l*D_, px, px, nullptr, D_, FF_);
    }

    ln_kernel<<<MR,256>>>(px, pxn, lnfg, lnfb);
    hgemm_kernel<1><<<dim3(V_/TBN, MR/TBM),256>>>(
        pxn, Wlm, blm, out, nullptr, nullptr, V_, D_);
}

// round 6
// speedup vs baseline: 2.0200x; 1.3376x over previous
#include <cuda_runtime.h>
#include <cuda_fp16.h>
#include <stdint.h>
#include <math.h>

#define B_   2
#define S_   1024
#define D_   1024
#define H_   16
#define DH_  64
#define FF_  4096
#define V_   32000
#define L_   4
#define PAD_ 3
#define CTX_ 1025

// ---------------- scratch (fp32) ----------------------------------------------
__device__ float g_x  [B_*S_*D_];
__device__ float g_xn [B_*S_*D_];
__device__ float g_q  [B_*S_*D_];
__device__ float g_k  [B_*S_*D_];
__device__ float g_v  [B_*S_*D_];
__device__ float g_r  [S_*D_];
__device__ float g_aw [(size_t)B_*H_*S_*S_];
__device__ float g_uk [B_*H_*S_];
__device__ float g_vr [H_*S_];

// ---------------- fp16 weights + activations -----------------------------------
__device__ __align__(16) __half h_Wq [L_*D_*D_];
__device__ __align__(16) __half h_Wk [L_*D_*D_];
__device__ __align__(16) __half h_Wv [L_*D_*D_];
__device__ __align__(16) __half h_Wr [L_*D_*D_];
__device__ __align__(16) __half h_Wfc[L_*D_*D_];
__device__ __align__(16) __half h_W1 [L_*D_*FF_];
__device__ __align__(16) __half h_W2 [L_*FF_*D_];
__device__ __align__(16) __half h_Wlm[(size_t)D_*V_];
__device__ __align__(16) __half h_xn [B_*S_*D_];
__device__ __align__(16) __half h_rel[S_*D_];
__device__ __align__(16) __half h_o  [B_*S_*D_];
__device__ __align__(16) __half h_ff [B_*S_*FF_];

// ---------------- helpers --------------------------------------------------
__device__ __forceinline__ float gelu_t(float x){
    return 0.5f*x*(1.0f + tanhf(0.7978845608028654f*(x + 0.044715f*x*x*x)));
}
__device__ __forceinline__ uint32_t f2tf(float x){
    uint32_t y; asm("cvt.rna.tf32.f32 %0, %1;" : "=r"(y) : "f"(x)); return y;
}
__device__ __forceinline__ uint32_t smaddr(const void* p){
    return (uint32_t)__cvta_generic_to_shared(p);
}
__device__ __forceinline__ void cp16(void* smem, const void* gmem){
    asm volatile("cp.async.cg.shared.global [%0], [%1], 16;\n"
        :: "r"(smaddr(smem)), "l"(gmem));
}
#define CP_COMMIT() asm volatile("cp.async.commit_group;\n" ::: "memory")
#define CP_WAIT(N)  asm volatile("cp.async.wait_group %0;\n" :: "n"(N) : "memory")

__device__ __forceinline__ void mma_tf32(float c[4], const uint32_t a[4], const uint32_t b[2]){
    asm volatile(
      "mma.sync.aligned.m16n8k8.row.col.f32.tf32.tf32.f32 "
      "{%0,%1,%2,%3}, {%4,%5,%6,%7}, {%8,%9}, {%0,%1,%2,%3};\n"
      : "+f"(c[0]), "+f"(c[1]), "+f"(c[2]), "+f"(c[3])
      : "r"(a[0]), "r"(a[1]), "r"(a[2]), "r"(a[3]), "r"(b[0]), "r"(b[1]));
}
__device__ __forceinline__ void mma_f16(float c[4], const uint32_t a[4], const uint32_t b0, const uint32_t b1){
    asm volatile(
      "mma.sync.aligned.m16n8k16.row.col.f32.f16.f16.f32 "
      "{%0,%1,%2,%3}, {%4,%5,%6,%7}, {%8,%9}, {%0,%1,%2,%3};\n"
      : "+f"(c[0]), "+f"(c[1]), "+f"(c[2]), "+f"(c[3])
      : "r"(a[0]), "r"(a[1]), "r"(a[2]), "r"(a[3]), "r"(b0), "r"(b1));
}
__device__ __forceinline__ void ldsm_x4(uint32_t r[4], uint32_t addr){
    asm volatile("ldmatrix.sync.aligned.m8n8.x4.shared.b16 {%0,%1,%2,%3}, [%4];"
      : "=r"(r[0]), "=r"(r[1]), "=r"(r[2]), "=r"(r[3]) : "r"(addr));
}
__device__ __forceinline__ void ldsm_x4_t(uint32_t r[4], uint32_t addr){
    asm volatile("ldmatrix.sync.aligned.m8n8.x4.trans.shared.b16 {%0,%1,%2,%3}, [%4];"
      : "=r"(r[0]), "=r"(r[1]), "=r"(r[2]), "=r"(r[3]) : "r"(addr));
}

// ---------------- fp32 -> fp16 convert ----------------------------------------
__global__ void cvt_kernel(const float4* __restrict__ src, uint2* __restrict__ dst, int n4){
    int i = blockIdx.x*256 + threadIdx.x;
    if (i < n4){
        float4 v = src[i];
        __half2 h0 = __floats2half2_rn(v.x, v.y);
        __half2 h1 = __floats2half2_rn(v.z, v.w);
        dst[i] = make_uint2(*(uint32_t*)&h0, *(uint32_t*)&h1);
    }
}

// ---------------- embedding ------------------------------------------------
__global__ void embed_kernel(const int* __restrict__ text, const float* __restrict__ emb){
    int idx = blockIdx.x*256 + threadIdx.x;
    int d4  = idx & (D_/4 - 1);
    int bs  = idx >> 8;
    int s   = bs & (S_-1);
    int b   = bs >> 10;
    int tok = text[b*CTX_ + s];
    ((float4*)g_x)[idx] = ((const float4*)(emb + (size_t)tok*D_))[d4];
}

// ---------------- sinusoidal relative positions (fp16 out) ------------------
__global__ void rel_kernel(){
    int idx = blockIdx.x*256 + threadIdx.x;
    int j = idx & 511;
    int s = idx >> 9;
    float pos  = (float)(S_-1-s);
    float invf = powf(10000.0f, -(float)(2*j)/(float)D_);
    float a = pos*invf;
    h_rel[s*D_ + j]       = __float2half_rn(sinf(a));
    h_rel[s*D_ + j + 512] = __float2half_rn(cosf(a));
}

// ---------------- layernorm (writes fp32 + fp16) ----------------------------
__global__ void ln_kernel(const float* __restrict__ in, float* __restrict__ out,
                          __half* __restrict__ out16,
                          const float* __restrict__ gam, const float* __restrict__ bet){
    int row = blockIdx.x;
    int t = threadIdx.x;
    const float4* x4 = (const float4*)(in + (size_t)row*D_);
    float4 v = x4[t];
    float s  = v.x+v.y+v.z+v.w;
    float s2 = v.x*v.x+v.y*v.y+v.z*v.z+v.w*v.w;
    #pragma unroll
    for (int o=16;o;o>>=1){ s += __shfl_xor_sync(0xffffffffu,s,o); s2 += __shfl_xor_sync(0xffffffffu,s2,o); }
    __shared__ float shs[8], shs2[8], bc[2];
    int w = t>>5, lane = t&31;
    if (!lane){ shs[w]=s; shs2[w]=s2; }
    __syncthreads();
    if (t==0){
        float ts=0.f, ts2=0.f;
        #pragma unroll
        for (int i=0;i<8;i++){ ts+=shs[i]; ts2+=shs2[i]; }
        float m   = ts*(1.0f/(float)D_);
        float var = ts2*(1.0f/(float)D_) - m*m;
        bc[0]=m; bc[1]=rsqrtf(var + 1e-5f);
    }
    __syncthreads();
    float m = bc[0], inv = bc[1];
    float4 gg = ((const float4*)gam)[t];
    float4 bb = ((const float4*)bet)[t];
    float4 o4;
    o4.x = (v.x-m)*inv*gg.x + bb.x;
    o4.y = (v.y-m)*inv*gg.y + bb.y;
    o4.z = (v.z-m)*inv*gg.z + bb.z;
    o4.w = (v.w-m)*inv*gg.w + bb.w;
    ((float4*)(out + (size_t)row*D_))[t] = o4;
    __half2 p0 = __floats2half2_rn(o4.x, o4.y);
    __half2 p1 = __floats2half2_rn(o4.z, o4.w);
    *(uint2*)(out16 + (size_t)row*D_ + t*4) = make_uint2(*(uint32_t*)&p0, *(uint32_t*)&p1);
}

// ================= fp16 GEMM with cp.async 4-stage pipeline =================
// CTA 128x128x32, 256 thr, 8 warps (4m x 2n), warp 32x64, mma m16n8k16.
// blockIdx.x = M-block, blockIdx.y = N-block (L2-friendly B reuse).
#define TBM 128
#define TBN 128
#define TBK 32
#define STAGES 4
#define HG_SMEM ((STAGES*TBM*40 + STAGES*TBK*136)*2)

// EPI: 0 plain | 1 +bias | 2 gelu(acc+bias) | 3 R1+R2+acc+bias | 4 R1+gelu(acc+bias)
template<int EPI, typename TC>
__device__ __forceinline__ void hgemm_body(
    const __half* __restrict__ A, const __half* __restrict__ Bm,
    const float* __restrict__ bias, TC* __restrict__ C,
    const float* __restrict__ R1, const float* __restrict__ R2,
    int N, int K)
{
    extern __shared__ __half hsm[];
    __half* Asm = hsm;                       // [STAGES][TBM][40]
    __half* Bsm = hsm + STAGES*TBM*40;       // [STAGES][TBK][136]

    const int tid = threadIdx.x;
    const int lane = tid & 31, wid = tid >> 5;
    const int wm = wid >> 1, wn = wid & 1;
    const int r = lane >> 2, cg = lane & 3;
    const int bm = blockIdx.x*TBM, bn = blockIdx.y*TBN;

    // cp.async fill roles
    const int arow = tid >> 1, ac0 = (tid & 1)*16;   // A: row, 16-half chunk pair
    const int brow = tid >> 3, bc0 = (tid & 7)*16;   // B: k-row, 16-half chunk pair

    // ldmatrix lane roles
    const int aRowL = lane & 15, aKH = lane >> 4;
    const int bKL   = (lane & 7) + ((lane >> 3) & 1)*8, bNH = lane >> 4;

    float acc[2][8][4];
    #pragma unroll
    for (int mt=0;mt<2;mt++)
        #pragma unroll
        for (int nt=0;nt<8;nt++)
            #pragma unroll
            for (int i=0;i<4;i++) acc[mt][nt][i]=0.f;

    const int nkt = K/TBK;

    auto issue = [&](int kt, int s){
        __half* as = Asm + (s*TBM + arow)*40 + ac0;
        const __half* ap = A + (size_t)(bm+arow)*K + kt*TBK + ac0;
        cp16(as,   ap);
        cp16(as+8, ap+8);
        __half* bs = Bsm + (s*TBK + brow)*136 + bc0;
        const __half* bp = Bm + (size_t)(kt*TBK + brow)*N + bn + bc0;
        cp16(bs,   bp);
        cp16(bs+8, bp+8);
    };

    #pragma unroll
    for (int s=0; s<STAGES-1; s++){ issue(s, s); CP_COMMIT(); }

    for (int kt=0; kt<nkt; kt++){
        CP_WAIT(STAGES-2);
        __syncthreads();
        const int nk = kt + STAGES-1;
        if (nk < nkt) issue(nk, nk & (STAGES-1));
        CP_COMMIT();

        const int s = kt & (STAGES-1);
        const __half* as = Asm + (size_t)s*TBM*40;
        const __half* bs = Bsm + (size_t)s*TBK*136;
        #pragma unroll
        for (int ks=0; ks<2; ks++){
            uint32_t af[2][4];
            #pragma unroll
            for (int mt=0;mt<2;mt++)
                ldsm_x4(af[mt], smaddr(as + (wm*32 + mt*16 + aRowL)*40 + ks*16 + aKH*8));
            #pragma unroll
            for (int nt=0;nt<4;nt++){
                uint32_t bf[4];
                ldsm_x4_t(bf, smaddr(bs + (ks*16 + bKL)*136 + wn*64 + nt*16 + bNH*8));
                mma_f16(acc[0][nt*2+0], af[0], bf[0], bf[1]);
                mma_f16(acc[1][nt*2+0], af[1], bf[0], bf[1]);
                mma_f16(acc[0][nt*2+1], af[0], bf[2], bf[3]);
                mma_f16(acc[1][nt*2+1], af[1], bf[2], bf[3]);
            }
        }
    }

    // -------- epilogue
    #pragma unroll
    for (int mt=0;mt<2;mt++){
        int row0 = bm + wm*32 + mt*16 + r;
        #pragma unroll
        for (int nt=0;nt<8;nt++){
            int col = bn + wn*64 + nt*8 + cg*2;
            float2 b2 = make_float2(0.f,0.f);
            if (EPI >= 1) b2 = *(const float2*)(bias + col);
            float2 v0, v1;
            v0.x = acc[mt][nt][0] + b2.x; v0.y = acc[mt][nt][1] + b2.y;
            v1.x = acc[mt][nt][2] + b2.x; v1.y = acc[mt][nt][3] + b2.y;
            if (EPI == 2 || EPI == 4){
                v0.x = gelu_t(v0.x); v0.y = gelu_t(v0.y);
                v1.x = gelu_t(v1.x); v1.y = gelu_t(v1.y);
            }
            size_t i0 = (size_t)row0*N + col, i1 = (size_t)(row0+8)*N + col;
            if (EPI == 3){
                float2 a0 = *(const float2*)(R1 + i0), a1 = *(const float2*)(R1 + i1);
                float2 x0 = *(const float2*)(R2 + i0), x1 = *(const float2*)(R2 + i1);
                v0.x += a0.x + x0.x; v0.y += a0.y + x0.y;
                v1.x += a1.x + x1.x; v1.y += a1.y + x1.y;
            }
            if (EPI == 4){
                float2 a0 = *(const float2*)(R1 + i0), a1 = *(const float2*)(R1 + i1);
                v0.x += a0.x; v0.y += a0.y;
                v1.x += a1.x; v1.y += a1.y;
            }
            if constexpr (sizeof(TC) == 2){
                *(__half2*)(C + i0) = __floats2half2_rn(v0.x, v0.y);
                *(__half2*)(C + i1) = __floats2half2_rn(v1.x, v1.y);
            } else {
                *(float2*)(C + i0) = v0;
                *(float2*)(C + i1) = v1;
            }
        }
    }
}

template<int EPI, typename TC>
__global__ void __launch_bounds__(256)
hgemm_kernel(const __half* __restrict__ A, const __half* __restrict__ Bm,
             const float* __restrict__ bias, TC* __restrict__ C,
             const float* __restrict__ R1, const float* __restrict__ R2,
             int N, int K)
{
    hgemm_body<EPI, TC>(A, Bm, bias, C, R1, R2, N, K);
}

__global__ void __launch_bounds__(256)
qkvr_kernel(int l, float* __restrict__ q, float* __restrict__ k,
            float* __restrict__ v, float* __restrict__ rr)
{
    const int z = blockIdx.z;
    if (z == 3 && blockIdx.x*TBM >= S_) return;
    const __half* A = (z < 3) ? h_xn : h_rel;
    const __half* W = ((z==0) ? h_Wq : (z==1) ? h_Wk : (z==2) ? h_Wv : h_Wr) + (size_t)l*D_*D_;
    float*        C = (z==0) ? q  : (z==1) ? k  : (z==2) ? v  : rr;
    hgemm_body<0, float>(A, W, nullptr, C, nullptr, nullptr, D_, D_);
}

// ---------------- bias precompute: uk[b,h,key]=u·k, vr[h,row]=v·r ----------
__global__ void bias_kernel(const float* __restrict__ uvec, const float* __restrict__ vvec){
    const int t = threadIdx.x;
    if (blockIdx.y == 0){
        int row = blockIdx.x;
        float4 kv = ((const float4*)(g_k + (size_t)row*D_))[t];
        float4 uu = ((const float4*)uvec)[t];
        float p = kv.x*uu.x + kv.y*uu.y + kv.z*uu.z + kv.w*uu.w;
        p += __shfl_xor_sync(0xffffffffu, p, 8);
        p += __shfl_xor_sync(0xffffffffu, p, 4);
        p += __shfl_xor_sync(0xffffffffu, p, 2);
        p += __shfl_xor_sync(0xffffffffu, p, 1);
        if ((t & 15) == 0){
            int h = t >> 4;
            int b = row >> 10, key = row & (S_-1);
            g_uk[((size_t)(b*H_ + h))*S_ + key] = p;
        }
    } else {
        int rrow = blockIdx.x;
        if (rrow >= S_) return;
        float4 rv = ((const float4*)(g_r + (size_t)rrow*D_))[t];
        float4 vv = ((const float4*)vvec)[t];
        float p = rv.x*vv.x + rv.y*vv.y + rv.z*vv.z + rv.w*vv.w;
        p += __shfl_xor_sync(0xffffffffu, p, 8);
        p += __shfl_xor_sync(0xffffffffu, p, 4);
        p += __shfl_xor_sync(0xffffffffu, p, 2);
        p += __shfl_xor_sync(0xffffffffu, p, 1);
        if ((t & 15) == 0)
            g_vr[(t>>4)*S_ + rrow] = p;
    }
}

// ---------------- tensor-core score kernel (tf32, unchanged) ----------------
#define QSS 68
#define KSS 72
#define RSS 136
#define CSS 132
#define SC_SMEM ((64*QSS + 64*KSS + 64*RSS + 64*CSS)*4)

__global__ void __launch_bounds__(256)
score_kernel(){
    if (blockIdx.x > blockIdx.y) return;
    const int kt0 = blockIdx.x*64, qt0 = blockIdx.y*64;
    const int bh = blockIdx.z, b = bh >> 4, h = bh & 15;
    const int rbase = S_ - 64 - qt0 + kt0;

    extern __shared__ uint32_t sm[];
    uint32_t* Qs = sm;
    uint32_t* Ks = Qs + 64*QSS;
    uint32_t* Rs = Ks + 64*KSS;
    float*    C2 = (float*)(Rs + 64*RSS);

    const int tid = threadIdx.x;
    const int lane = tid & 31, wid = tid >> 5;
    const int wm = wid >> 1, wn = wid & 1;
    const int r = lane >> 2, cg = lane & 3;

    {
        const int pos = tid & 63, dg = tid >> 6;
        const float* qrow = g_q + ((size_t)(b*S_ + qt0 + pos))*D_ + h*DH_;
        const float* krow = g_k + ((size_t)(b*S_ + kt0 + pos))*D_ + h*DH_;
        #pragma unroll
        for (int c=0;c<4;c++){
            int d0 = dg*16 + c*4;
            float4 v = *(const float4*)(qrow + d0);
            uint4 t; t.x=f2tf(v.x); t.y=f2tf(v.y); t.z=f2tf(v.z); t.w=f2tf(v.w);
            *(uint4*)&Qs[pos*QSS + d0] = t;
            float4 w = *(const float4*)(krow + d0);
            Ks[(d0+0)*KSS + pos] = f2tf(w.x);
            Ks[(d0+1)*KSS + pos] = f2tf(w.y);
            Ks[(d0+2)*KSS + pos] = f2tf(w.z);
            Ks[(d0+3)*KSS + pos] = f2tf(w.w);
        }
    }
    {
        const int j = tid & 127, dh2 = tid >> 7;
        const int rrow = rbase + j;
        if (rrow >= 0 && rrow < S_ && j < 127){
            const float* rr = g_r + (size_t)rrow*D_ + h*DH_ + dh2*32;
            #pragma unroll
            for (int c=0;c<8;c++){
                float4 v = *(const float4*)(rr + c*4);
                int d0 = dh2*32 + c*4;
                Rs[(d0+0)*RSS + j] = f2tf(v.x);
                Rs[(d0+1)*RSS + j] = f2tf(v.y);
                Rs[(d0+2)*RSS + j] = f2tf(v.z);
                Rs[(d0+3)*RSS + j] = f2tf(v.w);
            }
        } else {
            #pragma unroll
            for (int c=0;c<8;c++){
                int d0 = dh2*32 + c*4;
                Rs[(d0+0)*RSS + j] = 0u;
                Rs[(d0+1)*RSS + j] = 0u;
                Rs[(d0+2)*RSS + j] = 0u;
                Rs[(d0+3)*RSS + j] = 0u;
            }
        }
    }
    __syncthreads();

    float accA[4][4]; float accB[8][4];
    #pragma unroll
    for (int nt=0;nt<4;nt++){ accA[nt][0]=accA[nt][1]=accA[nt][2]=accA[nt][3]=0.f; }
    #pragma unroll
    for (int nt=0;nt<8;nt++){ accB[nt][0]=accB[nt][1]=accB[nt][2]=accB[nt][3]=0.f; }

    #pragma unroll
    for (int ks=0; ks<8; ks++){
        uint32_t a[4];
        const int mr = wm*16 + r;
        a[0] = Qs[mr*QSS     + ks*8 + cg];
        a[1] = Qs[(mr+8)*QSS + ks*8 + cg];
        a[2] = Qs[mr*QSS     + ks*8 + cg + 4];
        a[3] = Qs[(mr+8)*QSS + ks*8 + cg + 4];
        #pragma unroll
        for (int nt=0;nt<4;nt++){
            uint32_t bfr[2];
            bfr[0] = Ks[(ks*8+cg  )*KSS + wn*32 + nt*8 + r];
            bfr[1] = Ks[(ks*8+cg+4)*KSS + wn*32 + nt*8 + r];
            mma_tf32(accA[nt], a, bfr);
        }
        #pragma unroll
        for (int nt=0;nt<8;nt++){
            uint32_t bfr[2];
            bfr[0] = Rs[(ks*8+cg  )*RSS + wn*64 + nt*8 + r];
            bfr[1] = Rs[(ks*8+cg+4)*RSS + wn*64 + nt*8 + r];
            mma_tf32(accB[nt], a, bfr);
        }
    }
    #pragma unroll
    for (int nt=0;nt<8;nt++){
        int col = wn*64 + nt*8 + cg*2;
        C2[(wm*16+r  )*CSS + col    ] = accB[nt][0];
        C2[(wm*16+r  )*CSS + col + 1] = accB[nt][1];
        C2[(wm*16+r+8)*CSS + col    ] = accB[nt][2];
        C2[(wm*16+r+8)*CSS + col + 1] = accB[nt][3];
    }
    __syncthreads();

    const float* ukp = g_uk + (size_t)bh*S_ + kt0;
    const float* vrp = g_vr + (size_t)h*S_;
    #pragma unroll
    for (int i=0;i<2;i++){
        const int qr = wm*16 + r + i*8;
        const int q  = qt0 + qr;
        #pragma unroll
        for (int nt=0;nt<4;nt++){
            const int kr0 = wn*32 + nt*8 + cg*2;
            float2 o2;
            #pragma unroll
            for (int cc=0;cc<2;cc++){
                const int kr = kr0 + cc;
                const int k  = kt0 + kr;
                float sc;
                if (k <= q){
                    float bd = C2[qr*CSS + 63 + kr - qr] + vrp[S_-1-q+k];
                    sc = (accA[nt][i*2+cc] + ukp[kr] + bd) * 0.125f;
                } else sc = -1e30f;
                (cc ? o2.y : o2.x) = sc;
            }
            *(float2*)(g_aw + ((size_t)bh*S_ + q)*S_ + kt0 + kr0) = o2;
        }
    }
}

// ---------------- softmax per row --------------------------------------------
__global__ void softmax_kernel(const int* __restrict__ text){
    const int q = blockIdx.x, bh = blockIdx.y, b = bh >> 4;
    float* row = g_aw + ((size_t)bh*S_ + q)*S_;
    const int t = threadIdx.x;
    float4 v = ((float4*)row)[t];
    const int k0 = t*4;
    float vals[4] = {v.x, v.y, v.z, v.w};
    float mx = -1e30f;
    #pragma unroll
    for (int c=0;c<4;c++) if (k0+c <= q) mx = fmaxf(mx, vals[c]);
    #pragma unroll
    for (int o=16;o;o>>=1) mx = fmaxf(mx, __shfl_xor_sync(0xffffffffu, mx, o));
    __shared__ float sh[8], bc[2];
    int w = t>>5, lane = t&31;
    if (!lane) sh[w] = mx;
    __syncthreads();
    if (t==0){ float m=sh[0]; for (int i=1;i<8;i++) m=fmaxf(m,sh[i]); bc[0]=m; }
    __syncthreads();
    mx = bc[0];
    float e[4]; float s = 0.f;
    #pragma unroll
    for (int c=0;c<4;c++){ e[c] = (k0+c <= q) ? __expf(vals[c]-mx) : 0.f; s += e[c]; }
    #pragma unroll
    for (int o=16;o;o>>=1) s += __shfl_xor_sync(0xffffffffu, s, o);
    if (!lane) sh[w] = s;
    __syncthreads();
    if (t==0){ float m=0.f; for (int i=0;i<8;i++) m+=sh[i]; bc[1]=m; }
    __syncthreads();
    bool padq = (text[b*CTX_ + q] == PAD_);
    float inv = padq ? 0.f : 1.0f/bc[1];
    v.x=e[0]*inv; v.y=e[1]*inv; v.z=e[2]*inv; v.w=e[3]*inv;
    ((float4*)row)[t] = v;
}

// ---------------- tensor-core o = aw @ v (tf32 in, fp16 out) ----------------
#define AWS 68
#define VSS 72
__global__ void __launch_bounds__(256)
av2_kernel(){
    const int qt0 = blockIdx.x*64;
    const int bh = blockIdx.y, b = bh>>4, h = bh&15;
    __shared__ uint32_t AWs[64*AWS];
    __shared__ uint32_t Vs [64*VSS];

    const int tid = threadIdx.x;
    const int lane = tid & 31, wid = tid >> 5;
    const int wm = wid >> 1, wn = wid & 1;
    const int r = lane >> 2, cg = lane & 3;
    const int pos = tid & 63, dg = tid >> 6;

    float acc[4][4];
    #pragma unroll
    for (int nt=0;nt<4;nt++){ acc[nt][0]=acc[nt][1]=acc[nt][2]=acc[nt][3]=0.f; }

    for (int kt=0; kt<=blockIdx.x; kt++){
        {
            const float* arow = g_aw + ((size_t)bh*S_ + qt0 + pos)*S_ + kt*64;
            const float* vrow = g_v  + ((size_t)(b*S_ + kt*64 + pos))*D_ + h*DH_;
            #pragma unroll
            for (int c=0;c<4;c++){
                int d0 = dg*16 + c*4;
                float4 v = *(const float4*)(arow + d0);
                uint4 t; t.x=f2tf(v.x); t.y=f2tf(v.y); t.z=f2tf(v.z); t.w=f2tf(v.w);
                *(uint4*)&AWs[pos*AWS + d0] = t;
                float4 w = *(const float4*)(vrow + d0);
                uint4 tw; tw.x=f2tf(w.x); tw.y=f2tf(w.y); tw.z=f2tf(w.z); tw.w=f2tf(w.w);
                *(uint4*)&Vs[pos*VSS + d0] = tw;
            }
        }
        __syncthreads();
        #pragma unroll
        for (int ks=0; ks<8; ks++){
            uint32_t a[4];
            const int mr = wm*16 + r;
            a[0] = AWs[mr*AWS     + ks*8 + cg];
            a[1] = AWs[(mr+8)*AWS + ks*8 + cg];
            a[2] = AWs[mr*AWS     + ks*8 + cg + 4];
            a[3] = AWs[(mr+8)*AWS + ks*8 + cg + 4];
            #pragma unroll
            for (int nt=0;nt<4;nt++){
                uint32_t bfr[2];
                bfr[0] = Vs[(ks*8+cg  )*VSS + wn*32 + nt*8 + r];
                bfr[1] = Vs[(ks*8+cg+4)*VSS + wn*32 + nt*8 + r];
                mma_tf32(acc[nt], a, bfr);
            }
        }
        __syncthreads();
    }
    #pragma unroll
    for (int i=0;i<2;i++){
        int q = qt0 + wm*16 + r + i*8;
        #pragma unroll
        for (int nt=0;nt<4;nt++){
            __half2 o2 = __floats2half2_rn(acc[nt][i*2+0], acc[nt][i*2+1]);
            *(__half2*)(h_o + ((size_t)(b*S_ + q))*D_ + h*DH_ + wn*32 + nt*8 + cg*2) = o2;
        }
    }
}

// ---------------- orchestration -----------------------------------------------
extern "C" void kernel_launch(void* const* d_in, const int* in_sizes, int n_in,
                              void* d_out, int out_size)
{
    (void)in_sizes; (void)n_in; (void)out_size;
    const int*   text = (const int*)  d_in[0];
    const float* emb  = (const float*)d_in[1];
    const float* u    = (const float*)d_in[2];
    const float* vbp  = (const float*)d_in[3];
    const float* Wq   = (const float*)d_in[4];
    const float* Wk   = (const float*)d_in[5];
    const float* Wv   = (const float*)d_in[6];
    const float* Wr   = (const float*)d_in[7];
    const float* Wfc  = (const float*)d_in[8];
    const float* bfc  = (const float*)d_in[9];
    const float* ln1g = (const float*)d_in[10];
    const float* ln1b = (const float*)d_in[11];
    const float* ln2g = (const float*)d_in[12];
    const float* ln2b = (const float*)d_in[13];
    const float* W1   = (const float*)d_in[14];
    const float* b1   = (const float*)d_in[15];
    const float* W2   = (const float*)d_in[16];
    const float* b2   = (const float*)d_in[17];
    const float* lnfg = (const float*)d_in[18];
    const float* lnfb = (const float*)d_in[19];
    const float* Wlm  = (const float*)d_in[20];
    const float* blm  = (const float*)d_in[21];
    float* out = (float*)d_out;

    float *px,*pxn,*pq,*pk,*pv,*pr;
    __half *pWq16,*pWk16,*pWv16,*pWr16,*pWfc16,*pW116,*pW216,*pWlm16,*pxn16,*po16,*pff16;
    cudaGetSymbolAddress((void**)&px,   g_x);
    cudaGetSymbolAddress((void**)&pxn,  g_xn);
    cudaGetSymbolAddress((void**)&pq,   g_q);
    cudaGetSymbolAddress((void**)&pk,   g_k);
    cudaGetSymbolAddress((void**)&pv,   g_v);
    cudaGetSymbolAddress((void**)&pr,   g_r);
    cudaGetSymbolAddress((void**)&pWq16, h_Wq);
    cudaGetSymbolAddress((void**)&pWk16, h_Wk);
    cudaGetSymbolAddress((void**)&pWv16, h_Wv);
    cudaGetSymbolAddress((void**)&pWr16, h_Wr);
    cudaGetSymbolAddress((void**)&pWfc16,h_Wfc);
    cudaGetSymbolAddress((void**)&pW116, h_W1);
    cudaGetSymbolAddress((void**)&pW216, h_W2);
    cudaGetSymbolAddress((void**)&pWlm16,h_Wlm);
    cudaGetSymbolAddress((void**)&pxn16, h_xn);
    cudaGetSymbolAddress((void**)&po16,  h_o);
    cudaGetSymbolAddress((void**)&pff16, h_ff);

    static bool attr_done = false;
    if (!attr_done){
        cudaFuncSetAttribute(score_kernel, cudaFuncAttributeMaxDynamicSharedMemorySize, SC_SMEM);
        cudaFuncSetAttribute(qkvr_kernel,  cudaFuncAttributeMaxDynamicSharedMemorySize, HG_SMEM);
        cudaFuncSetAttribute((const void*)hgemm_kernel<1,float>,  cudaFuncAttributeMaxDynamicSharedMemorySize, HG_SMEM);
        cudaFuncSetAttribute((const void*)hgemm_kernel<2,__half>, cudaFuncAttributeMaxDynamicSharedMemorySize, HG_SMEM);
        cudaFuncSetAttribute((const void*)hgemm_kernel<3,float>,  cudaFuncAttributeMaxDynamicSharedMemorySize, HG_SMEM);
        cudaFuncSetAttribute((const void*)hgemm_kernel<4,float>,  cudaFuncAttributeMaxDynamicSharedMemorySize, HG_SMEM);
        attr_done = true;
    }

    const int MR = B_*S_;

    // ---- fp32 -> fp16 weight conversion (every call; deterministic) --------
    {
        int n4;
        n4 = L_*D_*D_/4;
        cvt_kernel<<<(n4+255)/256,256>>>((const float4*)Wq,  (uint2*)pWq16,  n4);
        cvt_kernel<<<(n4+255)/256,256>>>((const float4*)Wk,  (uint2*)pWk16,  n4);
        cvt_kernel<<<(n4+255)/256,256>>>((const float4*)Wv,  (uint2*)pWv16,  n4);
        cvt_kernel<<<(n4+255)/256,256>>>((const float4*)Wr,  (uint2*)pWr16,  n4);
        cvt_kernel<<<(n4+255)/256,256>>>((const float4*)Wfc, (uint2*)pWfc16, n4);
        n4 = L_*D_*FF_/4;
        cvt_kernel<<<(n4+255)/256,256>>>((const float4*)W1,  (uint2*)pW116,  n4);
        cvt_kernel<<<(n4+255)/256,256>>>((const float4*)W2,  (uint2*)pW216,  n4);
        n4 = D_*V_/4;
        cvt_kernel<<<(n4+255)/256,256>>>((const float4*)Wlm, (uint2*)pWlm16, n4);
    }

    embed_kernel<<<2048,256>>>(text, emb);
    rel_kernel  <<<2048,256>>>();

    for (int l=0; l<L_; l++){
        ln_kernel<<<MR,256>>>(px, pxn, pxn16, ln1g + l*D_, ln1b + l*D_);

        qkvr_kernel<<<dim3(MR/TBM, D_/TBN, 4),256, HG_SMEM>>>(l, pq, pk, pv, pr);

        bias_kernel   <<<dim3(B_*S_, 2),256>>>(u, vbp);
        score_kernel  <<<dim3(16,16,B_*H_),256, SC_SMEM>>>();
        softmax_kernel<<<dim3(S_, B_*H_),256>>>(text);
        av2_kernel    <<<dim3(16, B_*H_),256>>>();

        // x = x + xn + o@Wfc + bfc
        hgemm_kernel<3,float><<<dim3(MR/TBM, D_/TBN),256, HG_SMEM>>>(
            po16, pWfc16 + (size_t)l*D_*D_, bfc + l*D_, px, px, pxn, D_, D_);

        ln_kernel<<<MR,256>>>(px, pxn, pxn16, ln2g + l*D_, ln2b + l*D_);
        hgemm_kernel<2,__half><<<dim3(MR/TBM, FF_/TBN),256, HG_SMEM>>>(
            pxn16, pW116 + (size_t)l*D_*FF_, b1 + l*FF_, pff16, nullptr, nullptr, FF_, D_);
        // x = x + gelu(ff@W2 + b2)
        hgemm_kernel<4,float><<<dim3(MR/TBM, D_/TBN),256, HG_SMEM>>>(
            pff16, pW216 + (size_t)l*FF_*D_, b2 + l*D_, px, px, nullptr, D_, FF_);
    }

    ln_kernel<<<MR,256>>>(px, pxn, pxn16, lnfg, lnfb);
    hgemm_kernel<1,float><<<dim3(MR/TBM, V_/TBN),256, HG_SMEM>>>(
        pxn16, pWlm16, blm, out, nullptr, nullptr, V_, D_);
}

// round 7
// speedup vs baseline: 2.3011x; 1.1391x over previous
#include <cuda_runtime.h>
#include <cuda_fp16.h>
#include <stdint.h>
#include <math.h>

#define B_   2
#define S_   1024
#define D_   1024
#define H_   16
#define DH_  64
#define FF_  4096
#define V_   32000
#define L_   4
#define PAD_ 3
#define CTX_ 1025

// ---------------- scratch (fp32) ----------------------------------------------
__device__ float g_x  [B_*S_*D_];
__device__ float g_xn [B_*S_*D_];
__device__ float g_q  [B_*S_*D_];
__device__ float g_k  [B_*S_*D_];
__device__ float g_r  [S_*D_];
__device__ float g_aw [(size_t)B_*H_*S_*S_];   // fp32 scores (pre-softmax)
__device__ float g_uk [B_*H_*S_];
__device__ float g_vr [H_*S_];

// ---------------- fp16 weights + activations -----------------------------------
__device__ __align__(16) __half h_Wq [L_*D_*D_];
__device__ __align__(16) __half h_Wk [L_*D_*D_];
__device__ __align__(16) __half h_Wv [L_*D_*D_];
__device__ __align__(16) __half h_Wr [L_*D_*D_];
__device__ __align__(16) __half h_Wfc[L_*D_*D_];
__device__ __align__(16) __half h_W1 [L_*D_*FF_];
__device__ __align__(16) __half h_W2 [L_*FF_*D_];
__device__ __align__(16) __half h_Wlm[(size_t)D_*V_];
__device__ __align__(16) __half h_xn [B_*S_*D_];
__device__ __align__(16) __half h_rel[S_*D_];
__device__ __align__(16) __half h_o  [B_*S_*D_];
__device__ __align__(16) __half h_ff [B_*S_*FF_];
__device__ __align__(16) __half h_v  [B_*S_*D_];
__device__ __align__(16) __half h_aw [(size_t)B_*H_*S_*S_];   // fp16 attn weights

// ---------------- helpers --------------------------------------------------
__device__ __forceinline__ float gelu_t(float x){
    return 0.5f*x*(1.0f + tanhf(0.7978845608028654f*(x + 0.044715f*x*x*x)));
}
__device__ __forceinline__ uint32_t f2tf(float x){
    uint32_t y; asm("cvt.rna.tf32.f32 %0, %1;" : "=r"(y) : "f"(x)); return y;
}
__device__ __forceinline__ uint32_t smaddr(const void* p){
    return (uint32_t)__cvta_generic_to_shared(p);
}
__device__ __forceinline__ void cp16(void* smem, const void* gmem){
    asm volatile("cp.async.cg.shared.global [%0], [%1], 16;\n"
        :: "r"(smaddr(smem)), "l"(gmem));
}
#define CP_COMMIT() asm volatile("cp.async.commit_group;\n" ::: "memory")
#define CP_WAIT(N)  asm volatile("cp.async.wait_group %0;\n" :: "n"(N) : "memory")

__device__ __forceinline__ void mma_tf32(float c[4], const uint32_t a[4], const uint32_t b[2]){
    asm volatile(
      "mma.sync.aligned.m16n8k8.row.col.f32.tf32.tf32.f32 "
      "{%0,%1,%2,%3}, {%4,%5,%6,%7}, {%8,%9}, {%0,%1,%2,%3};\n"
      : "+f"(c[0]), "+f"(c[1]), "+f"(c[2]), "+f"(c[3])
      : "r"(a[0]), "r"(a[1]), "r"(a[2]), "r"(a[3]), "r"(b[0]), "r"(b[1]));
}
__device__ __forceinline__ void mma_f16(float c[4], const uint32_t a[4], const uint32_t b0, const uint32_t b1){
    asm volatile(
      "mma.sync.aligned.m16n8k16.row.col.f32.f16.f16.f32 "
      "{%0,%1,%2,%3}, {%4,%5,%6,%7}, {%8,%9}, {%0,%1,%2,%3};\n"
      : "+f"(c[0]), "+f"(c[1]), "+f"(c[2]), "+f"(c[3])
      : "r"(a[0]), "r"(a[1]), "r"(a[2]), "r"(a[3]), "r"(b0), "r"(b1));
}
__device__ __forceinline__ void ldsm_x4(uint32_t r[4], uint32_t addr){
    asm volatile("ldmatrix.sync.aligned.m8n8.x4.shared.b16 {%0,%1,%2,%3}, [%4];"
      : "=r"(r[0]), "=r"(r[1]), "=r"(r[2]), "=r"(r[3]) : "r"(addr));
}
__device__ __forceinline__ void ldsm_x4_t(uint32_t r[4], uint32_t addr){
    asm volatile("ldmatrix.sync.aligned.m8n8.x4.trans.shared.b16 {%0,%1,%2,%3}, [%4];"
      : "=r"(r[0]), "=r"(r[1]), "=r"(r[2]), "=r"(r[3]) : "r"(addr));
}

// ---------------- fp32 -> fp16 convert (8 elems/thread) ----------------------
__global__ void cvt_kernel(const float4* __restrict__ src, uint4* __restrict__ dst, int n8){
    int i = blockIdx.x*256 + threadIdx.x;
    if (i < n8){
        float4 a = src[i*2], b = src[i*2+1];
        __half2 h0 = __floats2half2_rn(a.x, a.y);
        __half2 h1 = __floats2half2_rn(a.z, a.w);
        __half2 h2 = __floats2half2_rn(b.x, b.y);
        __half2 h3 = __floats2half2_rn(b.z, b.w);
        dst[i] = make_uint4(*(uint32_t*)&h0, *(uint32_t*)&h1, *(uint32_t*)&h2, *(uint32_t*)&h3);
    }
}

// ---------------- embedding ------------------------------------------------
__global__ void embed_kernel(const int* __restrict__ text, const float* __restrict__ emb){
    int idx = blockIdx.x*256 + threadIdx.x;
    int d4  = idx & (D_/4 - 1);
    int bs  = idx >> 8;
    int s   = bs & (S_-1);
    int b   = bs >> 10;
    int tok = text[b*CTX_ + s];
    ((float4*)g_x)[idx] = ((const float4*)(emb + (size_t)tok*D_))[d4];
}

// ---------------- sinusoidal relative positions (fp16 out) ------------------
__global__ void rel_kernel(){
    int idx = blockIdx.x*256 + threadIdx.x;
    int j = idx & 511;
    int s = idx >> 9;
    float pos  = (float)(S_-1-s);
    float invf = powf(10000.0f, -(float)(2*j)/(float)D_);
    float a = pos*invf;
    h_rel[s*D_ + j]       = __float2half_rn(sinf(a));
    h_rel[s*D_ + j + 512] = __float2half_rn(cosf(a));
}

// ---------------- layernorm (writes fp32 + fp16) ----------------------------
__global__ void ln_kernel(const float* __restrict__ in, float* __restrict__ out,
                          __half* __restrict__ out16,
                          const float* __restrict__ gam, const float* __restrict__ bet){
    int row = blockIdx.x;
    int t = threadIdx.x;
    const float4* x4 = (const float4*)(in + (size_t)row*D_);
    float4 v = x4[t];
    float s  = v.x+v.y+v.z+v.w;
    float s2 = v.x*v.x+v.y*v.y+v.z*v.z+v.w*v.w;
    #pragma unroll
    for (int o=16;o;o>>=1){ s += __shfl_xor_sync(0xffffffffu,s,o); s2 += __shfl_xor_sync(0xffffffffu,s2,o); }
    __shared__ float shs[8], shs2[8], bc[2];
    int w = t>>5, lane = t&31;
    if (!lane){ shs[w]=s; shs2[w]=s2; }
    __syncthreads();
    if (t==0){
        float ts=0.f, ts2=0.f;
        #pragma unroll
        for (int i=0;i<8;i++){ ts+=shs[i]; ts2+=shs2[i]; }
        float m   = ts*(1.0f/(float)D_);
        float var = ts2*(1.0f/(float)D_) - m*m;
        bc[0]=m; bc[1]=rsqrtf(var + 1e-5f);
    }
    __syncthreads();
    float m = bc[0], inv = bc[1];
    float4 gg = ((const float4*)gam)[t];
    float4 bb = ((const float4*)bet)[t];
    float4 o4;
    o4.x = (v.x-m)*inv*gg.x + bb.x;
    o4.y = (v.y-m)*inv*gg.y + bb.y;
    o4.z = (v.z-m)*inv*gg.z + bb.z;
    o4.w = (v.w-m)*inv*gg.w + bb.w;
    ((float4*)(out + (size_t)row*D_))[t] = o4;
    __half2 p0 = __floats2half2_rn(o4.x, o4.y);
    __half2 p1 = __floats2half2_rn(o4.z, o4.w);
    *(uint2*)(out16 + (size_t)row*D_ + t*4) = make_uint2(*(uint32_t*)&p0, *(uint32_t*)&p1);
}

// ================= fp16 GEMM with cp.async 4-stage pipeline =================
#define TBM 128
#define TBN 128
#define TBK 32
#define STAGES 4
#define HG_SMEM ((STAGES*TBM*40 + STAGES*TBK*136)*2)

// EPI: 0 plain | 1 +bias | 2 gelu(acc+bias) | 3 R1+R2+acc+bias | 4 R1+gelu(acc+bias)
template<int EPI, typename TC>
__device__ __forceinline__ void hgemm_body(
    const __half* __restrict__ A, const __half* __restrict__ Bm,
    const float* __restrict__ bias, TC* __restrict__ C,
    const float* __restrict__ R1, const float* __restrict__ R2,
    int N, int K)
{
    extern __shared__ __half hsm[];
    __half* Asm = hsm;                       // [STAGES][TBM][40]
    __half* Bsm = hsm + STAGES*TBM*40;       // [STAGES][TBK][136]

    const int tid = threadIdx.x;
    const int lane = tid & 31, wid = tid >> 5;
    const int wm = wid >> 1, wn = wid & 1;
    const int r = lane >> 2, cg = lane & 3;
    const int bm = blockIdx.x*TBM, bn = blockIdx.y*TBN;

    const int arow = tid >> 1, ac0 = (tid & 1)*16;
    const int brow = tid >> 3, bc0 = (tid & 7)*16;

    const int aRowL = lane & 15, aKH = lane >> 4;
    const int bKL   = (lane & 7) + ((lane >> 3) & 1)*8, bNH = lane >> 4;

    float acc[2][8][4];
    #pragma unroll
    for (int mt=0;mt<2;mt++)
        #pragma unroll
        for (int nt=0;nt<8;nt++)
            #pragma unroll
            for (int i=0;i<4;i++) acc[mt][nt][i]=0.f;

    const int nkt = K/TBK;

    auto issue = [&](int kt, int s){
        __half* as = Asm + (s*TBM + arow)*40 + ac0;
        const __half* ap = A + (size_t)(bm+arow)*K + kt*TBK + ac0;
        cp16(as,   ap);
        cp16(as+8, ap+8);
        __half* bs = Bsm + (s*TBK + brow)*136 + bc0;
        const __half* bp = Bm + (size_t)(kt*TBK + brow)*N + bn + bc0;
        cp16(bs,   bp);
        cp16(bs+8, bp+8);
    };

    #pragma unroll
    for (int s=0; s<STAGES-1; s++){ issue(s, s); CP_COMMIT(); }

    for (int kt=0; kt<nkt; kt++){
        CP_WAIT(STAGES-2);
        __syncthreads();
        const int nk = kt + STAGES-1;
        if (nk < nkt) issue(nk, nk & (STAGES-1));
        CP_COMMIT();

        const int s = kt & (STAGES-1);
        const __half* as = Asm + (size_t)s*TBM*40;
        const __half* bs = Bsm + (size_t)s*TBK*136;
        #pragma unroll
        for (int ks=0; ks<2; ks++){
            uint32_t af[2][4];
            #pragma unroll
            for (int mt=0;mt<2;mt++)
                ldsm_x4(af[mt], smaddr(as + (wm*32 + mt*16 + aRowL)*40 + ks*16 + aKH*8));
            #pragma unroll
            for (int nt=0;nt<4;nt++){
                uint32_t bf[4];
                ldsm_x4_t(bf, smaddr(bs + (ks*16 + bKL)*136 + wn*64 + nt*16 + bNH*8));
                mma_f16(acc[0][nt*2+0], af[0], bf[0], bf[1]);
                mma_f16(acc[1][nt*2+0], af[1], bf[0], bf[1]);
                mma_f16(acc[0][nt*2+1], af[0], bf[2], bf[3]);
                mma_f16(acc[1][nt*2+1], af[1], bf[2], bf[3]);
            }
        }
    }

    // -------- epilogue
    #pragma unroll
    for (int mt=0;mt<2;mt++){
        int row0 = bm + wm*32 + mt*16 + r;
        #pragma unroll
        for (int nt=0;nt<8;nt++){
            int col = bn + wn*64 + nt*8 + cg*2;
            float2 b2 = make_float2(0.f,0.f);
            if (EPI >= 1) b2 = *(const float2*)(bias + col);
            float2 v0, v1;
            v0.x = acc[mt][nt][0] + b2.x; v0.y = acc[mt][nt][1] + b2.y;
            v1.x = acc[mt][nt][2] + b2.x; v1.y = acc[mt][nt][3] + b2.y;
            if (EPI == 2 || EPI == 4){
                v0.x = gelu_t(v0.x); v0.y = gelu_t(v0.y);
                v1.x = gelu_t(v1.x); v1.y = gelu_t(v1.y);
            }
            size_t i0 = (size_t)row0*N + col, i1 = (size_t)(row0+8)*N + col;
            if (EPI == 3){
                float2 a0 = *(const float2*)(R1 + i0), a1 = *(const float2*)(R1 + i1);
                float2 x0 = *(const float2*)(R2 + i0), x1 = *(const float2*)(R2 + i1);
                v0.x += a0.x + x0.x; v0.y += a0.y + x0.y;
                v1.x += a1.x + x1.x; v1.y += a1.y + x1.y;
            }
            if (EPI == 4){
                float2 a0 = *(const float2*)(R1 + i0), a1 = *(const float2*)(R1 + i1);
                v0.x += a0.x; v0.y += a0.y;
                v1.x += a1.x; v1.y += a1.y;
            }
            if constexpr (sizeof(TC) == 2){
                *(__half2*)(C + i0) = __floats2half2_rn(v0.x, v0.y);
                *(__half2*)(C + i1) = __floats2half2_rn(v1.x, v1.y);
            } else {
                *(float2*)(C + i0) = v0;
                *(float2*)(C + i1) = v1;
            }
        }
    }
}

template<int EPI, typename TC>
__global__ void __launch_bounds__(256)
hgemm_kernel(const __half* __restrict__ A, const __half* __restrict__ Bm,
             const float* __restrict__ bias, TC* __restrict__ C,
             const float* __restrict__ R1, const float* __restrict__ R2,
             int N, int K)
{
    hgemm_body<EPI, TC>(A, Bm, bias, C, R1, R2, N, K);
}

__global__ void __launch_bounds__(256)
qkvr_kernel(int l, float* __restrict__ q, float* __restrict__ k)
{
    const int z = blockIdx.z;
    if (z == 3 && blockIdx.x*TBM >= S_) return;
    if (z == 2){
        hgemm_body<0, __half>(h_xn, h_Wv + (size_t)l*D_*D_, nullptr, h_v, nullptr, nullptr, D_, D_);
    } else {
        const __half* A = (z < 3) ? h_xn : h_rel;
        const __half* W = ((z==0) ? h_Wq : (z==1) ? h_Wk : h_Wr) + (size_t)l*D_*D_;
        float*        C = (z==0) ? q : (z==1) ? k : g_r;
        hgemm_body<0, float>(A, W, nullptr, C, nullptr, nullptr, D_, D_);
    }
}

// ---------------- bias precompute: uk[b,h,key]=u·k, vr[h,row]=v·r ----------
__global__ void bias_kernel(const float* __restrict__ uvec, const float* __restrict__ vvec){
    const int t = threadIdx.x;
    if (blockIdx.y == 0){
        int row = blockIdx.x;
        float4 kv = ((const float4*)(g_k + (size_t)row*D_))[t];
        float4 uu = ((const float4*)uvec)[t];
        float p = kv.x*uu.x + kv.y*uu.y + kv.z*uu.z + kv.w*uu.w;
        p += __shfl_xor_sync(0xffffffffu, p, 8);
        p += __shfl_xor_sync(0xffffffffu, p, 4);
        p += __shfl_xor_sync(0xffffffffu, p, 2);
        p += __shfl_xor_sync(0xffffffffu, p, 1);
        if ((t & 15) == 0){
            int h = t >> 4;
            int b = row >> 10, key = row & (S_-1);
            g_uk[((size_t)(b*H_ + h))*S_ + key] = p;
        }
    } else {
        int rrow = blockIdx.x;
        if (rrow >= S_) return;
        float4 rv = ((const float4*)(g_r + (size_t)rrow*D_))[t];
        float4 vv = ((const float4*)vvec)[t];
        float p = rv.x*vv.x + rv.y*vv.y + rv.z*vv.z + rv.w*vv.w;
        p += __shfl_xor_sync(0xffffffffu, p, 8);
        p += __shfl_xor_sync(0xffffffffu, p, 4);
        p += __shfl_xor_sync(0xffffffffu, p, 2);
        p += __shfl_xor_sync(0xffffffffu, p, 1);
        if ((t & 15) == 0)
            g_vr[(t>>4)*S_ + rrow] = p;
    }
}

// ---------------- tensor-core score kernel (tf32) ---------------------------
#define QSS 68
#define KSS 72
#define RSS 136
#define CSS 132
#define SC_SMEM ((64*QSS + 64*KSS + 64*RSS + 64*CSS)*4)

__global__ void __launch_bounds__(256)
score_kernel(){
    if (blockIdx.x > blockIdx.y) return;
    const int kt0 = blockIdx.x*64, qt0 = blockIdx.y*64;
    const int bh = blockIdx.z, b = bh >> 4, h = bh & 15;
    const int rbase = S_ - 64 - qt0 + kt0;

    extern __shared__ uint32_t sm[];
    uint32_t* Qs = sm;
    uint32_t* Ks = Qs + 64*QSS;
    uint32_t* Rs = Ks + 64*KSS;
    float*    C2 = (float*)(Rs + 64*RSS);

    const int tid = threadIdx.x;
    const int lane = tid & 31, wid = tid >> 5;
    const int wm = wid >> 1, wn = wid & 1;
    const int r = lane >> 2, cg = lane & 3;

    {
        const int pos = tid & 63, dg = tid >> 6;
        const float* qrow = g_q + ((size_t)(b*S_ + qt0 + pos))*D_ + h*DH_;
        const float* krow = g_k + ((size_t)(b*S_ + kt0 + pos))*D_ + h*DH_;
        #pragma unroll
        for (int c=0;c<4;c++){
            int d0 = dg*16 + c*4;
            float4 v = *(const float4*)(qrow + d0);
            uint4 t; t.x=f2tf(v.x); t.y=f2tf(v.y); t.z=f2tf(v.z); t.w=f2tf(v.w);
            *(uint4*)&Qs[pos*QSS + d0] = t;
            float4 w = *(const float4*)(krow + d0);
            Ks[(d0+0)*KSS + pos] = f2tf(w.x);
            Ks[(d0+1)*KSS + pos] = f2tf(w.y);
            Ks[(d0+2)*KSS + pos] = f2tf(w.z);
            Ks[(d0+3)*KSS + pos] = f2tf(w.w);
        }
    }
    {
        const int j = tid & 127, dh2 = tid >> 7;
        const int rrow = rbase + j;
        if (rrow >= 0 && rrow < S_ && j < 127){
            const float* rr = g_r + (size_t)rrow*D_ + h*DH_ + dh2*32;
            #pragma unroll
            for (int c=0;c<8;c++){
                float4 v = *(const float4*)(rr + c*4);
                int d0 = dh2*32 + c*4;
                Rs[(d0+0)*RSS + j] = f2tf(v.x);
                Rs[(d0+1)*RSS + j] = f2tf(v.y);
                Rs[(d0+2)*RSS + j] = f2tf(v.z);
                Rs[(d0+3)*RSS + j] = f2tf(v.w);
            }
        } else {
            #pragma unroll
            for (int c=0;c<8;c++){
                int d0 = dh2*32 + c*4;
                Rs[(d0+0)*RSS + j] = 0u;
                Rs[(d0+1)*RSS + j] = 0u;
                Rs[(d0+2)*RSS + j] = 0u;
                Rs[(d0+3)*RSS + j] = 0u;
            }
        }
    }
    __syncthreads();

    float accA[4][4]; float accB[8][4];
    #pragma unroll
    for (int nt=0;nt<4;nt++){ accA[nt][0]=accA[nt][1]=accA[nt][2]=accA[nt][3]=0.f; }
    #pragma unroll
    for (int nt=0;nt<8;nt++){ accB[nt][0]=accB[nt][1]=accB[nt][2]=accB[nt][3]=0.f; }

    #pragma unroll
    for (int ks=0; ks<8; ks++){
        uint32_t a[4];
        const int mr = wm*16 + r;
        a[0] = Qs[mr*QSS     + ks*8 + cg];
        a[1] = Qs[(mr+8)*QSS + ks*8 + cg];
        a[2] = Qs[mr*QSS     + ks*8 + cg + 4];
        a[3] = Qs[(mr+8)*QSS + ks*8 + cg + 4];
        #pragma unroll
        for (int nt=0;nt<4;nt++){
            uint32_t bfr[2];
            bfr[0] = Ks[(ks*8+cg  )*KSS + wn*32 + nt*8 + r];
            bfr[1] = Ks[(ks*8+cg+4)*KSS + wn*32 + nt*8 + r];
            mma_tf32(accA[nt], a, bfr);
        }
        #pragma unroll
        for (int nt=0;nt<8;nt++){
            uint32_t bfr[2];
            bfr[0] = Rs[(ks*8+cg  )*RSS + wn*64 + nt*8 + r];
            bfr[1] = Rs[(ks*8+cg+4)*RSS + wn*64 + nt*8 + r];
            mma_tf32(accB[nt], a, bfr);
        }
    }
    #pragma unroll
    for (int nt=0;nt<8;nt++){
        int col = wn*64 + nt*8 + cg*2;
        C2[(wm*16+r  )*CSS + col    ] = accB[nt][0];
        C2[(wm*16+r  )*CSS + col + 1] = accB[nt][1];
        C2[(wm*16+r+8)*CSS + col    ] = accB[nt][2];
        C2[(wm*16+r+8)*CSS + col + 1] = accB[nt][3];
    }
    __syncthreads();

    const float* ukp = g_uk + (size_t)bh*S_ + kt0;
    const float* vrp = g_vr + (size_t)h*S_;
    #pragma unroll
    for (int i=0;i<2;i++){
        const int qr = wm*16 + r + i*8;
        const int q  = qt0 + qr;
        #pragma unroll
        for (int nt=0;nt<4;nt++){
            const int kr0 = wn*32 + nt*8 + cg*2;
            float2 o2;
            #pragma unroll
            for (int cc=0;cc<2;cc++){
                const int kr = kr0 + cc;
                const int k  = kt0 + kr;
                float sc;
                if (k <= q){
                    float bd = C2[qr*CSS + 63 + kr - qr] + vrp[S_-1-q+k];
                    sc = (accA[nt][i*2+cc] + ukp[kr] + bd) * 0.125f;
                } else sc = -1e30f;
                (cc ? o2.y : o2.x) = sc;
            }
            *(float2*)(g_aw + ((size_t)bh*S_ + q)*S_ + kt0 + kr0) = o2;
        }
    }
}

// ---------------- softmax per row (fp32 scores in, fp16 weights out) --------
__global__ void softmax_kernel(const int* __restrict__ text){
    const int q = blockIdx.x, bh = blockIdx.y, b = bh >> 4;
    const float* row = g_aw + ((size_t)bh*S_ + q)*S_;
    const int t = threadIdx.x;
    float4 v = ((const float4*)row)[t];
    const int k0 = t*4;
    float vals[4] = {v.x, v.y, v.z, v.w};
    float mx = -1e30f;
    #pragma unroll
    for (int c=0;c<4;c++) if (k0+c <= q) mx = fmaxf(mx, vals[c]);
    #pragma unroll
    for (int o=16;o;o>>=1) mx = fmaxf(mx, __shfl_xor_sync(0xffffffffu, mx, o));
    __shared__ float sh[8], bc[2];
    int w = t>>5, lane = t&31;
    if (!lane) sh[w] = mx;
    __syncthreads();
    if (t==0){ float m=sh[0]; for (int i=1;i<8;i++) m=fmaxf(m,sh[i]); bc[0]=m; }
    __syncthreads();
    mx = bc[0];
    float e[4]; float s = 0.f;
    #pragma unroll
    for (int c=0;c<4;c++){ e[c] = (k0+c <= q) ? __expf(vals[c]-mx) : 0.f; s += e[c]; }
    #pragma unroll
    for (int o=16;o;o>>=1) s += __shfl_xor_sync(0xffffffffu, s, o);
    if (!lane) sh[w] = s;
    __syncthreads();
    if (t==0){ float m=0.f; for (int i=0;i<8;i++) m+=sh[i]; bc[1]=m; }
    __syncthreads();
    bool padq = (text[b*CTX_ + q] == PAD_);
    float inv = padq ? 0.f : 1.0f/bc[1];
    __half2 p0 = __floats2half2_rn(e[0]*inv, e[1]*inv);
    __half2 p1 = __floats2half2_rn(e[2]*inv, e[3]*inv);
    *(uint2*)(h_aw + ((size_t)bh*S_ + q)*S_ + k0) = make_uint2(*(uint32_t*)&p0, *(uint32_t*)&p1);
}

// ---------------- fp16 o = aw @ v (cp.async double-buffered) -----------------
#define AVS 72
__global__ void __launch_bounds__(256)
av3_kernel(){
    const int qtile = blockIdx.x;
    const int qt0 = qtile*64;
    const int bh = blockIdx.y, b = bh>>4, h = bh&15;
    __shared__ __align__(16) __half Aav[2][64][AVS];
    __shared__ __align__(16) __half Bav[2][64][AVS];

    const int tid = threadIdx.x;
    const int lane = tid & 31, wid = tid >> 5;
    const int wm = wid >> 1, wn = wid & 1;
    const int r = lane >> 2, cg = lane & 3;

    const int frow = tid >> 2, fc0 = (tid & 3)*16;
    const int aRowL = lane & 15, aKH = lane >> 4;
    const int bKL   = (lane & 7) + ((lane >> 3) & 1)*8, bNH = lane >> 4;

    float acc[4][4];
    #pragma unroll
    for (int nt=0;nt<4;nt++){ acc[nt][0]=acc[nt][1]=acc[nt][2]=acc[nt][3]=0.f; }

    const int nk = qtile + 1;
    auto issue = [&](int kt, int s){
        const __half* ap = h_aw + ((size_t)bh*S_ + qt0 + frow)*S_ + kt*64 + fc0;
        cp16(&Aav[s][frow][fc0],   ap);
        cp16(&Aav[s][frow][fc0+8], ap+8);
        const __half* vp = h_v + ((size_t)(b*S_ + kt*64 + frow))*D_ + h*DH_ + fc0;
        cp16(&Bav[s][frow][fc0],   vp);
        cp16(&Bav[s][frow][fc0+8], vp+8);
    };

    issue(0, 0); CP_COMMIT();
    for (int kt=0; kt<nk; kt++){
        if (kt+1 < nk) issue(kt+1, (kt+1)&1);
        CP_COMMIT();
        CP_WAIT(1);
        __syncthreads();
        const int s = kt & 1;
        #pragma unroll
        for (int ks=0; ks<4; ks++){
            uint32_t af[4];
            ldsm_x4(af, smaddr(&Aav[s][wm*16 + aRowL][ks*16 + aKH*8]));
            #pragma unroll
            for (int nt=0; nt<2; nt++){
                uint32_t bf[4];
                ldsm_x4_t(bf, smaddr(&Bav[s][ks*16 + bKL][wn*32 + nt*16 + bNH*8]));
                mma_f16(acc[nt*2+0], af, bf[0], bf[1]);
                mma_f16(acc[nt*2+1], af, bf[2], bf[3]);
            }
        }
        __syncthreads();
    }

    const int q0 = qt0 + wm*16 + r;
    #pragma unroll
    for (int nt=0;nt<4;nt++){
        int col = h*DH_ + wn*32 + nt*8 + cg*2;
        __half2 o0 = __floats2half2_rn(acc[nt][0], acc[nt][1]);
        __half2 o1 = __floats2half2_rn(acc[nt][2], acc[nt][3]);
        *(__half2*)(h_o + (size_t)(b*S_ + q0    )*D_ + col) = o0;
        *(__half2*)(h_o + (size_t)(b*S_ + q0 + 8)*D_ + col) = o1;
    }
}

// ---------------- orchestration -----------------------------------------------
extern "C" void kernel_launch(void* const* d_in, const int* in_sizes, int n_in,
                              void* d_out, int out_size)
{
    (void)in_sizes; (void)n_in; (void)out_size;
    const int*   text = (const int*)  d_in[0];
    const float* emb  = (const float*)d_in[1];
    const float* u    = (const float*)d_in[2];
    const float* vbp  = (const float*)d_in[3];
    const float* Wq   = (const float*)d_in[4];
    const float* Wk   = (const float*)d_in[5];
    const float* Wv   = (const float*)d_in[6];
    const float* Wr   = (const float*)d_in[7];
    const float* Wfc  = (const float*)d_in[8];
    const float* bfc  = (const float*)d_in[9];
    const float* ln1g = (const float*)d_in[10];
    const float* ln1b = (const float*)d_in[11];
    const float* ln2g = (const float*)d_in[12];
    const float* ln2b = (const float*)d_in[13];
    const float* W1   = (const float*)d_in[14];
    const float* b1   = (const float*)d_in[15];
    const float* W2   = (const float*)d_in[16];
    const float* b2   = (const float*)d_in[17];
    const float* lnfg = (const float*)d_in[18];
    const float* lnfb = (const float*)d_in[19];
    const float* Wlm  = (const float*)d_in[20];
    const float* blm  = (const float*)d_in[21];
    float* out = (float*)d_out;

    float *px,*pxn,*pq,*pk;
    __half *pWq16,*pWk16,*pWv16,*pWr16,*pWfc16,*pW116,*pW216,*pWlm16,*pxn16,*po16,*pff16;
    cudaGetSymbolAddress((void**)&px,   g_x);
    cudaGetSymbolAddress((void**)&pxn,  g_xn);
    cudaGetSymbolAddress((void**)&pq,   g_q);
    cudaGetSymbolAddress((void**)&pk,   g_k);
    cudaGetSymbolAddress((void**)&pWq16, h_Wq);
    cudaGetSymbolAddress((void**)&pWk16, h_Wk);
    cudaGetSymbolAddress((void**)&pWv16, h_Wv);
    cudaGetSymbolAddress((void**)&pWr16, h_Wr);
    cudaGetSymbolAddress((void**)&pWfc16,h_Wfc);
    cudaGetSymbolAddress((void**)&pW116, h_W1);
    cudaGetSymbolAddress((void**)&pW216, h_W2);
    cudaGetSymbolAddress((void**)&pWlm16,h_Wlm);
    cudaGetSymbolAddress((void**)&pxn16, h_xn);
    cudaGetSymbolAddress((void**)&po16,  h_o);
    cudaGetSymbolAddress((void**)&pff16, h_ff);

    static bool attr_done = false;
    if (!attr_done){
        cudaFuncSetAttribute(score_kernel, cudaFuncAttributeMaxDynamicSharedMemorySize, SC_SMEM);
        cudaFuncSetAttribute(qkvr_kernel,  cudaFuncAttributeMaxDynamicSharedMemorySize, HG_SMEM);
        cudaFuncSetAttribute((const void*)hgemm_kernel<1,float>,  cudaFuncAttributeMaxDynamicSharedMemorySize, HG_SMEM);
        cudaFuncSetAttribute((const void*)hgemm_kernel<2,__half>, cudaFuncAttributeMaxDynamicSharedMemorySize, HG_SMEM);
        cudaFuncSetAttribute((const void*)hgemm_kernel<3,float>,  cudaFuncAttributeMaxDynamicSharedMemorySize, HG_SMEM);
        cudaFuncSetAttribute((const void*)hgemm_kernel<4,float>,  cudaFuncAttributeMaxDynamicSharedMemorySize, HG_SMEM);
        attr_done = true;
    }

    const int MR = B_*S_;

    // ---- fp32 -> fp16 weight conversion (every call; deterministic) --------
    {
        int n8;
        n8 = L_*D_*D_/8;
        cvt_kernel<<<(n8+255)/256,256>>>((const float4*)Wq,  (uint4*)pWq16,  n8);
        cvt_kernel<<<(n8+255)/256,256>>>((const float4*)Wk,  (uint4*)pWk16,  n8);
        cvt_kernel<<<(n8+255)/256,256>>>((const float4*)Wv,  (uint4*)pWv16,  n8);
        cvt_kernel<<<(n8+255)/256,256>>>((const float4*)Wr,  (uint4*)pWr16,  n8);
        cvt_kernel<<<(n8+255)/256,256>>>((const float4*)Wfc, (uint4*)pWfc16, n8);
        n8 = L_*D_*FF_/8;
        cvt_kernel<<<(n8+255)/256,256>>>((const float4*)W1,  (uint4*)pW116,  n8);
        cvt_kernel<<<(n8+255)/256,256>>>((const float4*)W2,  (uint4*)pW216,  n8);
        n8 = D_*V_/8;
        cvt_kernel<<<(n8+255)/256,256>>>((const float4*)Wlm, (uint4*)pWlm16, n8);
    }

    embed_kernel<<<2048,256>>>(text, emb);
    rel_kernel  <<<2048,256>>>();

    for (int l=0; l<L_; l++){
        ln_kernel<<<MR,256>>>(px, pxn, pxn16, ln1g + l*D_, ln1b + l*D_);

        qkvr_kernel<<<dim3(MR/TBM, D_/TBN, 4),256, HG_SMEM>>>(l, pq, pk);

        bias_kernel   <<<dim3(B_*S_, 2),256>>>(u, vbp);
        score_kernel  <<<dim3(16,16,B_*H_),256, SC_SMEM>>>();
        softmax_kernel<<<dim3(S_, B_*H_),256>>>(text);
        av3_kernel    <<<dim3(16, B_*H_),256>>>();

        // x = x + xn + o@Wfc + bfc
        hgemm_kernel<3,float><<<dim3(MR/TBM, D_/TBN),256, HG_SMEM>>>(
            po16, pWfc16 + (size_t)l*D_*D_, bfc + l*D_, px, px, pxn, D_, D_);

        ln_kernel<<<MR,256>>>(px, pxn, pxn16, ln2g + l*D_, ln2b + l*D_);
        hgemm_kernel<2,__half><<<dim3(MR/TBM, FF_/TBN),256, HG_SMEM>>>(
            pxn16, pW116 + (size_t)l*D_*FF_, b1 + l*FF_, pff16, nullptr, nullptr, FF_, D_);
        // x = x + gelu(ff@W2 + b2)
        hgemm_kernel<4,float><<<dim3(MR/TBM, D_/TBN),256, HG_SMEM>>>(
            pff16, pW216 + (size_t)l*FF_*D_, b2 + l*D_, px, px, nullptr, D_, FF_);
    }

    ln_kernel<<<MR,256>>>(px, pxn, pxn16, lnfg, lnfb);
    hgemm_kernel<1,float><<<dim3(MR/TBM, V_/TBN),256, HG_SMEM>>>(
        pxn16, pWlm16, blm, out, nullptr, nullptr, V_, D_);
}

// round 8
// speedup vs baseline: 2.6665x; 1.1588x over previous
#include <cuda_runtime.h>
#include <cuda_fp16.h>
#include <stdint.h>
#include <math.h>

#define B_   2
#define S_   1024
#define D_   1024
#define H_   16
#define DH_  64
#define FF_  4096
#define V_   32000
#define L_   4
#define PAD_ 3
#define CTX_ 1025

// ---------------- scratch (fp32) ----------------------------------------------
__device__ float g_x  [B_*S_*D_];
__device__ float g_xn [B_*S_*D_];
__device__ float g_aw [(size_t)B_*H_*S_*S_];   // fp32 scores (pre-softmax)
__device__ float g_uk [B_*H_*S_];
__device__ float g_vr [H_*S_];

// ---------------- fp16 weights + activations -----------------------------------
__device__ __align__(16) __half h_Wq [L_*D_*D_];
__device__ __align__(16) __half h_Wk [L_*D_*D_];
__device__ __align__(16) __half h_Wv [L_*D_*D_];
__device__ __align__(16) __half h_Wr [L_*D_*D_];
__device__ __align__(16) __half h_Wfc[L_*D_*D_];
__device__ __align__(16) __half h_W1 [L_*D_*FF_];
__device__ __align__(16) __half h_W2 [L_*FF_*D_];
__device__ __align__(16) __half h_Wlm[(size_t)D_*V_];
__device__ __align__(16) __half h_xn [B_*S_*D_];
__device__ __align__(16) __half h_rel[S_*D_];
__device__ __align__(16) __half h_o  [B_*S_*D_];
__device__ __align__(16) __half h_ff [B_*S_*FF_];
__device__ __align__(16) __half h_q  [B_*S_*D_];
__device__ __align__(16) __half h_k  [B_*S_*D_];
__device__ __align__(16) __half h_v  [B_*S_*D_];
__device__ __align__(16) __half h_r  [S_*D_];
__device__ __align__(16) __half h_aw [(size_t)B_*H_*S_*S_];   // fp16 attn weights

// ---------------- helpers --------------------------------------------------
__device__ __forceinline__ float gelu_t(float x){
    return 0.5f*x*(1.0f + tanhf(0.7978845608028654f*(x + 0.044715f*x*x*x)));
}
__device__ __forceinline__ uint32_t smaddr(const void* p){
    return (uint32_t)__cvta_generic_to_shared(p);
}
__device__ __forceinline__ void cp16(void* smem, const void* gmem){
    asm volatile("cp.async.cg.shared.global [%0], [%1], 16;\n"
        :: "r"(smaddr(smem)), "l"(gmem));
}
#define CP_COMMIT() asm volatile("cp.async.commit_group;\n" ::: "memory")
#define CP_WAIT(N)  asm volatile("cp.async.wait_group %0;\n" :: "n"(N) : "memory")

__device__ __forceinline__ void mma_f16(float c[4], const uint32_t a[4], const uint32_t b0, const uint32_t b1){
    asm volatile(
      "mma.sync.aligned.m16n8k16.row.col.f32.f16.f16.f32 "
      "{%0,%1,%2,%3}, {%4,%5,%6,%7}, {%8,%9}, {%0,%1,%2,%3};\n"
      : "+f"(c[0]), "+f"(c[1]), "+f"(c[2]), "+f"(c[3])
      : "r"(a[0]), "r"(a[1]), "r"(a[2]), "r"(a[3]), "r"(b0), "r"(b1));
}
__device__ __forceinline__ void ldsm_x4(uint32_t r[4], uint32_t addr){
    asm volatile("ldmatrix.sync.aligned.m8n8.x4.shared.b16 {%0,%1,%2,%3}, [%4];"
      : "=r"(r[0]), "=r"(r[1]), "=r"(r[2]), "=r"(r[3]) : "r"(addr));
}
__device__ __forceinline__ void ldsm_x4_t(uint32_t r[4], uint32_t addr){
    asm volatile("ldmatrix.sync.aligned.m8n8.x4.trans.shared.b16 {%0,%1,%2,%3}, [%4];"
      : "=r"(r[0]), "=r"(r[1]), "=r"(r[2]), "=r"(r[3]) : "r"(addr));
}

// ---------------- fp32 -> fp16 convert (8 elems/thread) ----------------------
__global__ void cvt_kernel(const float4* __restrict__ src, uint4* __restrict__ dst, int n8){
    int i = blockIdx.x*256 + threadIdx.x;
    if (i < n8){
        float4 a = src[i*2], b = src[i*2+1];
        __half2 h0 = __floats2half2_rn(a.x, a.y);
        __half2 h1 = __floats2half2_rn(a.z, a.w);
        __half2 h2 = __floats2half2_rn(b.x, b.y);
        __half2 h3 = __floats2half2_rn(b.z, b.w);
        dst[i] = make_uint4(*(uint32_t*)&h0, *(uint32_t*)&h1, *(uint32_t*)&h2, *(uint32_t*)&h3);
    }
}

// ---------------- embedding ------------------------------------------------
__global__ void embed_kernel(const int* __restrict__ text, const float* __restrict__ emb){
    int idx = blockIdx.x*256 + threadIdx.x;
    int d4  = idx & (D_/4 - 1);
    int bs  = idx >> 8;
    int s   = bs & (S_-1);
    int b   = bs >> 10;
    int tok = text[b*CTX_ + s];
    ((float4*)g_x)[idx] = ((const float4*)(emb + (size_t)tok*D_))[d4];
}

// ---------------- sinusoidal relative positions (fp16 out) ------------------
__global__ void rel_kernel(){
    int idx = blockIdx.x*256 + threadIdx.x;
    int j = idx & 511;
    int s = idx >> 9;
    float pos  = (float)(S_-1-s);
    float invf = powf(10000.0f, -(float)(2*j)/(float)D_);
    float a = pos*invf;
    h_rel[s*D_ + j]       = __float2half_rn(sinf(a));
    h_rel[s*D_ + j + 512] = __float2half_rn(cosf(a));
}

// ---------------- layernorm (writes fp32 + fp16) ----------------------------
__global__ void ln_kernel(const float* __restrict__ in, float* __restrict__ out,
                          __half* __restrict__ out16,
                          const float* __restrict__ gam, const float* __restrict__ bet){
    int row = blockIdx.x;
    int t = threadIdx.x;
    const float4* x4 = (const float4*)(in + (size_t)row*D_);
    float4 v = x4[t];
    float s  = v.x+v.y+v.z+v.w;
    float s2 = v.x*v.x+v.y*v.y+v.z*v.z+v.w*v.w;
    #pragma unroll
    for (int o=16;o;o>>=1){ s += __shfl_xor_sync(0xffffffffu,s,o); s2 += __shfl_xor_sync(0xffffffffu,s2,o); }
    __shared__ float shs[8], shs2[8], bc[2];
    int w = t>>5, lane = t&31;
    if (!lane){ shs[w]=s; shs2[w]=s2; }
    __syncthreads();
    if (t==0){
        float ts=0.f, ts2=0.f;
        #pragma unroll
        for (int i=0;i<8;i++){ ts+=shs[i]; ts2+=shs2[i]; }
        float m   = ts*(1.0f/(float)D_);
        float var = ts2*(1.0f/(float)D_) - m*m;
        bc[0]=m; bc[1]=rsqrtf(var + 1e-5f);
    }
    __syncthreads();
    float m = bc[0], inv = bc[1];
    float4 gg = ((const float4*)gam)[t];
    float4 bb = ((const float4*)bet)[t];
    float4 o4;
    o4.x = (v.x-m)*inv*gg.x + bb.x;
    o4.y = (v.y-m)*inv*gg.y + bb.y;
    o4.z = (v.z-m)*inv*gg.z + bb.z;
    o4.w = (v.w-m)*inv*gg.w + bb.w;
    ((float4*)(out + (size_t)row*D_))[t] = o4;
    __half2 p0 = __floats2half2_rn(o4.x, o4.y);
    __half2 p1 = __floats2half2_rn(o4.z, o4.w);
    *(uint2*)(out16 + (size_t)row*D_ + t*4) = make_uint2(*(uint32_t*)&p0, *(uint32_t*)&p1);
}

// ================= fp16 GEMM with cp.async 4-stage pipeline =================
#define TBM 128
#define TBN 128
#define TBK 32
#define STAGES 4
#define HG_SMEM ((STAGES*TBM*40 + STAGES*TBK*136)*2)

// EPI: 0 plain | 1 +bias | 2 gelu(acc+bias) | 3 R1+R2+acc+bias | 4 R1+gelu(acc+bias)
template<int EPI, typename TC>
__device__ __forceinline__ void hgemm_body(
    const __half* __restrict__ A, const __half* __restrict__ Bm,
    const float* __restrict__ bias, TC* __restrict__ C,
    const float* __restrict__ R1, const float* __restrict__ R2,
    int N, int K)
{
    extern __shared__ __half hsm[];
    __half* Asm = hsm;                       // [STAGES][TBM][40]
    __half* Bsm = hsm + STAGES*TBM*40;       // [STAGES][TBK][136]

    const int tid = threadIdx.x;
    const int lane = tid & 31, wid = tid >> 5;
    const int wm = wid >> 1, wn = wid & 1;
    const int r = lane >> 2, cg = lane & 3;
    const int bm = blockIdx.x*TBM, bn = blockIdx.y*TBN;

    const int arow = tid >> 1, ac0 = (tid & 1)*16;
    const int brow = tid >> 3, bc0 = (tid & 7)*16;

    const int aRowL = lane & 15, aKH = lane >> 4;
    const int bKL   = (lane & 7) + ((lane >> 3) & 1)*8, bNH = lane >> 4;

    float acc[2][8][4];
    #pragma unroll
    for (int mt=0;mt<2;mt++)
        #pragma unroll
        for (int nt=0;nt<8;nt++)
            #pragma unroll
            for (int i=0;i<4;i++) acc[mt][nt][i]=0.f;

    const int nkt = K/TBK;

    auto issue = [&](int kt, int s){
        __half* as = Asm + (s*TBM + arow)*40 + ac0;
        const __half* ap = A + (size_t)(bm+arow)*K + kt*TBK + ac0;
        cp16(as,   ap);
        cp16(as+8, ap+8);
        __half* bs = Bsm + (s*TBK + brow)*136 + bc0;
        const __half* bp = Bm + (size_t)(kt*TBK + brow)*N + bn + bc0;
        cp16(bs,   bp);
        cp16(bs+8, bp+8);
    };

    #pragma unroll
    for (int s=0; s<STAGES-1; s++){ issue(s, s); CP_COMMIT(); }

    for (int kt=0; kt<nkt; kt++){
        CP_WAIT(STAGES-2);
        __syncthreads();
        const int nk = kt + STAGES-1;
        if (nk < nkt) issue(nk, nk & (STAGES-1));
        CP_COMMIT();

        const int s = kt & (STAGES-1);
        const __half* as = Asm + (size_t)s*TBM*40;
        const __half* bs = Bsm + (size_t)s*TBK*136;
        #pragma unroll
        for (int ks=0; ks<2; ks++){
            uint32_t af[2][4];
            #pragma unroll
            for (int mt=0;mt<2;mt++)
                ldsm_x4(af[mt], smaddr(as + (wm*32 + mt*16 + aRowL)*40 + ks*16 + aKH*8));
            #pragma unroll
            for (int nt=0;nt<4;nt++){
                uint32_t bf[4];
                ldsm_x4_t(bf, smaddr(bs + (ks*16 + bKL)*136 + wn*64 + nt*16 + bNH*8));
                mma_f16(acc[0][nt*2+0], af[0], bf[0], bf[1]);
                mma_f16(acc[1][nt*2+0], af[1], bf[0], bf[1]);
                mma_f16(acc[0][nt*2+1], af[0], bf[2], bf[3]);
                mma_f16(acc[1][nt*2+1], af[1], bf[2], bf[3]);
            }
        }
    }

    // -------- epilogue
    #pragma unroll
    for (int mt=0;mt<2;mt++){
        int row0 = bm + wm*32 + mt*16 + r;
        #pragma unroll
        for (int nt=0;nt<8;nt++){
            int col = bn + wn*64 + nt*8 + cg*2;
            float2 b2 = make_float2(0.f,0.f);
            if (EPI >= 1) b2 = *(const float2*)(bias + col);
            float2 v0, v1;
            v0.x = acc[mt][nt][0] + b2.x; v0.y = acc[mt][nt][1] + b2.y;
            v1.x = acc[mt][nt][2] + b2.x; v1.y = acc[mt][nt][3] + b2.y;
            if (EPI == 2 || EPI == 4){
                v0.x = gelu_t(v0.x); v0.y = gelu_t(v0.y);
                v1.x = gelu_t(v1.x); v1.y = gelu_t(v1.y);
            }
            size_t i0 = (size_t)row0*N + col, i1 = (size_t)(row0+8)*N + col;
            if (EPI == 3){
                float2 a0 = *(const float2*)(R1 + i0), a1 = *(const float2*)(R1 + i1);
                float2 x0 = *(const float2*)(R2 + i0), x1 = *(const float2*)(R2 + i1);
                v0.x += a0.x + x0.x; v0.y += a0.y + x0.y;
                v1.x += a1.x + x1.x; v1.y += a1.y + x1.y;
            }
            if (EPI == 4){
                float2 a0 = *(const float2*)(R1 + i0), a1 = *(const float2*)(R1 + i1);
                v0.x += a0.x; v0.y += a0.y;
                v1.x += a1.x; v1.y += a1.y;
            }
            if constexpr (sizeof(TC) == 2){
                *(__half2*)(C + i0) = __floats2half2_rn(v0.x, v0.y);
                *(__half2*)(C + i1) = __floats2half2_rn(v1.x, v1.y);
            } else {
                *(float2*)(C + i0) = v0;
                *(float2*)(C + i1) = v1;
            }
        }
    }
}

template<int EPI, typename TC>
__global__ void __launch_bounds__(256)
hgemm_kernel(const __half* __restrict__ A, const __half* __restrict__ Bm,
             const float* __restrict__ bias, TC* __restrict__ C,
             const float* __restrict__ R1, const float* __restrict__ R2,
             int N, int K)
{
    hgemm_body<EPI, TC>(A, Bm, bias, C, R1, R2, N, K);
}

__global__ void __launch_bounds__(256)
qkvr_kernel(int l)
{
    const int z = blockIdx.z;
    if (z == 3 && blockIdx.x*TBM >= S_) return;
    const __half* A = (z < 3) ? h_xn : h_rel;
    const __half* W = ((z==0) ? h_Wq : (z==1) ? h_Wk : (z==2) ? h_Wv : h_Wr) + (size_t)l*D_*D_;
    __half*       C = (z==0) ? h_q : (z==1) ? h_k : (z==2) ? h_v : h_r;
    hgemm_body<0, __half>(A, W, nullptr, C, nullptr, nullptr, D_, D_);
}

// ---------------- bias precompute: uk[b,h,key]=u·k, vr[h,row]=v·r ----------
__global__ void bias_kernel(const float* __restrict__ uvec, const float* __restrict__ vvec){
    const int t = threadIdx.x;
    float4 uu;
    float2 f0, f1;
    if (blockIdx.y == 0){
        int row = blockIdx.x;
        uint2 raw = *(const uint2*)(h_k + (size_t)row*D_ + t*4);
        f0 = __half22float2(*(__half2*)&raw.x);
        f1 = __half22float2(*(__half2*)&raw.y);
        uu = ((const float4*)uvec)[t];
        float p = f0.x*uu.x + f0.y*uu.y + f1.x*uu.z + f1.y*uu.w;
        p += __shfl_xor_sync(0xffffffffu, p, 8);
        p += __shfl_xor_sync(0xffffffffu, p, 4);
        p += __shfl_xor_sync(0xffffffffu, p, 2);
        p += __shfl_xor_sync(0xffffffffu, p, 1);
        if ((t & 15) == 0){
            int h = t >> 4;
            int b = row >> 10, key = row & (S_-1);
            g_uk[((size_t)(b*H_ + h))*S_ + key] = p;
        }
    } else {
        int rrow = blockIdx.x;
        if (rrow >= S_) return;
        uint2 raw = *(const uint2*)(h_r + (size_t)rrow*D_ + t*4);
        f0 = __half22float2(*(__half2*)&raw.x);
        f1 = __half22float2(*(__half2*)&raw.y);
        uu = ((const float4*)vvec)[t];
        float p = f0.x*uu.x + f0.y*uu.y + f1.x*uu.z + f1.y*uu.w;
        p += __shfl_xor_sync(0xffffffffu, p, 8);
        p += __shfl_xor_sync(0xffffffffu, p, 4);
        p += __shfl_xor_sync(0xffffffffu, p, 2);
        p += __shfl_xor_sync(0xffffffffu, p, 1);
        if ((t & 15) == 0)
            g_vr[(t>>4)*S_ + rrow] = p;
    }
}

// ---------------- fp16 tensor-core score kernel -----------------------------
// scores[b,h,q,k] = 0.125*( Q·K^T + uk[k] + C2[q, 63+k-q] + vr[S-1-q+k] ), k<=q
#define QH  72                       // fp16 tile row stride (halves)
#define CSS 132
#define SC_SMEM ((64*QH + 64*QH + 128*QH)*2 + 64*CSS*4)

__global__ void __launch_bounds__(256)
score_kernel(){
    if (blockIdx.x > blockIdx.y) return;
    const int kt0 = blockIdx.x*64, qt0 = blockIdx.y*64;
    const int bh = blockIdx.z, b = bh >> 4, h = bh & 15;
    const int rbase = S_ - 64 - qt0 + kt0;

    extern __shared__ __half smh[];
    __half* Qs = smh;                 // [64][QH]  rows=q, cols=d
    __half* Ks = Qs + 64*QH;          // [64][QH]  rows=key, cols=d
    __half* Rs = Ks + 64*QH;          // [128][QH] rows=j,  cols=d
    float*  C2 = (float*)(Rs + 128*QH);  // [64][CSS]

    const int tid = threadIdx.x;
    const int lane = tid & 31, wid = tid >> 5;
    const int wm = wid >> 1, wn = wid & 1;
    const int r = lane >> 2, cg = lane & 3;
    const int rowL = lane & 15, kHalf = lane >> 4;

    // ---- fill Qs/Ks: 64 rows x 64 halves, 4 threads/row x 16 halves
    {
        const int pos = tid >> 2, c0 = (tid & 3)*16;
        const __half* qp = h_q + ((size_t)(b*S_ + qt0 + pos))*D_ + h*DH_ + c0;
        *(uint4*)&Qs[pos*QH + c0]     = *(const uint4*)qp;
        *(uint4*)&Qs[pos*QH + c0 + 8] = *(const uint4*)(qp + 8);
        const __half* kp = h_k + ((size_t)(b*S_ + kt0 + pos))*D_ + h*DH_ + c0;
        *(uint4*)&Ks[pos*QH + c0]     = *(const uint4*)kp;
        *(uint4*)&Ks[pos*QH + c0 + 8] = *(const uint4*)(kp + 8);
    }
    // ---- fill Rs: 128 rows x 64 halves, 2 threads/row x 32 halves
    {
        const int j = tid >> 1, rc0 = (tid & 1)*32;
        const int rrow = rbase + j;
        if (rrow >= 0 && rrow < S_ && j < 127){
            const __half* rp = h_r + (size_t)rrow*D_ + h*DH_ + rc0;
            #pragma unroll
            for (int c=0;c<4;c++)
                *(uint4*)&Rs[j*QH + rc0 + c*8] = *(const uint4*)(rp + c*8);
        } else {
            uint4 z = make_uint4(0,0,0,0);
            #pragma unroll
            for (int c=0;c<4;c++)
                *(uint4*)&Rs[j*QH + rc0 + c*8] = z;
        }
    }
    __syncthreads();

    float accA[4][4]; float accB[8][4];
    #pragma unroll
    for (int nt=0;nt<4;nt++){ accA[nt][0]=accA[nt][1]=accA[nt][2]=accA[nt][3]=0.f; }
    #pragma unroll
    for (int nt=0;nt<8;nt++){ accB[nt][0]=accB[nt][1]=accB[nt][2]=accB[nt][3]=0.f; }

    #pragma unroll
    for (int ks=0; ks<4; ks++){
        uint32_t a[4];
        ldsm_x4(a, smaddr(Qs + (wm*16 + rowL)*QH + ks*16 + kHalf*8));
        #pragma unroll
        for (int np=0; np<2; np++){
            uint32_t bk[4];
            ldsm_x4(bk, smaddr(Ks + (wn*32 + np*16 + rowL)*QH + ks*16 + kHalf*8));
            mma_f16(accA[np*2+0], a, bk[0], bk[2]);
            mma_f16(accA[np*2+1], a, bk[1], bk[3]);
        }
        #pragma unroll
        for (int np=0; np<4; np++){
            uint32_t br[4];
            ldsm_x4(br, smaddr(Rs + (wn*64 + np*16 + rowL)*QH + ks*16 + kHalf*8));
            mma_f16(accB[np*2+0], a, br[0], br[2]);
            mma_f16(accB[np*2+1], a, br[1], br[3]);
        }
    }
    // stage C2 to smem
    #pragma unroll
    for (int nt=0;nt<8;nt++){
        int col = wn*64 + nt*8 + cg*2;
        C2[(wm*16+r  )*CSS + col    ] = accB[nt][0];
        C2[(wm*16+r  )*CSS + col + 1] = accB[nt][1];
        C2[(wm*16+r+8)*CSS + col    ] = accB[nt][2];
        C2[(wm*16+r+8)*CSS + col + 1] = accB[nt][3];
    }
    __syncthreads();

    const float* ukp = g_uk + (size_t)bh*S_ + kt0;
    const float* vrp = g_vr + (size_t)h*S_;
    #pragma unroll
    for (int i=0;i<2;i++){
        const int qr = wm*16 + r + i*8;
        const int q  = qt0 + qr;
        #pragma unroll
        for (int nt=0;nt<4;nt++){
            const int kr0 = wn*32 + nt*8 + cg*2;
            float2 o2;
            #pragma unroll
            for (int cc=0;cc<2;cc++){
                const int kr = kr0 + cc;
                const int k  = kt0 + kr;
                float sc;
                if (k <= q){
                    float bd = C2[qr*CSS + 63 + kr - qr] + vrp[S_-1-q+k];
                    sc = (accA[nt][i*2+cc] + ukp[kr] + bd) * 0.125f;
                } else sc = -1e30f;
                (cc ? o2.y : o2.x) = sc;
            }
            *(float2*)(g_aw + ((size_t)bh*S_ + q)*S_ + kt0 + kr0) = o2;
        }
    }
}

// ---------------- softmax (triangular: load k<=q, write to diag-tile end) ---
__global__ void softmax_kernel(const int* __restrict__ text){
    const int q = blockIdx.x, bh = blockIdx.y, b = bh >> 4;
    const float* row = g_aw + ((size_t)bh*S_ + q)*S_;
    const int t = threadIdx.x;
    const int k0 = t*4;
    float vals[4] = {-1e30f, -1e30f, -1e30f, -1e30f};
    if (k0 <= q){
        float4 v = ((const float4*)row)[t];
        vals[0]=v.x; vals[1]=v.y; vals[2]=v.z; vals[3]=v.w;
    }
    float mx = -1e30f;
    #pragma unroll
    for (int c=0;c<4;c++) if (k0+c <= q) mx = fmaxf(mx, vals[c]);
    #pragma unroll
    for (int o=16;o;o>>=1) mx = fmaxf(mx, __shfl_xor_sync(0xffffffffu, mx, o));
    __shared__ float sh[8], bc[2];
    int w = t>>5, lane = t&31;
    if (!lane) sh[w] = mx;
    __syncthreads();
    if (t==0){ float m=sh[0]; for (int i=1;i<8;i++) m=fmaxf(m,sh[i]); bc[0]=m; }
    __syncthreads();
    mx = bc[0];
    float e[4]; float s = 0.f;
    #pragma unroll
    for (int c=0;c<4;c++){ e[c] = (k0+c <= q) ? __expf(vals[c]-mx) : 0.f; s += e[c]; }
    #pragma unroll
    for (int o=16;o;o>>=1) s += __shfl_xor_sync(0xffffffffu, s, o);
    if (!lane) sh[w] = s;
    __syncthreads();
    if (t==0){ float m=0.f; for (int i=0;i<8;i++) m+=sh[i]; bc[1]=m; }
    __syncthreads();
    const int kwend = ((q >> 6) + 1) << 6;       // end of diagonal 64-tile
    if (k0 >= kwend) return;
    bool padq = (text[b*CTX_ + q] == PAD_);
    float inv = padq ? 0.f : 1.0f/bc[1];
    __half2 p0 = __floats2half2_rn(e[0]*inv, e[1]*inv);
    __half2 p1 = __floats2half2_rn(e[2]*inv, e[3]*inv);
    *(uint2*)(h_aw + ((size_t)bh*S_ + q)*S_ + k0) = make_uint2(*(uint32_t*)&p0, *(uint32_t*)&p1);
}

// ---------------- fp16 o = aw @ v (cp.async double-buffered) -----------------
#define AVS 72
__global__ void __launch_bounds__(256)
av3_kernel(){
    const int qtile = blockIdx.x;
    const int qt0 = qtile*64;
    const int bh = blockIdx.y, b = bh>>4, h = bh&15;
    __shared__ __align__(16) __half Aav[2][64][AVS];
    __shared__ __align__(16) __half Bav[2][64][AVS];

    const int tid = threadIdx.x;
    const int lane = tid & 31, wid = tid >> 5;
    const int wm = wid >> 1, wn = wid & 1;
    const int r = lane >> 2, cg = lane & 3;

    const int frow = tid >> 2, fc0 = (tid & 3)*16;
    const int aRowL = lane & 15, aKH = lane >> 4;
    const int bKL   = (lane & 7) + ((lane >> 3) & 1)*8, bNH = lane >> 4;

    float acc[4][4];
    #pragma unroll
    for (int nt=0;nt<4;nt++){ acc[nt][0]=acc[nt][1]=acc[nt][2]=acc[nt][3]=0.f; }

    const int nk = qtile + 1;
    auto issue = [&](int kt, int s){
        const __half* ap = h_aw + ((size_t)bh*S_ + qt0 + frow)*S_ + kt*64 + fc0;
        cp16(&Aav[s][frow][fc0],   ap);
        cp16(&Aav[s][frow][fc0+8], ap+8);
        const __half* vp = h_v + ((size_t)(b*S_ + kt*64 + frow))*D_ + h*DH_ + fc0;
        cp16(&Bav[s][frow][fc0],   vp);
        cp16(&Bav[s][frow][fc0+8], vp+8);
    };

    issue(0, 0); CP_COMMIT();
    for (int kt=0; kt<nk; kt++){
        if (kt+1 < nk) issue(kt+1, (kt+1)&1);
        CP_COMMIT();
        CP_WAIT(1);
        __syncthreads();
        const int s = kt & 1;
        #pragma unroll
        for (int ks=0; ks<4; ks++){
            uint32_t af[4];
            ldsm_x4(af, smaddr(&Aav[s][wm*16 + aRowL][ks*16 + aKH*8]));
            #pragma unroll
            for (int nt=0; nt<2; nt++){
                uint32_t bf[4];
                ldsm_x4_t(bf, smaddr(&Bav[s][ks*16 + bKL][wn*32 + nt*16 + bNH*8]));
                mma_f16(acc[nt*2+0], af, bf[0], bf[1]);
                mma_f16(acc[nt*2+1], af, bf[2], bf[3]);
            }
        }
        __syncthreads();
    }

    const int q0 = qt0 + wm*16 + r;
    #pragma unroll
    for (int nt=0;nt<4;nt++){
        int col = h*DH_ + wn*32 + nt*8 + cg*2;
        __half2 o0 = __floats2half2_rn(acc[nt][0], acc[nt][1]);
        __half2 o1 = __floats2half2_rn(acc[nt][2], acc[nt][3]);
        *(__half2*)(h_o + (size_t)(b*S_ + q0    )*D_ + col) = o0;
        *(__half2*)(h_o + (size_t)(b*S_ + q0 + 8)*D_ + col) = o1;
    }
}

// ---------------- orchestration -----------------------------------------------
extern "C" void kernel_launch(void* const* d_in, const int* in_sizes, int n_in,
                              void* d_out, int out_size)
{
    (void)in_sizes; (void)n_in; (void)out_size;
    const int*   text = (const int*)  d_in[0];
    const float* emb  = (const float*)d_in[1];
    const float* u    = (const float*)d_in[2];
    const float* vbp  = (const float*)d_in[3];
    const float* Wq   = (const float*)d_in[4];
    const float* Wk   = (const float*)d_in[5];
    const float* Wv   = (const float*)d_in[6];
    const float* Wr   = (const float*)d_in[7];
    const float* Wfc  = (const float*)d_in[8];
    const float* bfc  = (const float*)d_in[9];
    const float* ln1g = (const float*)d_in[10];
    const float* ln1b = (const float*)d_in[11];
    const float* ln2g = (const float*)d_in[12];
    const float* ln2b = (const float*)d_in[13];
    const float* W1   = (const float*)d_in[14];
    const float* b1   = (const float*)d_in[15];
    const float* W2   = (const float*)d_in[16];
    const float* b2   = (const float*)d_in[17];
    const float* lnfg = (const float*)d_in[18];
    const float* lnfb = (const float*)d_in[19];
    const float* Wlm  = (const float*)d_in[20];
    const float* blm  = (const float*)d_in[21];
    float* out = (float*)d_out;

    float *px,*pxn;
    __half *pWq16,*pWk16,*pWv16,*pWr16,*pWfc16,*pW116,*pW216,*pWlm16,*pxn16,*po16,*pff16;
    cudaGetSymbolAddress((void**)&px,   g_x);
    cudaGetSymbolAddress((void**)&pxn,  g_xn);
    cudaGetSymbolAddress((void**)&pWq16, h_Wq);
    cudaGetSymbolAddress((void**)&pWk16, h_Wk);
    cudaGetSymbolAddress((void**)&pWv16, h_Wv);
    cudaGetSymbolAddress((void**)&pWr16, h_Wr);
    cudaGetSymbolAddress((void**)&pWfc16,h_Wfc);
    cudaGetSymbolAddress((void**)&pW116, h_W1);
    cudaGetSymbolAddress((void**)&pW216, h_W2);
    cudaGetSymbolAddress((void**)&pWlm16,h_Wlm);
    cudaGetSymbolAddress((void**)&pxn16, h_xn);
    cudaGetSymbolAddress((void**)&po16,  h_o);
    cudaGetSymbolAddress((void**)&pff16, h_ff);

    static bool attr_done = false;
    if (!attr_done){
        cudaFuncSetAttribute(score_kernel, cudaFuncAttributeMaxDynamicSharedMemorySize, SC_SMEM);
        cudaFuncSetAttribute(qkvr_kernel,  cudaFuncAttributeMaxDynamicSharedMemorySize, HG_SMEM);
        cudaFuncSetAttribute((const void*)hgemm_kernel<1,float>,  cudaFuncAttributeMaxDynamicSharedMemorySize, HG_SMEM);
        cudaFuncSetAttribute((const void*)hgemm_kernel<2,__half>, cudaFuncAttributeMaxDynamicSharedMemorySize, HG_SMEM);
        cudaFuncSetAttribute((const void*)hgemm_kernel<3,float>,  cudaFuncAttributeMaxDynamicSharedMemorySize, HG_SMEM);
        cudaFuncSetAttribute((const void*)hgemm_kernel<4,float>,  cudaFuncAttributeMaxDynamicSharedMemorySize, HG_SMEM);
        attr_done = true;
    }

    const int MR = B_*S_;

    // ---- fp32 -> fp16 weight conversion (every call; deterministic) --------
    {
        int n8;
        n8 = L_*D_*D_/8;
        cvt_kernel<<<(n8+255)/256,256>>>((const float4*)Wq,  (uint4*)pWq16,  n8);
        cvt_kernel<<<(n8+255)/256,256>>>((const float4*)Wk,  (uint4*)pWk16,  n8);
        cvt_kernel<<<(n8+255)/256,256>>>((const float4*)Wv,  (uint4*)pWv16,  n8);
        cvt_kernel<<<(n8+255)/256,256>>>((const float4*)Wr,  (uint4*)pWr16,  n8);
        cvt_kernel<<<(n8+255)/256,256>>>((const float4*)Wfc, (uint4*)pWfc16, n8);
        n8 = L_*D_*FF_/8;
        cvt_kernel<<<(n8+255)/256,256>>>((const float4*)W1,  (uint4*)pW116,  n8);
        cvt_kernel<<<(n8+255)/256,256>>>((const float4*)W2,  (uint4*)pW216,  n8);
        n8 = D_*V_/8;
        cvt_kernel<<<(n8+255)/256,256>>>((const float4*)Wlm, (uint4*)pWlm16, n8);
    }

    embed_kernel<<<2048,256>>>(text, emb);
    rel_kernel  <<<2048,256>>>();

    for (int l=0; l<L_; l++){
        ln_kernel<<<MR,256>>>(px, pxn, pxn16, ln1g + l*D_, ln1b + l*D_);

        qkvr_kernel<<<dim3(MR/TBM, D_/TBN, 4),256, HG_SMEM>>>(l);

        bias_kernel   <<<dim3(B_*S_, 2),256>>>(u, vbp);
        score_kernel  <<<dim3(16,16,B_*H_),256, SC_SMEM>>>();
        softmax_kernel<<<dim3(S_, B_*H_),256>>>(text);
        av3_kernel    <<<dim3(16, B_*H_),256>>>();

        // x = x + xn + o@Wfc + bfc
        hgemm_kernel<3,float><<<dim3(MR/TBM, D_/TBN),256, HG_SMEM>>>(
            po16, pWfc16 + (size_t)l*D_*D_, bfc + l*D_, px, px, pxn, D_, D_);

        ln_kernel<<<MR,256>>>(px, pxn, pxn16, ln2g + l*D_, ln2b + l*D_);
        hgemm_kernel<2,__half><<<dim3(MR/TBM, FF_/TBN),256, HG_SMEM>>>(
            pxn16, pW116 + (size_t)l*D_*FF_, b1 + l*FF_, pff16, nullptr, nullptr, FF_, D_);
        // x = x + gelu(ff@W2 + b2)
        hgemm_kernel<4,float><<<dim3(MR/TBM, D_/TBN),256, HG_SMEM>>>(
            pff16, pW216 + (size_t)l*FF_*D_, b2 + l*D_, px, px, nullptr, D_, FF_);
    }

    ln_kernel<<<MR,256>>>(px, pxn, pxn16, lnfg, lnfb);
    hgemm_kernel<1,float><<<dim3(MR/TBM, V_/TBN),256, HG_SMEM>>>(
        pxn16, pWlm16, blm, out, nullptr, nullptr, V_, D_);
}

// round 9
// speedup vs baseline: 2.8861x; 1.0824x over previous
#include <cuda_runtime.h>
#include <cuda_fp16.h>
#include <stdint.h>
#include <math.h>

#define B_   2
#define S_   1024
#define D_   1024
#define H_   16
#define DH_  64
#define FF_  4096
#define V_   32000
#define L_   4
#define PAD_ 3
#define CTX_ 1025

// ---------------- scratch (fp32) ----------------------------------------------
__device__ float g_x  [B_*S_*D_];
__device__ float g_xn [B_*S_*D_];
__device__ float g_uk [B_*H_*S_];
__device__ float g_vr [H_*S_];

// ---------------- fp16 weights + activations -----------------------------------
__device__ __align__(16) __half h_Wq [L_*D_*D_];
__device__ __align__(16) __half h_Wk [L_*D_*D_];
__device__ __align__(16) __half h_Wv [L_*D_*D_];
__device__ __align__(16) __half h_Wr [L_*D_*D_];
__device__ __align__(16) __half h_Wfc[L_*D_*D_];
__device__ __align__(16) __half h_W1 [L_*D_*FF_];
__device__ __align__(16) __half h_W2 [L_*FF_*D_];
__device__ __align__(16) __half h_Wlm[(size_t)D_*V_];
__device__ __align__(16) __half h_xn [B_*S_*D_];
__device__ __align__(16) __half h_rel[S_*D_];
__device__ __align__(16) __half h_o  [B_*S_*D_];
__device__ __align__(16) __half h_ff [B_*S_*FF_];
__device__ __align__(16) __half h_q  [B_*S_*D_];
__device__ __align__(16) __half h_k  [B_*S_*D_];
__device__ __align__(16) __half h_v  [B_*S_*D_];
__device__ __align__(16) __half h_r  [S_*D_];

// ---------------- helpers --------------------------------------------------
__device__ __forceinline__ float gelu_t(float x){
    return 0.5f*x*(1.0f + tanhf(0.7978845608028654f*(x + 0.044715f*x*x*x)));
}
__device__ __forceinline__ uint32_t smaddr(const void* p){
    return (uint32_t)__cvta_generic_to_shared(p);
}
__device__ __forceinline__ void cp16(void* smem, const void* gmem){
    asm volatile("cp.async.cg.shared.global [%0], [%1], 16;\n"
        :: "r"(smaddr(smem)), "l"(gmem));
}
#define CP_COMMIT() asm volatile("cp.async.commit_group;\n" ::: "memory")
#define CP_WAIT(N)  asm volatile("cp.async.wait_group %0;\n" :: "n"(N) : "memory")

__device__ __forceinline__ void mma_f16(float c[4], const uint32_t a[4], const uint32_t b0, const uint32_t b1){
    asm volatile(
      "mma.sync.aligned.m16n8k16.row.col.f32.f16.f16.f32 "
      "{%0,%1,%2,%3}, {%4,%5,%6,%7}, {%8,%9}, {%0,%1,%2,%3};\n"
      : "+f"(c[0]), "+f"(c[1]), "+f"(c[2]), "+f"(c[3])
      : "r"(a[0]), "r"(a[1]), "r"(a[2]), "r"(a[3]), "r"(b0), "r"(b1));
}
__device__ __forceinline__ void ldsm_x4(uint32_t r[4], uint32_t addr){
    asm volatile("ldmatrix.sync.aligned.m8n8.x4.shared.b16 {%0,%1,%2,%3}, [%4];"
      : "=r"(r[0]), "=r"(r[1]), "=r"(r[2]), "=r"(r[3]) : "r"(addr));
}
__device__ __forceinline__ void ldsm_x4_t(uint32_t r[4], uint32_t addr){
    asm volatile("ldmatrix.sync.aligned.m8n8.x4.trans.shared.b16 {%0,%1,%2,%3}, [%4];"
      : "=r"(r[0]), "=r"(r[1]), "=r"(r[2]), "=r"(r[3]) : "r"(addr));
}

// ---------------- fp32 -> fp16 convert (8 elems/thread) ----------------------
__global__ void cvt_kernel(const float4* __restrict__ src, uint4* __restrict__ dst, int n8){
    int i = blockIdx.x*256 + threadIdx.x;
    if (i < n8){
        float4 a = src[i*2], b = src[i*2+1];
        __half2 h0 = __floats2half2_rn(a.x, a.y);
        __half2 h1 = __floats2half2_rn(a.z, a.w);
        __half2 h2 = __floats2half2_rn(b.x, b.y);
        __half2 h3 = __floats2half2_rn(b.z, b.w);
        dst[i] = make_uint4(*(uint32_t*)&h0, *(uint32_t*)&h1, *(uint32_t*)&h2, *(uint32_t*)&h3);
    }
}

// ---------------- embedding ------------------------------------------------
__global__ void embed_kernel(const int* __restrict__ text, const float* __restrict__ emb){
    int idx = blockIdx.x*256 + threadIdx.x;
    int d4  = idx & (D_/4 - 1);
    int bs  = idx >> 8;
    int s   = bs & (S_-1);
    int b   = bs >> 10;
    int tok = text[b*CTX_ + s];
    ((float4*)g_x)[idx] = ((const float4*)(emb + (size_t)tok*D_))[d4];
}

// ---------------- sinusoidal relative positions (fp16 out) ------------------
__global__ void rel_kernel(){
    int idx = blockIdx.x*256 + threadIdx.x;
    int j = idx & 511;
    int s = idx >> 9;
    float pos  = (float)(S_-1-s);
    float invf = powf(10000.0f, -(float)(2*j)/(float)D_);
    float a = pos*invf;
    h_rel[s*D_ + j]       = __float2half_rn(sinf(a));
    h_rel[s*D_ + j + 512] = __float2half_rn(cosf(a));
}

// ---------------- layernorm (writes fp32 + fp16) ----------------------------
__global__ void ln_kernel(const float* __restrict__ in, float* __restrict__ out,
                          __half* __restrict__ out16,
                          const float* __restrict__ gam, const float* __restrict__ bet){
    int row = blockIdx.x;
    int t = threadIdx.x;
    const float4* x4 = (const float4*)(in + (size_t)row*D_);
    float4 v = x4[t];
    float s  = v.x+v.y+v.z+v.w;
    float s2 = v.x*v.x+v.y*v.y+v.z*v.z+v.w*v.w;
    #pragma unroll
    for (int o=16;o;o>>=1){ s += __shfl_xor_sync(0xffffffffu,s,o); s2 += __shfl_xor_sync(0xffffffffu,s2,o); }
    __shared__ float shs[8], shs2[8], bc[2];
    int w = t>>5, lane = t&31;
    if (!lane){ shs[w]=s; shs2[w]=s2; }
    __syncthreads();
    if (t==0){
        float ts=0.f, ts2=0.f;
        #pragma unroll
        for (int i=0;i<8;i++){ ts+=shs[i]; ts2+=shs2[i]; }
        float m   = ts*(1.0f/(float)D_);
        float var = ts2*(1.0f/(float)D_) - m*m;
        bc[0]=m; bc[1]=rsqrtf(var + 1e-5f);
    }
    __syncthreads();
    float m = bc[0], inv = bc[1];
    float4 gg = ((const float4*)gam)[t];
    float4 bb = ((const float4*)bet)[t];
    float4 o4;
    o4.x = (v.x-m)*inv*gg.x + bb.x;
    o4.y = (v.y-m)*inv*gg.y + bb.y;
    o4.z = (v.z-m)*inv*gg.z + bb.z;
    o4.w = (v.w-m)*inv*gg.w + bb.w;
    ((float4*)(out + (size_t)row*D_))[t] = o4;
    __half2 p0 = __floats2half2_rn(o4.x, o4.y);
    __half2 p1 = __floats2half2_rn(o4.z, o4.w);
    *(uint2*)(out16 + (size_t)row*D_ + t*4) = make_uint2(*(uint32_t*)&p0, *(uint32_t*)&p1);
}

// ================= fp16 GEMM with cp.async 4-stage pipeline =================
#define TBM 128
#define TBN 128
#define TBK 32
#define STAGES 4
#define HG_SMEM ((STAGES*TBM*40 + STAGES*TBK*136)*2)

// EPI: 0 plain | 1 +bias | 2 gelu(acc+bias) | 3 R1+R2+acc+bias | 4 R1+gelu(acc+bias)
template<int EPI, typename TC>
__device__ __forceinline__ void hgemm_body(
    const __half* __restrict__ A, const __half* __restrict__ Bm,
    const float* __restrict__ bias, TC* __restrict__ C,
    const float* __restrict__ R1, const float* __restrict__ R2,
    int N, int K)
{
    extern __shared__ __half hsm[];
    __half* Asm = hsm;
    __half* Bsm = hsm + STAGES*TBM*40;

    const int tid = threadIdx.x;
    const int lane = tid & 31, wid = tid >> 5;
    const int wm = wid >> 1, wn = wid & 1;
    const int r = lane >> 2, cg = lane & 3;
    const int bm = blockIdx.x*TBM, bn = blockIdx.y*TBN;

    const int arow = tid >> 1, ac0 = (tid & 1)*16;
    const int brow = tid >> 3, bc0 = (tid & 7)*16;

    const int aRowL = lane & 15, aKH = lane >> 4;
    const int bKL   = (lane & 7) + ((lane >> 3) & 1)*8, bNH = lane >> 4;

    float acc[2][8][4];
    #pragma unroll
    for (int mt=0;mt<2;mt++)
        #pragma unroll
        for (int nt=0;nt<8;nt++)
            #pragma unroll
            for (int i=0;i<4;i++) acc[mt][nt][i]=0.f;

    const int nkt = K/TBK;

    auto issue = [&](int kt, int s){
        __half* as = Asm + (s*TBM + arow)*40 + ac0;
        const __half* ap = A + (size_t)(bm+arow)*K + kt*TBK + ac0;
        cp16(as,   ap);
        cp16(as+8, ap+8);
        __half* bs = Bsm + (s*TBK + brow)*136 + bc0;
        const __half* bp = Bm + (size_t)(kt*TBK + brow)*N + bn + bc0;
        cp16(bs,   bp);
        cp16(bs+8, bp+8);
    };

    #pragma unroll
    for (int s=0; s<STAGES-1; s++){ issue(s, s); CP_COMMIT(); }

    for (int kt=0; kt<nkt; kt++){
        CP_WAIT(STAGES-2);
        __syncthreads();
        const int nk = kt + STAGES-1;
        if (nk < nkt) issue(nk, nk & (STAGES-1));
        CP_COMMIT();

        const int s = kt & (STAGES-1);
        const __half* as = Asm + (size_t)s*TBM*40;
        const __half* bs = Bsm + (size_t)s*TBK*136;
        #pragma unroll
        for (int ks=0; ks<2; ks++){
            uint32_t af[2][4];
            #pragma unroll
            for (int mt=0;mt<2;mt++)
                ldsm_x4(af[mt], smaddr(as + (wm*32 + mt*16 + aRowL)*40 + ks*16 + aKH*8));
            #pragma unroll
            for (int nt=0;nt<4;nt++){
                uint32_t bf[4];
                ldsm_x4_t(bf, smaddr(bs + (ks*16 + bKL)*136 + wn*64 + nt*16 + bNH*8));
                mma_f16(acc[0][nt*2+0], af[0], bf[0], bf[1]);
                mma_f16(acc[1][nt*2+0], af[1], bf[0], bf[1]);
                mma_f16(acc[0][nt*2+1], af[0], bf[2], bf[3]);
                mma_f16(acc[1][nt*2+1], af[1], bf[2], bf[3]);
            }
        }
    }

    #pragma unroll
    for (int mt=0;mt<2;mt++){
        int row0 = bm + wm*32 + mt*16 + r;
        #pragma unroll
        for (int nt=0;nt<8;nt++){
            int col = bn + wn*64 + nt*8 + cg*2;
            float2 b2 = make_float2(0.f,0.f);
            if (EPI >= 1) b2 = *(const float2*)(bias + col);
            float2 v0, v1;
            v0.x = acc[mt][nt][0] + b2.x; v0.y = acc[mt][nt][1] + b2.y;
            v1.x = acc[mt][nt][2] + b2.x; v1.y = acc[mt][nt][3] + b2.y;
            if (EPI == 2 || EPI == 4){
                v0.x = gelu_t(v0.x); v0.y = gelu_t(v0.y);
                v1.x = gelu_t(v1.x); v1.y = gelu_t(v1.y);
            }
            size_t i0 = (size_t)row0*N + col, i1 = (size_t)(row0+8)*N + col;
            if (EPI == 3){
                float2 a0 = *(const float2*)(R1 + i0), a1 = *(const float2*)(R1 + i1);
                float2 x0 = *(const float2*)(R2 + i0), x1 = *(const float2*)(R2 + i1);
                v0.x += a0.x + x0.x; v0.y += a0.y + x0.y;
                v1.x += a1.x + x1.x; v1.y += a1.y + x1.y;
            }
            if (EPI == 4){
                float2 a0 = *(const float2*)(R1 + i0), a1 = *(const float2*)(R1 + i1);
                v0.x += a0.x; v0.y += a0.y;
                v1.x += a1.x; v1.y += a1.y;
            }
            if constexpr (sizeof(TC) == 2){
                *(__half2*)(C + i0) = __floats2half2_rn(v0.x, v0.y);
                *(__half2*)(C + i1) = __floats2half2_rn(v1.x, v1.y);
            } else {
                *(float2*)(C + i0) = v0;
                *(float2*)(C + i1) = v1;
            }
        }
    }
}

template<int EPI, typename TC>
__global__ void __launch_bounds__(256)
hgemm_kernel(const __half* __restrict__ A, const __half* __restrict__ Bm,
             const float* __restrict__ bias, TC* __restrict__ C,
             const float* __restrict__ R1, const float* __restrict__ R2,
             int N, int K)
{
    hgemm_body<EPI, TC>(A, Bm, bias, C, R1, R2, N, K);
}

__global__ void __launch_bounds__(256)
qkvr_kernel(int l)
{
    const int z = blockIdx.z;
    if (z == 3 && blockIdx.x*TBM >= S_) return;
    const __half* A = (z < 3) ? h_xn : h_rel;
    const __half* W = ((z==0) ? h_Wq : (z==1) ? h_Wk : (z==2) ? h_Wv : h_Wr) + (size_t)l*D_*D_;
    __half*       C = (z==0) ? h_q : (z==1) ? h_k : (z==2) ? h_v : h_r;
    hgemm_body<0, __half>(A, W, nullptr, C, nullptr, nullptr, D_, D_);
}

// ---------------- bias precompute: uk[b,h,key]=u·k, vr[h,row]=v·r ----------
__global__ void bias_kernel(const float* __restrict__ uvec, const float* __restrict__ vvec){
    const int t = threadIdx.x;
    float4 uu;
    float2 f0, f1;
    if (blockIdx.y == 0){
        int row = blockIdx.x;
        uint2 raw = *(const uint2*)(h_k + (size_t)row*D_ + t*4);
        f0 = __half22float2(*(__half2*)&raw.x);
        f1 = __half22float2(*(__half2*)&raw.y);
        uu = ((const float4*)uvec)[t];
        float p = f0.x*uu.x + f0.y*uu.y + f1.x*uu.z + f1.y*uu.w;
        p += __shfl_xor_sync(0xffffffffu, p, 8);
        p += __shfl_xor_sync(0xffffffffu, p, 4);
        p += __shfl_xor_sync(0xffffffffu, p, 2);
        p += __shfl_xor_sync(0xffffffffu, p, 1);
        if ((t & 15) == 0){
            int h = t >> 4;
            int b = row >> 10, key = row & (S_-1);
            g_uk[((size_t)(b*H_ + h))*S_ + key] = p;
        }
    } else {
        int rrow = blockIdx.x;
        if (rrow >= S_) return;
        uint2 raw = *(const uint2*)(h_r + (size_t)rrow*D_ + t*4);
        f0 = __half22float2(*(__half2*)&raw.x);
        f1 = __half22float2(*(__half2*)&raw.y);
        uu = ((const float4*)vvec)[t];
        float p = f0.x*uu.x + f0.y*uu.y + f1.x*uu.z + f1.y*uu.w;
        p += __shfl_xor_sync(0xffffffffu, p, 8);
        p += __shfl_xor_sync(0xffffffffu, p, 4);
        p += __shfl_xor_sync(0xffffffffu, p, 2);
        p += __shfl_xor_sync(0xffffffffu, p, 1);
        if ((t & 15) == 0)
            g_vr[(t>>4)*S_ + rrow] = p;
    }
}

// ================= fused flash attention ====================================
// One CTA per (q-tile 64, bh). Online softmax; O accumulated in registers.
#define FQH 72
#define FC2 132
#define FL_SMEM ((384*FQH)*2 + (64*FC2 + 128 + 128 + 64 + 64)*4)

__global__ void __launch_bounds__(256)
flash_kernel(const int* __restrict__ text){
    const int qtile = 15 - blockIdx.x;          // big tiles first
    const int qt0 = qtile*64;
    const int bh = blockIdx.y, b = bh>>4, h = bh&15;

    extern __shared__ __half fsm[];
    __half* Qs = fsm;                     // [64][FQH]
    __half* Ks = Qs + 64*FQH;             // [64][FQH]
    __half* Vs = Ks + 64*FQH;             // [64][FQH]
    __half* Rs = Vs + 64*FQH;             // [128][FQH]
    __half* Ps = Rs + 128*FQH;            // [64][FQH]
    float*  C2  = (float*)(Ps + 64*FQH);  // [64][FC2]
    float*  wmx = C2 + 64*FC2;            // [2][64]
    float*  wsm = wmx + 128;              // [2][64]
    float*  mrow = wsm + 128;             // [64]
    float*  lrow = mrow + 64;             // [64]

    const int tid = threadIdx.x;
    const int lane = tid&31, wid = tid>>5;
    const int wm = wid>>1, wn = wid&1;
    const int r = lane>>2, cg = lane&3;
    const int rowL = lane&15, kHalf = lane>>4;
    const int bKL = (lane&7) + ((lane>>3)&1)*8, bNH = lane>>4;

    // load Q tile + init stats
    {
        const int pos = tid>>2, c0 = (tid&3)*16;
        const __half* qp = h_q + ((size_t)(b*S_+qt0+pos))*D_ + h*DH_ + c0;
        *(uint4*)&Qs[pos*FQH+c0]   = *(const uint4*)qp;
        *(uint4*)&Qs[pos*FQH+c0+8] = *(const uint4*)(qp+8);
    }
    if (tid < 64){ mrow[tid] = -1e30f; lrow[tid] = 0.f; }

    float accO[4][4];
    #pragma unroll
    for (int nt=0;nt<4;nt++){ accO[nt][0]=accO[nt][1]=accO[nt][2]=accO[nt][3]=0.f; }

    const float* ukb = g_uk + (size_t)bh*S_;
    const float* vrp = g_vr + (size_t)h*S_;

    for (int kt=0; kt<=qtile; kt++){
        __syncthreads();
        // ---- load K/V tiles
        {
            const int pos = tid>>2, c0 = (tid&3)*16;
            const __half* kp = h_k + ((size_t)(b*S_+kt*64+pos))*D_ + h*DH_ + c0;
            *(uint4*)&Ks[pos*FQH+c0]   = *(const uint4*)kp;
            *(uint4*)&Ks[pos*FQH+c0+8] = *(const uint4*)(kp+8);
            const __half* vp = h_v + ((size_t)(b*S_+kt*64+pos))*D_ + h*DH_ + c0;
            *(uint4*)&Vs[pos*FQH+c0]   = *(const uint4*)vp;
            *(uint4*)&Vs[pos*FQH+c0+8] = *(const uint4*)(vp+8);
        }
        // ---- load R band
        {
            const int rbase = S_ - 64 - qt0 + kt*64;
            const int j = tid>>1, rc0 = (tid&1)*32;
            const int rrow = rbase + j;
            if (rrow >= 0 && rrow < S_ && j < 127){
                const __half* rp = h_r + (size_t)rrow*D_ + h*DH_ + rc0;
                #pragma unroll
                for (int c=0;c<4;c++)
                    *(uint4*)&Rs[j*FQH + rc0 + c*8] = *(const uint4*)(rp + c*8);
            } else {
                uint4 z = make_uint4(0,0,0,0);
                #pragma unroll
                for (int c=0;c<4;c++)
                    *(uint4*)&Rs[j*FQH + rc0 + c*8] = z;
            }
        }
        __syncthreads();

        // ---- score mma
        float accA[4][4], accB[8][4];
        #pragma unroll
        for (int nt=0;nt<4;nt++){ accA[nt][0]=accA[nt][1]=accA[nt][2]=accA[nt][3]=0.f; }
        #pragma unroll
        for (int nt=0;nt<8;nt++){ accB[nt][0]=accB[nt][1]=accB[nt][2]=accB[nt][3]=0.f; }
        #pragma unroll
        for (int ks=0; ks<4; ks++){
            uint32_t a[4];
            ldsm_x4(a, smaddr(Qs + (wm*16 + rowL)*FQH + ks*16 + kHalf*8));
            #pragma unroll
            for (int np=0; np<2; np++){
                uint32_t bk[4];
                ldsm_x4(bk, smaddr(Ks + (wn*32 + np*16 + rowL)*FQH + ks*16 + kHalf*8));
                mma_f16(accA[np*2+0], a, bk[0], bk[2]);
                mma_f16(accA[np*2+1], a, bk[1], bk[3]);
            }
            #pragma unroll
            for (int np=0; np<4; np++){
                uint32_t br[4];
                ldsm_x4(br, smaddr(Rs + (wn*64 + np*16 + rowL)*FQH + ks*16 + kHalf*8));
                mma_f16(accB[np*2+0], a, br[0], br[2]);
                mma_f16(accB[np*2+1], a, br[1], br[3]);
            }
        }
        // stage C2 (BD shear source)
        #pragma unroll
        for (int nt=0;nt<8;nt++){
            int col = wn*64 + nt*8 + cg*2;
            C2[(wm*16+r  )*FC2 + col    ] = accB[nt][0];
            C2[(wm*16+r  )*FC2 + col + 1] = accB[nt][1];
            C2[(wm*16+r+8)*FC2 + col    ] = accB[nt][2];
            C2[(wm*16+r+8)*FC2 + col + 1] = accB[nt][3];
        }
        __syncthreads();

        // ---- combine scores, per-warp row max
        const float* ukp = ukb + kt*64;
        float sv[2][4][2];
        float tmax[2] = {-1e30f, -1e30f};
        #pragma unroll
        for (int i=0;i<2;i++){
            const int qr = wm*16 + r + i*8;
            const int q  = qt0 + qr;
            #pragma unroll
            for (int nt=0;nt<4;nt++){
                #pragma unroll
                for (int cc=0;cc<2;cc++){
                    const int kr = wn*32 + nt*8 + cg*2 + cc;
                    const int k  = kt*64 + kr;
                    float v;
                    if (k <= q){
                        v = (accA[nt][i*2+cc] + ukp[kr]
                             + C2[qr*FC2 + 63 + kr - qr] + vrp[S_-1-q+k]) * 0.125f;
                    } else v = -1e30f;
                    sv[i][nt][cc] = v;
                    tmax[i] = fmaxf(tmax[i], v);
                }
            }
        }
        #pragma unroll
        for (int i=0;i<2;i++){
            tmax[i] = fmaxf(tmax[i], __shfl_xor_sync(0xffffffffu, tmax[i], 1));
            tmax[i] = fmaxf(tmax[i], __shfl_xor_sync(0xffffffffu, tmax[i], 2));
        }
        if (cg == 0){
            wmx[wn*64 + wm*16 + r    ] = tmax[0];
            wmx[wn*64 + wm*16 + r + 8] = tmax[1];
        }
        __syncthreads();

        // ---- p = exp(s - m_new), rescale O, stage P, per-warp row sums
        #pragma unroll
        for (int i=0;i<2;i++){
            const int row = wm*16 + r + i*8;
            float m_old = mrow[row];
            float m_new = fmaxf(m_old, fmaxf(wmx[row], wmx[64+row]));
            float scl = __expf(m_old - m_new);
            float psum = 0.f;
            #pragma unroll
            for (int nt=0;nt<4;nt++){
                float p0 = __expf(sv[i][nt][0] - m_new);
                float p1 = __expf(sv[i][nt][1] - m_new);
                psum += p0 + p1;
                *(__half2*)&Ps[row*FQH + wn*32 + nt*8 + cg*2] = __floats2half2_rn(p0, p1);
                accO[nt][i*2+0] *= scl;
                accO[nt][i*2+1] *= scl;
            }
            psum += __shfl_xor_sync(0xffffffffu, psum, 1);
            psum += __shfl_xor_sync(0xffffffffu, psum, 2);
            if (cg == 0) wsm[wn*64 + row] = psum;
        }
        __syncthreads();

        // ---- stats update (single writer per row)
        if (tid < 64){
            float m_old = mrow[tid];
            float m_new = fmaxf(m_old, fmaxf(wmx[tid], wmx[64+tid]));
            lrow[tid] = lrow[tid]*__expf(m_old - m_new) + wsm[tid] + wsm[64+tid];
            mrow[tid] = m_new;
        }
        // ---- AV mma: O += P @ V
        #pragma unroll
        for (int ks=0; ks<4; ks++){
            uint32_t af[4];
            ldsm_x4(af, smaddr(Ps + (wm*16 + rowL)*FQH + ks*16 + kHalf*8));
            #pragma unroll
            for (int nt=0; nt<2; nt++){
                uint32_t bf[4];
                ldsm_x4_t(bf, smaddr(Vs + (ks*16 + bKL)*FQH + wn*32 + nt*16 + bNH*8));
                mma_f16(accO[nt*2+0], af, bf[0], bf[1]);
                mma_f16(accO[nt*2+1], af, bf[2], bf[3]);
            }
        }
    }
    __syncthreads();

    // ---- output: O / l (0 for pad queries)
    #pragma unroll
    for (int i=0;i<2;i++){
        const int row = wm*16 + r + i*8;
        const int q   = qt0 + row;
        bool padq = (text[b*CTX_ + q] == PAD_);
        float inv = padq ? 0.f : 1.0f/lrow[row];
        #pragma unroll
        for (int nt=0;nt<4;nt++){
            int col = h*DH_ + wn*32 + nt*8 + cg*2;
            __half2 o2 = __floats2half2_rn(accO[nt][i*2+0]*inv, accO[nt][i*2+1]*inv);
            *(__half2*)(h_o + (size_t)(b*S_ + q)*D_ + col) = o2;
        }
    }
}

// ---------------- orchestration -----------------------------------------------
extern "C" void kernel_launch(void* const* d_in, const int* in_sizes, int n_in,
                              void* d_out, int out_size)
{
    (void)in_sizes; (void)n_in; (void)out_size;
    const int*   text = (const int*)  d_in[0];
    const float* emb  = (const float*)d_in[1];
    const float* u    = (const float*)d_in[2];
    const float* vbp  = (const float*)d_in[3];
    const float* Wq   = (const float*)d_in[4];
    const float* Wk   = (const float*)d_in[5];
    const float* Wv   = (const float*)d_in[6];
    const float* Wr   = (const float*)d_in[7];
    const float* Wfc  = (const float*)d_in[8];
    const float* bfc  = (const float*)d_in[9];
    const float* ln1g = (const float*)d_in[10];
    const float* ln1b = (const float*)d_in[11];
    const float* ln2g = (const float*)d_in[12];
    const float* ln2b = (const float*)d_in[13];
    const float* W1   = (const float*)d_in[14];
    const float* b1   = (const float*)d_in[15];
    const float* W2   = (const float*)d_in[16];
    const float* b2   = (const float*)d_in[17];
    const float* lnfg = (const float*)d_in[18];
    const float* lnfb = (const float*)d_in[19];
    const float* Wlm  = (const float*)d_in[20];
    const float* blm  = (const float*)d_in[21];
    float* out = (float*)d_out;

    float *px,*pxn;
    __half *pWq16,*pWk16,*pWv16,*pWr16,*pWfc16,*pW116,*pW216,*pWlm16,*pxn16,*po16,*pff16;
    cudaGetSymbolAddress((void**)&px,   g_x);
    cudaGetSymbolAddress((void**)&pxn,  g_xn);
    cudaGetSymbolAddress((void**)&pWq16, h_Wq);
    cudaGetSymbolAddress((void**)&pWk16, h_Wk);
    cudaGetSymbolAddress((void**)&pWv16, h_Wv);
    cudaGetSymbolAddress((void**)&pWr16, h_Wr);
    cudaGetSymbolAddress((void**)&pWfc16,h_Wfc);
    cudaGetSymbolAddress((void**)&pW116, h_W1);
    cudaGetSymbolAddress((void**)&pW216, h_W2);
    cudaGetSymbolAddress((void**)&pWlm16,h_Wlm);
    cudaGetSymbolAddress((void**)&pxn16, h_xn);
    cudaGetSymbolAddress((void**)&po16,  h_o);
    cudaGetSymbolAddress((void**)&pff16, h_ff);

    static bool attr_done = false;
    if (!attr_done){
        cudaFuncSetAttribute(flash_kernel, cudaFuncAttributeMaxDynamicSharedMemorySize, FL_SMEM);
        cudaFuncSetAttribute(qkvr_kernel,  cudaFuncAttributeMaxDynamicSharedMemorySize, HG_SMEM);
        cudaFuncSetAttribute((const void*)hgemm_kernel<1,float>,  cudaFuncAttributeMaxDynamicSharedMemorySize, HG_SMEM);
        cudaFuncSetAttribute((const void*)hgemm_kernel<2,__half>, cudaFuncAttributeMaxDynamicSharedMemorySize, HG_SMEM);
        cudaFuncSetAttribute((const void*)hgemm_kernel<3,float>,  cudaFuncAttributeMaxDynamicSharedMemorySize, HG_SMEM);
        cudaFuncSetAttribute((const void*)hgemm_kernel<4,float>,  cudaFuncAttributeMaxDynamicSharedMemorySize, HG_SMEM);
        attr_done = true;
    }

    const int MR = B_*S_;

    // ---- fp32 -> fp16 weight conversion (every call; deterministic) --------
    {
        int n8;
        n8 = L_*D_*D_/8;
        cvt_kernel<<<(n8+255)/256,256>>>((const float4*)Wq,  (uint4*)pWq16,  n8);
        cvt_kernel<<<(n8+255)/256,256>>>((const float4*)Wk,  (uint4*)pWk16,  n8);
        cvt_kernel<<<(n8+255)/256,256>>>((const float4*)Wv,  (uint4*)pWv16,  n8);
        cvt_kernel<<<(n8+255)/256,256>>>((const float4*)Wr,  (uint4*)pWr16,  n8);
        cvt_kernel<<<(n8+255)/256,256>>>((const float4*)Wfc, (uint4*)pWfc16, n8);
        n8 = L_*D_*FF_/8;
        cvt_kernel<<<(n8+255)/256,256>>>((const float4*)W1,  (uint4*)pW116,  n8);
        cvt_kernel<<<(n8+255)/256,256>>>((const float4*)W2,  (uint4*)pW216,  n8);
        n8 = D_*V_/8;
        cvt_kernel<<<(n8+255)/256,256>>>((const float4*)Wlm, (uint4*)pWlm16, n8);
    }

    embed_kernel<<<2048,256>>>(text, emb);
    rel_kernel  <<<2048,256>>>();

    for (int l=0; l<L_; l++){
        ln_kernel<<<MR,256>>>(px, pxn, pxn16, ln1g + l*D_, ln1b + l*D_);

        qkvr_kernel<<<dim3(MR/TBM, D_/TBN, 4),256, HG_SMEM>>>(l);

        bias_kernel <<<dim3(B_*S_, 2),256>>>(u, vbp);
        flash_kernel<<<dim3(16, B_*H_),256, FL_SMEM>>>(text);

        // x = x + xn + o@Wfc + bfc
        hgemm_kernel<3,float><<<dim3(MR/TBM, D_/TBN),256, HG_SMEM>>>(
            po16, pWfc16 + (size_t)l*D_*D_, bfc + l*D_, px, px, pxn, D_, D_);

        ln_kernel<<<MR,256>>>(px, pxn, pxn16, ln2g + l*D_, ln2b + l*D_);
        hgemm_kernel<2,__half><<<dim3(MR/TBM, FF_/TBN),256, HG_SMEM>>>(
            pxn16, pW116 + (size_t)l*D_*FF_, b1 + l*FF_, pff16, nullptr, nullptr, FF_, D_);
        // x = x + gelu(ff@W2 + b2)
        hgemm_kernel<4,float><<<dim3(MR/TBM, D_/TBN),256, HG_SMEM>>>(
            pff16, pW216 + (size_t)l*FF_*D_, b2 + l*D_, px, px, nullptr, D_, FF_);
    }

    ln_kernel<<<MR,256>>>(px, pxn, pxn16, lnfg, lnfb);
    hgemm_kernel<1,float><<<dim3(MR/TBM, V_/TBN),256, HG_SMEM>>>(
        pxn16, pWlm16, blm, out, nullptr, nullptr, V_, D_);
}

// round 11
// speedup vs baseline: 3.0195x; 1.0462x over previous
#include <cuda_runtime.h>
#include <cuda_fp16.h>
#include <stdint.h>
#include <math.h>

#define B_   2
#define S_   1024
#define D_   1024
#define H_   16
#define DH_  64
#define FF_  4096
#define V_   32000
#define L_   4
#define PAD_ 3
#define CTX_ 1025

// ---------------- scratch (fp32) ----------------------------------------------
__device__ float g_x  [B_*S_*D_];
__device__ float g_xn [B_*S_*D_];
__device__ float g_uk [B_*H_*S_];
__device__ float g_vr [H_*S_];

// ---------------- fp16 weights + activations -----------------------------------
__device__ __align__(16) __half h_Wq [L_*D_*D_];
__device__ __align__(16) __half h_Wk [L_*D_*D_];
__device__ __align__(16) __half h_Wv [L_*D_*D_];
__device__ __align__(16) __half h_Wr [L_*D_*D_];
__device__ __align__(16) __half h_Wfc[L_*D_*D_];
__device__ __align__(16) __half h_W1 [L_*D_*FF_];
__device__ __align__(16) __half h_W2 [L_*FF_*D_];
__device__ __align__(16) __half h_Wlm[(size_t)D_*V_];
__device__ __align__(16) __half h_xn [B_*S_*D_];
__device__ __align__(16) __half h_rel[S_*D_];
__device__ __align__(16) __half h_o  [B_*S_*D_];
__device__ __align__(16) __half h_ff [B_*S_*FF_];
__device__ __align__(16) __half h_q  [B_*S_*D_];
__device__ __align__(16) __half h_k  [B_*S_*D_];
__device__ __align__(16) __half h_v  [B_*S_*D_];
__device__ __align__(16) __half h_r  [S_*D_];

// ---------------- helpers --------------------------------------------------
__device__ __forceinline__ float gelu_t(float x){
    return 0.5f*x*(1.0f + tanhf(0.7978845608028654f*(x + 0.044715f*x*x*x)));
}
__device__ __forceinline__ uint32_t smaddr(const void* p){
    return (uint32_t)__cvta_generic_to_shared(p);
}
__device__ __forceinline__ void cp16(void* smem, const void* gmem){
    asm volatile("cp.async.cg.shared.global [%0], [%1], 16;\n"
        :: "r"(smaddr(smem)), "l"(gmem));
}
#define CP_COMMIT() asm volatile("cp.async.commit_group;\n" ::: "memory")
#define CP_WAIT(N)  asm volatile("cp.async.wait_group %0;\n" :: "n"(N) : "memory")

__device__ __forceinline__ void mma_f16(float c[4], const uint32_t a[4], const uint32_t b0, const uint32_t b1){
    asm volatile(
      "mma.sync.aligned.m16n8k16.row.col.f32.f16.f16.f32 "
      "{%0,%1,%2,%3}, {%4,%5,%6,%7}, {%8,%9}, {%0,%1,%2,%3};\n"
      : "+f"(c[0]), "+f"(c[1]), "+f"(c[2]), "+f"(c[3])
      : "r"(a[0]), "r"(a[1]), "r"(a[2]), "r"(a[3]), "r"(b0), "r"(b1));
}
__device__ __forceinline__ void ldsm_x4(uint32_t r[4], uint32_t addr){
    asm volatile("ldmatrix.sync.aligned.m8n8.x4.shared.b16 {%0,%1,%2,%3}, [%4];"
      : "=r"(r[0]), "=r"(r[1]), "=r"(r[2]), "=r"(r[3]) : "r"(addr));
}
__device__ __forceinline__ void ldsm_x4_t(uint32_t r[4], uint32_t addr){
    asm volatile("ldmatrix.sync.aligned.m8n8.x4.trans.shared.b16 {%0,%1,%2,%3}, [%4];"
      : "=r"(r[0]), "=r"(r[1]), "=r"(r[2]), "=r"(r[3]) : "r"(addr));
}

// ---------------- merged fp32 -> fp16 weight convert -------------------------
// One launch for all 8 weight tensors; segments are compile-time constants.
#define N8_DD (L_*D_*D_/8)       // 524288
#define N8_DF (L_*D_*FF_/8)      // 2097152
#define N8_LM (D_*V_/8)          // 4096000
#define N8_TOTAL (5*N8_DD + 2*N8_DF + N8_LM)   // 10,911,744 = 42624*256

__global__ void cvt_all_kernel(
    const float4* __restrict__ Wq,  const float4* __restrict__ Wk,
    const float4* __restrict__ Wv,  const float4* __restrict__ Wr,
    const float4* __restrict__ Wfc, const float4* __restrict__ W1,
    const float4* __restrict__ W2,  const float4* __restrict__ Wlm)
{
    int i = blockIdx.x*256 + threadIdx.x;
    const float4* src; uint4* dst; size_t j;
    if (i < 5*N8_DD){
        int t = i / N8_DD; j = i - t*N8_DD;
        src = (t==0)?Wq:(t==1)?Wk:(t==2)?Wv:(t==3)?Wr:Wfc;
        dst = (t==0)?(uint4*)h_Wq:(t==1)?(uint4*)h_Wk:(t==2)?(uint4*)h_Wv:(t==3)?(uint4*)h_Wr:(uint4*)h_Wfc;
    } else if (i < 5*N8_DD + 2*N8_DF){
        int k = i - 5*N8_DD; int t = k / N8_DF; j = k - t*N8_DF;
        src = t ? W2 : W1;
        dst = t ? (uint4*)h_W2 : (uint4*)h_W1;
    } else {
        j = i - (5*N8_DD + 2*N8_DF);
        src = Wlm; dst = (uint4*)h_Wlm;
    }
    float4 a = src[j*2], b = src[j*2+1];
    __half2 h0 = __floats2half2_rn(a.x, a.y);
    __half2 h1 = __floats2half2_rn(a.z, a.w);
    __half2 h2 = __floats2half2_rn(b.x, b.y);
    __half2 h3 = __floats2half2_rn(b.z, b.w);
    dst[j] = make_uint4(*(uint32_t*)&h0, *(uint32_t*)&h1, *(uint32_t*)&h2, *(uint32_t*)&h3);
}

// ---------------- embedding ------------------------------------------------
__global__ void embed_kernel(const int* __restrict__ text, const float* __restrict__ emb){
    int idx = blockIdx.x*256 + threadIdx.x;
    int d4  = idx & (D_/4 - 1);
    int bs  = idx >> 8;
    int s   = bs & (S_-1);
    int b   = bs >> 10;
    int tok = text[b*CTX_ + s];
    ((float4*)g_x)[idx] = ((const float4*)(emb + (size_t)tok*D_))[d4];
}

// ---------------- sinusoidal relative positions (fp16 out) ------------------
__global__ void rel_kernel(){
    int idx = blockIdx.x*256 + threadIdx.x;
    int j = idx & 511;
    int s = idx >> 9;
    float pos  = (float)(S_-1-s);
    float invf = powf(10000.0f, -(float)(2*j)/(float)D_);
    float a = pos*invf;
    h_rel[s*D_ + j]       = __float2half_rn(sinf(a));
    h_rel[s*D_ + j + 512] = __float2half_rn(cosf(a));
}

// ---------------- layernorm (writes fp32 + fp16) ----------------------------
__global__ void ln_kernel(const float* __restrict__ in, float* __restrict__ out,
                          __half* __restrict__ out16,
                          const float* __restrict__ gam, const float* __restrict__ bet){
    int row = blockIdx.x;
    int t = threadIdx.x;
    const float4* x4 = (const float4*)(in + (size_t)row*D_);
    float4 v = x4[t];
    float s  = v.x+v.y+v.z+v.w;
    float s2 = v.x*v.x+v.y*v.y+v.z*v.z+v.w*v.w;
    #pragma unroll
    for (int o=16;o;o>>=1){ s += __shfl_xor_sync(0xffffffffu,s,o); s2 += __shfl_xor_sync(0xffffffffu,s2,o); }
    __shared__ float shs[8], shs2[8], bc[2];
    int w = t>>5, lane = t&31;
    if (!lane){ shs[w]=s; shs2[w]=s2; }
    __syncthreads();
    if (t==0){
        float ts=0.f, ts2=0.f;
        #pragma unroll
        for (int i=0;i<8;i++){ ts+=shs[i]; ts2+=shs2[i]; }
        float m   = ts*(1.0f/(float)D_);
        float var = ts2*(1.0f/(float)D_) - m*m;
        bc[0]=m; bc[1]=rsqrtf(var + 1e-5f);
    }
    __syncthreads();
    float m = bc[0], inv = bc[1];
    float4 gg = ((const float4*)gam)[t];
    float4 bb = ((const float4*)bet)[t];
    float4 o4;
    o4.x = (v.x-m)*inv*gg.x + bb.x;
    o4.y = (v.y-m)*inv*gg.y + bb.y;
    o4.z = (v.z-m)*inv*gg.z + bb.z;
    o4.w = (v.w-m)*inv*gg.w + bb.w;
    ((float4*)(out + (size_t)row*D_))[t] = o4;
    __half2 p0 = __floats2half2_rn(o4.x, o4.y);
    __half2 p1 = __floats2half2_rn(o4.z, o4.w);
    *(uint2*)(out16 + (size_t)row*D_ + t*4) = make_uint2(*(uint32_t*)&p0, *(uint32_t*)&p1);
}

// ================= fp16 GEMM with cp.async 4-stage pipeline =================
#define TBM 128
#define TBN 128
#define TBK 32
#define STAGES 4
#define HG_SMEM ((STAGES*TBM*40 + STAGES*TBK*136)*2)

// EPI: 0 plain | 1 +bias | 2 gelu(acc+bias) | 3 R1+R2+acc+bias | 4 R1+gelu(acc+bias)
template<int EPI, typename TC>
__device__ __forceinline__ void hgemm_body(
    const __half* __restrict__ A, const __half* __restrict__ Bm,
    const float* __restrict__ bias, TC* __restrict__ C,
    const float* __restrict__ R1, const float* __restrict__ R2,
    int N, int K)
{
    extern __shared__ __half hsm[];
    __half* Asm = hsm;
    __half* Bsm = hsm + STAGES*TBM*40;

    const int tid = threadIdx.x;
    const int lane = tid & 31, wid = tid >> 5;
    const int wm = wid >> 1, wn = wid & 1;
    const int r = lane >> 2, cg = lane & 3;
    const int bm = blockIdx.x*TBM, bn = blockIdx.y*TBN;

    const int arow = tid >> 1, ac0 = (tid & 1)*16;
    const int brow = tid >> 3, bc0 = (tid & 7)*16;

    const int aRowL = lane & 15, aKH = lane >> 4;
    const int bKL   = (lane & 7) + ((lane >> 3) & 1)*8, bNH = lane >> 4;

    float acc[2][8][4];
    #pragma unroll
    for (int mt=0;mt<2;mt++)
        #pragma unroll
        for (int nt=0;nt<8;nt++)
            #pragma unroll
            for (int i=0;i<4;i++) acc[mt][nt][i]=0.f;

    const int nkt = K/TBK;

    auto issue = [&](int kt, int s){
        __half* as = Asm + (s*TBM + arow)*40 + ac0;
        const __half* ap = A + (size_t)(bm+arow)*K + kt*TBK + ac0;
        cp16(as,   ap);
        cp16(as+8, ap+8);
        __half* bs = Bsm + (s*TBK + brow)*136 + bc0;
        const __half* bp = Bm + (size_t)(kt*TBK + brow)*N + bn + bc0;
        cp16(bs,   bp);
        cp16(bs+8, bp+8);
    };

    #pragma unroll
    for (int s=0; s<STAGES-1; s++){ issue(s, s); CP_COMMIT(); }

    for (int kt=0; kt<nkt; kt++){
        CP_WAIT(STAGES-2);
        __syncthreads();
        const int nk = kt + STAGES-1;
        if (nk < nkt) issue(nk, nk & (STAGES-1));
        CP_COMMIT();

        const int s = kt & (STAGES-1);
        const __half* as = Asm + (size_t)s*TBM*40;
        const __half* bs = Bsm + (size_t)s*TBK*136;
        #pragma unroll
        for (int ks=0; ks<2; ks++){
            uint32_t af[2][4];
            #pragma unroll
            for (int mt=0;mt<2;mt++)
                ldsm_x4(af[mt], smaddr(as + (wm*32 + mt*16 + aRowL)*40 + ks*16 + aKH*8));
            #pragma unroll
            for (int nt=0;nt<4;nt++){
                uint32_t bf[4];
                ldsm_x4_t(bf, smaddr(bs + (ks*16 + bKL)*136 + wn*64 + nt*16 + bNH*8));
                mma_f16(acc[0][nt*2+0], af[0], bf[0], bf[1]);
                mma_f16(acc[1][nt*2+0], af[1], bf[0], bf[1]);
                mma_f16(acc[0][nt*2+1], af[0], bf[2], bf[3]);
                mma_f16(acc[1][nt*2+1], af[1], bf[2], bf[3]);
            }
        }
    }

    #pragma unroll
    for (int mt=0;mt<2;mt++){
        int row0 = bm + wm*32 + mt*16 + r;
        #pragma unroll
        for (int nt=0;nt<8;nt++){
            int col = bn + wn*64 + nt*8 + cg*2;
            float2 b2 = make_float2(0.f,0.f);
            if (EPI >= 1) b2 = *(const float2*)(bias + col);
            float2 v0, v1;
            v0.x = acc[mt][nt][0] + b2.x; v0.y = acc[mt][nt][1] + b2.y;
            v1.x = acc[mt][nt][2] + b2.x; v1.y = acc[mt][nt][3] + b2.y;
            if (EPI == 2 || EPI == 4){
                v0.x = gelu_t(v0.x); v0.y = gelu_t(v0.y);
                v1.x = gelu_t(v1.x); v1.y = gelu_t(v1.y);
            }
            size_t i0 = (size_t)row0*N + col, i1 = (size_t)(row0+8)*N + col;
            if (EPI == 3){
                float2 a0 = *(const float2*)(R1 + i0), a1 = *(const float2*)(R1 + i1);
                float2 x0 = *(const float2*)(R2 + i0), x1 = *(const float2*)(R2 + i1);
                v0.x += a0.x + x0.x; v0.y += a0.y + x0.y;
                v1.x += a1.x + x1.x; v1.y += a1.y + x1.y;
            }
            if (EPI == 4){
                float2 a0 = *(const float2*)(R1 + i0), a1 = *(const float2*)(R1 + i1);
                v0.x += a0.x; v0.y += a0.y;
                v1.x += a1.x; v1.y += a1.y;
            }
            if constexpr (sizeof(TC) == 2){
                *(__half2*)(C + i0) = __floats2half2_rn(v0.x, v0.y);
                *(__half2*)(C + i1) = __floats2half2_rn(v1.x, v1.y);
            } else {
                *(float2*)(C + i0) = v0;
                *(float2*)(C + i1) = v1;
            }
        }
    }
}

template<int EPI, typename TC>
__global__ void __launch_bounds__(256, 2)
hgemm_kernel(const __half* __restrict__ A, const __half* __restrict__ Bm,
             const float* __restrict__ bias, TC* __restrict__ C,
             const float* __restrict__ R1, const float* __restrict__ R2,
             int N, int K)
{
    hgemm_body<EPI, TC>(A, Bm, bias, C, R1, R2, N, K);
}

__global__ void __launch_bounds__(256, 2)
qkvr_kernel(int l)
{
    const int z = blockIdx.z;
    if (z == 3 && blockIdx.x*TBM >= S_) return;
    const __half* A = (z < 3) ? h_xn : h_rel;
    const __half* W = ((z==0) ? h_Wq : (z==1) ? h_Wk : (z==2) ? h_Wv : h_Wr) + (size_t)l*D_*D_;
    __half*       C = (z==0) ? h_q : (z==1) ? h_k : (z==2) ? h_v : h_r;
    hgemm_body<0, __half>(A, W, nullptr, C, nullptr, nullptr, D_, D_);
}

// ---------------- bias precompute: uk[b,h,key]=u·k, vr[h,row]=v·r ----------
__global__ void bias_kernel(const float* __restrict__ uvec, const float* __restrict__ vvec){
    const int t = threadIdx.x;
    float4 uu;
    float2 f0, f1;
    if (blockIdx.y == 0){
        int row = blockIdx.x;
        uint2 raw = *(const uint2*)(h_k + (size_t)row*D_ + t*4);
        f0 = __half22float2(*(__half2*)&raw.x);
        f1 = __half22float2(*(__half2*)&raw.y);
        uu = ((const float4*)uvec)[t];
        float p = f0.x*uu.x + f0.y*uu.y + f1.x*uu.z + f1.y*uu.w;
        p += __shfl_xor_sync(0xffffffffu, p, 8);
        p += __shfl_xor_sync(0xffffffffu, p, 4);
        p += __shfl_xor_sync(0xffffffffu, p, 2);
        p += __shfl_xor_sync(0xffffffffu, p, 1);
        if ((t & 15) == 0){
            int h = t >> 4;
            int b = row >> 10, key = row & (S_-1);
            g_uk[((size_t)(b*H_ + h))*S_ + key] = p;
        }
    } else {
        int rrow = blockIdx.x;
        if (rrow >= S_) return;
        uint2 raw = *(const uint2*)(h_r + (size_t)rrow*D_ + t*4);
        f0 = __half22float2(*(__half2*)&raw.x);
        f1 = __half22float2(*(__half2*)&raw.y);
        uu = ((const float4*)vvec)[t];
        float p = f0.x*uu.x + f0.y*uu.y + f1.x*uu.z + f1.y*uu.w;
        p += __shfl_xor_sync(0xffffffffu, p, 8);
        p += __shfl_xor_sync(0xffffffffu, p, 4);
        p += __shfl_xor_sync(0xffffffffu, p, 2);
        p += __shfl_xor_sync(0xffffffffu, p, 1);
        if ((t & 15) == 0)
            g_vr[(t>>4)*S_ + rrow] = p;
    }
}

// ================= fused flash attention (unchanged from R9) =================
#define FQH 72
#define FC2 132
#define FL_SMEM ((384*FQH)*2 + (64*FC2 + 128 + 128 + 64 + 64)*4)

__global__ void __launch_bounds__(256)
flash_kernel(const int* __restrict__ text){
    const int qtile = 15 - blockIdx.x;
    const int qt0 = qtile*64;
    const int bh = blockIdx.y, b = bh>>4, h = bh&15;

    extern __shared__ __half fsm[];
    __half* Qs = fsm;
    __half* Ks = Qs + 64*FQH;
    __half* Vs = Ks + 64*FQH;
    __half* Rs = Vs + 64*FQH;
    __half* Ps = Rs + 128*FQH;
    float*  C2  = (float*)(Ps + 64*FQH);
    float*  wmx = C2 + 64*FC2;
    float*  wsm = wmx + 128;
    float*  mrow = wsm + 128;
    float*  lrow = mrow + 64;

    const int tid = threadIdx.x;
    const int lane = tid&31, wid = tid>>5;
    const int wm = wid>>1, wn = wid&1;
    const int r = lane>>2, cg = lane&3;
    const int rowL = lane&15, kHalf = lane>>4;
    const int bKL = (lane&7) + ((lane>>3)&1)*8, bNH = lane>>4;

    {
        const int pos = tid>>2, c0 = (tid&3)*16;
        const __half* qp = h_q + ((size_t)(b*S_+qt0+pos))*D_ + h*DH_ + c0;
        *(uint4*)&Qs[pos*FQH+c0]   = *(const uint4*)qp;
        *(uint4*)&Qs[pos*FQH+c0+8] = *(const uint4*)(qp+8);
    }
    if (tid < 64){ mrow[tid] = -1e30f; lrow[tid] = 0.f; }

    float accO[4][4];
    #pragma unroll
    for (int nt=0;nt<4;nt++){ accO[nt][0]=accO[nt][1]=accO[nt][2]=accO[nt][3]=0.f; }

    const float* ukb = g_uk + (size_t)bh*S_;
    const float* vrp = g_vr + (size_t)h*S_;

    for (int kt=0; kt<=qtile; kt++){
        __syncthreads();
        {
            const int pos = tid>>2, c0 = (tid&3)*16;
            const __half* kp = h_k + ((size_t)(b*S_+kt*64+pos))*D_ + h*DH_ + c0;
            *(uint4*)&Ks[pos*FQH+c0]   = *(const uint4*)kp;
            *(uint4*)&Ks[pos*FQH+c0+8] = *(const uint4*)(kp+8);
            const __half* vp = h_v + ((size_t)(b*S_+kt*64+pos))*D_ + h*DH_ + c0;
            *(uint4*)&Vs[pos*FQH+c0]   = *(const uint4*)vp;
            *(uint4*)&Vs[pos*FQH+c0+8] = *(const uint4*)(vp+8);
        }
        {
            const int rbase = S_ - 64 - qt0 + kt*64;
            const int j = tid>>1, rc0 = (tid&1)*32;
            const int rrow = rbase + j;
            if (rrow >= 0 && rrow < S_ && j < 127){
                const __half* rp = h_r + (size_t)rrow*D_ + h*DH_ + rc0;
                #pragma unroll
                for (int c=0;c<4;c++)
                    *(uint4*)&Rs[j*FQH + rc0 + c*8] = *(const uint4*)(rp + c*8);
            } else {
                uint4 z = make_uint4(0,0,0,0);
                #pragma unroll
                for (int c=0;c<4;c++)
                    *(uint4*)&Rs[j*FQH + rc0 + c*8] = z;
            }
        }
        __syncthreads();

        float accA[4][4], accB[8][4];
        #pragma unroll
        for (int nt=0;nt<4;nt++){ accA[nt][0]=accA[nt][1]=accA[nt][2]=accA[nt][3]=0.f; }
        #pragma unroll
        for (int nt=0;nt<8;nt++){ accB[nt][0]=accB[nt][1]=accB[nt][2]=accB[nt][3]=0.f; }
        #pragma unroll
        for (int ks=0; ks<4; ks++){
            uint32_t a[4];
            ldsm_x4(a, smaddr(Qs + (wm*16 + rowL)*FQH + ks*16 + kHalf*8));
            #pragma unroll
            for (int np=0; np<2; np++){
                uint32_t bk[4];
                ldsm_x4(bk, smaddr(Ks + (wn*32 + np*16 + rowL)*FQH + ks*16 + kHalf*8));
                mma_f16(accA[np*2+0], a, bk[0], bk[2]);
                mma_f16(accA[np*2+1], a, bk[1], bk[3]);
            }
            #pragma unroll
            for (int np=0; np<4; np++){
                uint32_t br[4];
                ldsm_x4(br, smaddr(Rs + (wn*64 + np*16 + rowL)*FQH + ks*16 + kHalf*8));
                mma_f16(accB[np*2+0], a, br[0], br[2]);
                mma_f16(accB[np*2+1], a, br[1], br[3]);
            }
        }
        #pragma unroll
        for (int nt=0;nt<8;nt++){
            int col = wn*64 + nt*8 + cg*2;
            C2[(wm*16+r  )*FC2 + col    ] = accB[nt][0];
            C2[(wm*16+r  )*FC2 + col + 1] = accB[nt][1];
            C2[(wm*16+r+8)*FC2 + col    ] = accB[nt][2];
            C2[(wm*16+r+8)*FC2 + col + 1] = accB[nt][3];
        }
        __syncthreads();

        const float* ukp = ukb + kt*64;
        float sv[2][4][2];
        float tmax[2] = {-1e30f, -1e30f};
        #pragma unroll
        for (int i=0;i<2;i++){
            const int qr = wm*16 + r + i*8;
            const int q  = qt0 + qr;
            #pragma unroll
            for (int nt=0;nt<4;nt++){
                #pragma unroll
                for (int cc=0;cc<2;cc++){
                    const int kr = wn*32 + nt*8 + cg*2 + cc;
                    const int k  = kt*64 + kr;
                    float v;
                    if (k <= q){
                        v = (accA[nt][i*2+cc] + ukp[kr]
                             + C2[qr*FC2 + 63 + kr - qr] + vrp[S_-1-q+k]) * 0.125f;
                    } else v = -1e30f;
                    sv[i][nt][cc] = v;
                    tmax[i] = fmaxf(tmax[i], v);
                }
            }
        }
        #pragma unroll
        for (int i=0;i<2;i++){
            tmax[i] = fmaxf(tmax[i], __shfl_xor_sync(0xffffffffu, tmax[i], 1));
            tmax[i] = fmaxf(tmax[i], __shfl_xor_sync(0xffffffffu, tmax[i], 2));
        }
        if (cg == 0){
            wmx[wn*64 + wm*16 + r    ] = tmax[0];
            wmx[wn*64 + wm*16 + r + 8] = tmax[1];
        }
        __syncthreads();

        #pragma unroll
        for (int i=0;i<2;i++){
            const int row = wm*16 + r + i*8;
            float m_old = mrow[row];
            float m_new = fmaxf(m_old, fmaxf(wmx[row], wmx[64+row]));
            float scl = __expf(m_old - m_new);
            float psum = 0.f;
            #pragma unroll
            for (int nt=0;nt<4;nt++){
                float p0 = __expf(sv[i][nt][0] - m_new);
                float p1 = __expf(sv[i][nt][1] - m_new);
                psum += p0 + p1;
                *(__half2*)&Ps[row*FQH + wn*32 + nt*8 + cg*2] = __floats2half2_rn(p0, p1);
                accO[nt][i*2+0] *= scl;
                accO[nt][i*2+1] *= scl;
            }
            psum += __shfl_xor_sync(0xffffffffu, psum, 1);
            psum += __shfl_xor_sync(0xffffffffu, psum, 2);
            if (cg == 0) wsm[wn*64 + row] = psum;
        }
        __syncthreads();

        if (tid < 64){
            float m_old = mrow[tid];
            float m_new = fmaxf(m_old, fmaxf(wmx[tid], wmx[64+tid]));
            lrow[tid] = lrow[tid]*__expf(m_old - m_new) + wsm[tid] + wsm[64+tid];
            mrow[tid] = m_new;
        }
        #pragma unroll
        for (int ks=0; ks<4; ks++){
            uint32_t af[4];
            ldsm_x4(af, smaddr(Ps + (wm*16 + rowL)*FQH + ks*16 + kHalf*8));
            #pragma unroll
            for (int nt=0; nt<2; nt++){
                uint32_t bf[4];
                ldsm_x4_t(bf, smaddr(Vs + (ks*16 + bKL)*FQH + wn*32 + nt*16 + bNH*8));
                mma_f16(accO[nt*2+0], af, bf[0], bf[1]);
                mma_f16(accO[nt*2+1], af, bf[2], bf[3]);
            }
        }
    }
    __syncthreads();

    #pragma unroll
    for (int i=0;i<2;i++){
        const int row = wm*16 + r + i*8;
        const int q   = qt0 + row;
        bool padq = (text[b*CTX_ + q] == PAD_);
        float inv = padq ? 0.f : 1.0f/lrow[row];
        #pragma unroll
        for (int nt=0;nt<4;nt++){
            int col = h*DH_ + wn*32 + nt*8 + cg*2;
            __half2 o2 = __floats2half2_rn(accO[nt][i*2+0]*inv, accO[nt][i*2+1]*inv);
            *(__half2*)(h_o + (size_t)(b*S_ + q)*D_ + col) = o2;
        }
    }
}

// ---------------- orchestration -----------------------------------------------
extern "C" void kernel_launch(void* const* d_in, const int* in_sizes, int n_in,
                              void* d_out, int out_size)
{
    (void)in_sizes; (void)n_in; (void)out_size;
    const int*   text = (const int*)  d_in[0];
    const float* emb  = (const float*)d_in[1];
    const float* u    = (const float*)d_in[2];
    const float* vbp  = (const float*)d_in[3];
    const float* Wq   = (const float*)d_in[4];
    const float* Wk   = (const float*)d_in[5];
    const float* Wv   = (const float*)d_in[6];
    const float* Wr   = (const float*)d_in[7];
    const float* Wfc  = (const float*)d_in[8];
    const float* bfc  = (const float*)d_in[9];
    const float* ln1g = (const float*)d_in[10];
    const float* ln1b = (const float*)d_in[11];
    const float* ln2g = (const float*)d_in[12];
    const float* ln2b = (const float*)d_in[13];
    const float* W1   = (const float*)d_in[14];
    const float* b1   = (const float*)d_in[15];
    const float* W2   = (const float*)d_in[16];
    const float* b2   = (const float*)d_in[17];
    const float* lnfg = (const float*)d_in[18];
    const float* lnfb = (const float*)d_in[19];
    const float* Wlm  = (const float*)d_in[20];
    const float* blm  = (const float*)d_in[21];
    float* out = (float*)d_out;

    float *px,*pxn;
    __half *pWq16,*pWk16,*pWv16,*pWr16,*pWfc16,*pW116,*pW216,*pWlm16,*pxn16,*po16,*pff16;
    cudaGetSymbolAddress((void**)&px,   g_x);
    cudaGetSymbolAddress((void**)&pxn,  g_xn);
    cudaGetSymbolAddress((void**)&pWq16, h_Wq);
    cudaGetSymbolAddress((void**)&pWk16, h_Wk);
    cudaGetSymbolAddress((void**)&pWv16, h_Wv);
    cudaGetSymbolAddress((void**)&pWr16, h_Wr);
    cudaGetSymbolAddress((void**)&pWfc16,h_Wfc);
    cudaGetSymbolAddress((void**)&pW116, h_W1);
    cudaGetSymbolAddress((void**)&pW216, h_W2);
    cudaGetSymbolAddress((void**)&pWlm16,h_Wlm);
    cudaGetSymbolAddress((void**)&pxn16, h_xn);
    cudaGetSymbolAddress((void**)&po16,  h_o);
    cudaGetSymbolAddress((void**)&pff16, h_ff);

    static bool attr_done = false;
    if (!attr_done){
        cudaFuncSetAttribute(flash_kernel, cudaFuncAttributeMaxDynamicSharedMemorySize, FL_SMEM);
        cudaFuncSetAttribute(qkvr_kernel,  cudaFuncAttributeMaxDynamicSharedMemorySize, HG_SMEM);
        cudaFuncSetAttribute((const void*)hgemm_kernel<1,float>,  cudaFuncAttributeMaxDynamicSharedMemorySize, HG_SMEM);
        cudaFuncSetAttribute((const void*)hgemm_kernel<2,__half>, cudaFuncAttributeMaxDynamicSharedMemorySize, HG_SMEM);
        cudaFuncSetAttribute((const void*)hgemm_kernel<3,float>,  cudaFuncAttributeMaxDynamicSharedMemorySize, HG_SMEM);
        cudaFuncSetAttribute((const void*)hgemm_kernel<4,float>,  cudaFuncAttributeMaxDynamicSharedMemorySize, HG_SMEM);
        attr_done = true;
    }

    const int MR = B_*S_;

    // ---- merged fp32 -> fp16 weight conversion (one launch) -----------------
    cvt_all_kernel<<<N8_TOTAL/256, 256>>>(
        (const float4*)Wq,  (const float4*)Wk,  (const float4*)Wv,  (const float4*)Wr,
        (const float4*)Wfc, (const float4*)W1,  (const float4*)W2,  (const float4*)Wlm);

    embed_kernel<<<2048,256>>>(text, emb);
    rel_kernel  <<<2048,256>>>();

    for (int l=0; l<L_; l++){
        ln_kernel<<<MR,256>>>(px, pxn, pxn16, ln1g + l*D_, ln1b + l*D_);

        qkvr_kernel<<<dim3(MR/TBM, D_/TBN, 4),256, HG_SMEM>>>(l);

        bias_kernel <<<dim3(B_*S_, 2),256>>>(u, vbp);
        flash_kernel<<<dim3(16, B_*H_),256, FL_SMEM>>>(text);

        // x = x + xn + o@Wfc + bfc
        hgemm_kernel<3,float><<<dim3(MR/TBM, D_/TBN),256, HG_SMEM>>>(
            po16, pWfc16 + (size_t)l*D_*D_, bfc + l*D_, px, px, pxn, D_, D_);

        ln_kernel<<<MR,256>>>(px, pxn, pxn16, ln2g + l*D_, ln2b + l*D_);
        hgemm_kernel<2,__half><<<dim3(MR/TBM, FF_/TBN),256, HG_SMEM>>>(
            pxn16, pW116 + (size_t)l*D_*FF_, b1 + l*FF_, pff16, nullptr, nullptr, FF_, D_);
        // x = x + gelu(ff@W2 + b2)
        hgemm_kernel<4,float><<<dim3(MR/TBM, D_/TBN),256, HG_SMEM>>>(
            pff16, pW216 + (size_t)l*FF_*D_, b2 + l*D_, px, px, nullptr, D_, FF_);
    }

    ln_kernel<<<MR,256>>>(px, pxn, pxn16, lnfg, lnfb);
    hgemm_kernel<1,float><<<dim3(MR/TBM, V_/TBN),256, HG_SMEM>>>(
        pxn16, pWlm16, blm, out, nullptr, nullptr, V_, D_);
}